// round 1
// baseline (speedup 1.0000x reference)
#include <cuda_runtime.h>
#include <math.h>

#define HEADS 12
#define DH 64
#define DIM 768
#define BATCH 8
#define SEQ 1024
#define ROWS (BATCH * SEQ)   // 8192

// ---------------- scratch (static device allocations are allowed) ----------------
__device__ float g_Q[ROWS * DIM];
__device__ float g_K[ROWS * DIM];
__device__ float g_V[ROWS * DIM];
__device__ float g_AO[ROWS * DIM];
__device__ float g_cosT[512];   // [pos 0..31][freq 0..15]
__device__ float g_sinT[512];

// ---------------- RoPE tables (double precision; immune to fast-math) ----------------
__global__ void init_tables_kernel() {
    int i = threadIdx.x;            // 0..511
    int p = i >> 4;
    int f = i & 15;
    double inv = pow(100.0, -((double)(2 * f)) / 32.0);
    double fr = (double)p * inv;
    g_cosT[i] = (float)cos(fr);
    g_sinT[i] = (float)sin(fr);
}

// ---------------- fp32 GEMM: C[8192,768] = A[8192,768] @ W[768,768] + bias ----------------
__global__ __launch_bounds__(256) void gemm_bias_kernel(
    const float* __restrict__ A, const float* __restrict__ W,
    const float* __restrict__ bias, float* __restrict__ C)
{
    const int K = DIM, N = DIM;
    __shared__ float As[16][64];   // [k][m] (transposed on load)
    __shared__ float Ws[16][64];   // [k][n]

    const int t  = threadIdx.x;
    const int tx = t & 15;
    const int ty = t >> 4;
    const int m0 = blockIdx.y * 64;
    const int n0 = blockIdx.x * 64;

    const int aRow = t >> 2;          // 0..63
    const int aK   = (t & 3) << 2;    // 0,4,8,12
    const int wK   = t >> 4;          // 0..15
    const int wN   = (t & 15) << 2;   // 0..60

    const float* Aptr = A + (m0 + aRow) * K + aK;
    const float* Wptr = W + wK * N + n0 + wN;

    float4 acc0 = make_float4(0.f, 0.f, 0.f, 0.f);
    float4 acc1 = acc0, acc2 = acc0, acc3 = acc0;

    for (int k0 = 0; k0 < K; k0 += 16) {
        float4 av = *(const float4*)(Aptr + k0);
        float4 wv = *(const float4*)(Wptr + (long)k0 * N);
        As[aK + 0][aRow] = av.x;
        As[aK + 1][aRow] = av.y;
        As[aK + 2][aRow] = av.z;
        As[aK + 3][aRow] = av.w;
        *(float4*)&Ws[wK][wN] = wv;
        __syncthreads();
        #pragma unroll
        for (int k = 0; k < 16; ++k) {
            float4 a = *(const float4*)&As[k][ty << 2];
            float4 b = *(const float4*)&Ws[k][tx << 2];
            acc0.x += a.x * b.x; acc0.y += a.x * b.y; acc0.z += a.x * b.z; acc0.w += a.x * b.w;
            acc1.x += a.y * b.x; acc1.y += a.y * b.y; acc1.z += a.y * b.z; acc1.w += a.y * b.w;
            acc2.x += a.z * b.x; acc2.y += a.z * b.y; acc2.z += a.z * b.z; acc2.w += a.z * b.w;
            acc3.x += a.w * b.x; acc3.y += a.w * b.y; acc3.z += a.w * b.z; acc3.w += a.w * b.w;
        }
        __syncthreads();
    }

    float4 bv = *(const float4*)&bias[n0 + (tx << 2)];
    float4 outs[4] = {acc0, acc1, acc2, acc3};
    #pragma unroll
    for (int i = 0; i < 4; ++i) {
        float4 o = outs[i];
        o.x += bv.x; o.y += bv.y; o.z += bv.z; o.w += bv.w;
        *(float4*)&C[(long)(m0 + (ty << 2) + i) * N + n0 + (tx << 2)] = o;
    }
}

// ---------------- 2D RoPE, in place on [ROWS, DIM] projected tensor ----------------
// For each (row s, head h): first 32 dims use pos[s][0], last 32 use pos[s][1].
// Within a 32-half: out[f]    = v[f]*cos - v[f+16]*sin
//                   out[f+16] = v[f+16]*cos + v[f]*sin        (f = 0..15)
__global__ void rope_kernel(float* __restrict__ T, const int* __restrict__ pos) {
    int idx = blockIdx.x * blockDim.x + threadIdx.x;
    const int total = ROWS * HEADS * 32;
    if (idx >= total) return;
    int j = idx & 31;
    int h = (idx >> 5) % HEADS;
    int s = idx / (32 * HEADS);
    int half = j >> 4;
    int f = j & 15;
    int p = pos[s * 2 + half];
    float c  = g_cosT[p * 16 + f];
    float sn = g_sinT[p * 16 + f];
    int base = s * DIM + h * DH + half * 32 + f;
    float v1 = T[base];
    float v2 = T[base + 16];
    T[base]      = v1 * c - v2 * sn;
    T[base + 16] = v2 * c + v1 * sn;
}

// ---------------- flash attention: 64q x 64kv tiles, online softmax ----------------
// Swizzle for the K/P union buffer: 16B-granule XOR by (row>>2)&7 so that
// column-direction reads (16 threads hitting 16 different rows at one d) spread banks.
__device__ __forceinline__ int swz(int row, int d) {
    return row * 64 + ((((d >> 2) ^ ((row >> 2) & 7)) << 2) | (d & 3));
}

__global__ __launch_bounds__(256) void flash_kernel(
    const float* __restrict__ Qp, const float* __restrict__ Kp,
    const float* __restrict__ Vp, float* __restrict__ Ao)
{
    __shared__ float Qs[64 * 64];    // [q][d]
    __shared__ float KPs[64 * 64];   // K tile [kv][d] swizzled, reused as P [q][kv] swizzled
    __shared__ float Vs[64 * 64];    // [kv][d]

    const int t  = threadIdx.x;
    const int tx = t & 15;
    const int ty = t >> 4;
    const int qb = blockIdx.x * 64;
    const int h  = blockIdx.y;
    const int b  = blockIdx.z;
    const long qrow0 = (long)b * SEQ + qb;
    const int col0 = h * DH;

    // load Q tile (natural layout)
    {
        int r  = t >> 4;
        int d4 = (t & 15) << 2;
        #pragma unroll
        for (int it = 0; it < 4; ++it) {
            int row = r + it * 16;
            *(float4*)&Qs[row * 64 + d4] =
                *(const float4*)&Qp[(qrow0 + row) * DIM + col0 + d4];
        }
    }

    float m_run[4], l_run[4];
    float4 acc[4];
    #pragma unroll
    for (int i = 0; i < 4; ++i) {
        m_run[i] = -1e30f; l_run[i] = 0.f;
        acc[i] = make_float4(0.f, 0.f, 0.f, 0.f);
    }

    for (int kt = 0; kt < SEQ / 64; ++kt) {
        // load K (swizzled) and V tiles
        {
            int r  = t >> 4;
            int d4 = (t & 15) << 2;
            #pragma unroll
            for (int it = 0; it < 4; ++it) {
                int row = r + it * 16;
                long g = ((long)b * SEQ + kt * 64 + row) * DIM + col0 + d4;
                *(float4*)&KPs[swz(row, d4)] = *(const float4*)&Kp[g];
                *(float4*)&Vs[row * 64 + d4] = *(const float4*)&Vp[g];
            }
        }
        __syncthreads();

        // S = Q @ K^T (4x4 per thread over 64-d)
        float s00=0,s01=0,s02=0,s03=0, s10=0,s11=0,s12=0,s13=0;
        float s20=0,s21=0,s22=0,s23=0, s30=0,s31=0,s32=0,s33=0;
        #pragma unroll
        for (int d = 0; d < 64; d += 4) {
            float4 a0 = *(const float4*)&Qs[((ty << 2) + 0) * 64 + d];
            float4 a1 = *(const float4*)&Qs[((ty << 2) + 1) * 64 + d];
            float4 a2 = *(const float4*)&Qs[((ty << 2) + 2) * 64 + d];
            float4 a3 = *(const float4*)&Qs[((ty << 2) + 3) * 64 + d];
            float4 b0 = *(const float4*)&KPs[swz((tx << 2) + 0, d)];
            float4 b1 = *(const float4*)&KPs[swz((tx << 2) + 1, d)];
            float4 b2 = *(const float4*)&KPs[swz((tx << 2) + 2, d)];
            float4 b3 = *(const float4*)&KPs[swz((tx << 2) + 3, d)];
            s00 += a0.x*b0.x + a0.y*b0.y + a0.z*b0.z + a0.w*b0.w;
            s01 += a0.x*b1.x + a0.y*b1.y + a0.z*b1.z + a0.w*b1.w;
            s02 += a0.x*b2.x + a0.y*b2.y + a0.z*b2.z + a0.w*b2.w;
            s03 += a0.x*b3.x + a0.y*b3.y + a0.z*b3.z + a0.w*b3.w;
            s10 += a1.x*b0.x + a1.y*b0.y + a1.z*b0.z + a1.w*b0.w;
            s11 += a1.x*b1.x + a1.y*b1.y + a1.z*b1.z + a1.w*b1.w;
            s12 += a1.x*b2.x + a1.y*b2.y + a1.z*b2.z + a1.w*b2.w;
            s13 += a1.x*b3.x + a1.y*b3.y + a1.z*b3.z + a1.w*b3.w;
            s20 += a2.x*b0.x + a2.y*b0.y + a2.z*b0.z + a2.w*b0.w;
            s21 += a2.x*b1.x + a2.y*b1.y + a2.z*b1.z + a2.w*b1.w;
            s22 += a2.x*b2.x + a2.y*b2.y + a2.z*b2.z + a2.w*b2.w;
            s23 += a2.x*b3.x + a2.y*b3.y + a2.z*b3.z + a2.w*b3.w;
            s30 += a3.x*b0.x + a3.y*b0.y + a3.z*b0.z + a3.w*b0.w;
            s31 += a3.x*b1.x + a3.y*b1.y + a3.z*b1.z + a3.w*b1.w;
            s32 += a3.x*b2.x + a3.y*b2.y + a3.z*b2.z + a3.w*b2.w;
            s33 += a3.x*b3.x + a3.y*b3.y + a3.z*b3.z + a3.w*b3.w;
        }

        float s[4][4] = {{s00,s01,s02,s03},{s10,s11,s12,s13},{s20,s21,s22,s23},{s30,s31,s32,s33}};
        float p[4][4];
        #pragma unroll
        for (int i = 0; i < 4; ++i) {
            float v0 = s[i][0] * 0.125f, v1 = s[i][1] * 0.125f;
            float v2 = s[i][2] * 0.125f, v3 = s[i][3] * 0.125f;
            float mx = fmaxf(fmaxf(v0, v1), fmaxf(v2, v3));
            mx = fmaxf(mx, __shfl_xor_sync(0xffffffffu, mx, 1));
            mx = fmaxf(mx, __shfl_xor_sync(0xffffffffu, mx, 2));
            mx = fmaxf(mx, __shfl_xor_sync(0xffffffffu, mx, 4));
            mx = fmaxf(mx, __shfl_xor_sync(0xffffffffu, mx, 8));
            float mnew = fmaxf(m_run[i], mx);
            float corr = __expf(m_run[i] - mnew);
            m_run[i] = mnew;
            p[i][0] = __expf(v0 - mnew);
            p[i][1] = __expf(v1 - mnew);
            p[i][2] = __expf(v2 - mnew);
            p[i][3] = __expf(v3 - mnew);
            float ps = p[i][0] + p[i][1] + p[i][2] + p[i][3];
            ps += __shfl_xor_sync(0xffffffffu, ps, 1);
            ps += __shfl_xor_sync(0xffffffffu, ps, 2);
            ps += __shfl_xor_sync(0xffffffffu, ps, 4);
            ps += __shfl_xor_sync(0xffffffffu, ps, 8);
            l_run[i] = l_run[i] * corr + ps;
            acc[i].x *= corr; acc[i].y *= corr; acc[i].z *= corr; acc[i].w *= corr;
        }
        __syncthreads();   // everyone done reading K from KPs

        // stash P into KPs as [q][kv] (swizzled)
        #pragma unroll
        for (int i = 0; i < 4; ++i)
            *(float4*)&KPs[swz((ty << 2) + i, tx << 2)] =
                make_float4(p[i][0], p[i][1], p[i][2], p[i][3]);
        __syncthreads();

        // O += P @ V
        #pragma unroll
        for (int kv = 0; kv < 64; kv += 4) {
            float4 a0 = *(const float4*)&KPs[swz((ty << 2) + 0, kv)];
            float4 a1 = *(const float4*)&KPs[swz((ty << 2) + 1, kv)];
            float4 a2 = *(const float4*)&KPs[swz((ty << 2) + 2, kv)];
            float4 a3 = *(const float4*)&KPs[swz((ty << 2) + 3, kv)];
            float4 b0 = *(const float4*)&Vs[(kv + 0) * 64 + (tx << 2)];
            float4 b1 = *(const float4*)&Vs[(kv + 1) * 64 + (tx << 2)];
            float4 b2 = *(const float4*)&Vs[(kv + 2) * 64 + (tx << 2)];
            float4 b3 = *(const float4*)&Vs[(kv + 3) * 64 + (tx << 2)];
            acc[0].x += a0.x*b0.x + a0.y*b1.x + a0.z*b2.x + a0.w*b3.x;
            acc[0].y += a0.x*b0.y + a0.y*b1.y + a0.z*b2.y + a0.w*b3.y;
            acc[0].z += a0.x*b0.z + a0.y*b1.z + a0.z*b2.z + a0.w*b3.z;
            acc[0].w += a0.x*b0.w + a0.y*b1.w + a0.z*b2.w + a0.w*b3.w;
            acc[1].x += a1.x*b0.x + a1.y*b1.x + a1.z*b2.x + a1.w*b3.x;
            acc[1].y += a1.x*b0.y + a1.y*b1.y + a1.z*b2.y + a1.w*b3.y;
            acc[1].z += a1.x*b0.z + a1.y*b1.z + a1.z*b2.z + a1.w*b3.z;
            acc[1].w += a1.x*b0.w + a1.y*b1.w + a1.z*b2.w + a1.w*b3.w;
            acc[2].x += a2.x*b0.x + a2.y*b1.x + a2.z*b2.x + a2.w*b3.x;
            acc[2].y += a2.x*b0.y + a2.y*b1.y + a2.z*b2.y + a2.w*b3.y;
            acc[2].z += a2.x*b0.z + a2.y*b1.z + a2.z*b2.z + a2.w*b3.z;
            acc[2].w += a2.x*b0.w + a2.y*b1.w + a2.z*b2.w + a2.w*b3.w;
            acc[3].x += a3.x*b0.x + a3.y*b1.x + a3.z*b2.x + a3.w*b3.x;
            acc[3].y += a3.x*b0.y + a3.y*b1.y + a3.z*b2.y + a3.w*b3.y;
            acc[3].z += a3.x*b0.z + a3.y*b1.z + a3.z*b2.z + a3.w*b3.z;
            acc[3].w += a3.x*b0.w + a3.y*b1.w + a3.z*b2.w + a3.w*b3.w;
        }
        __syncthreads();
    }

    #pragma unroll
    for (int i = 0; i < 4; ++i) {
        float inv = 1.0f / l_run[i];
        float4 o = acc[i];
        o.x *= inv; o.y *= inv; o.z *= inv; o.w *= inv;
        *(float4*)&Ao[(qrow0 + (ty << 2) + i) * DIM + col0 + (tx << 2)] = o;
    }
}

// ---------------- launch ----------------
extern "C" void kernel_launch(void* const* d_in, const int* in_sizes, int n_in,
                              void* d_out, int out_size) {
    const float* x      = (const float*)d_in[0];
    const float* y      = (const float*)d_in[1];
    const int*   pos_q  = (const int*)d_in[2];
    const int*   pos_kv = (const int*)d_in[3];
    const float* Wq = (const float*)d_in[4];
    const float* bq = (const float*)d_in[5];
    const float* Wk = (const float*)d_in[6];
    const float* bk = (const float*)d_in[7];
    const float* Wv = (const float*)d_in[8];
    const float* bv = (const float*)d_in[9];
    const float* Wo = (const float*)d_in[10];
    const float* bo = (const float*)d_in[11];
    float* out = (float*)d_out;

    float *Qp, *Kp, *Vp, *Ao;
    cudaGetSymbolAddress((void**)&Qp, g_Q);
    cudaGetSymbolAddress((void**)&Kp, g_K);
    cudaGetSymbolAddress((void**)&Vp, g_V);
    cudaGetSymbolAddress((void**)&Ao, g_AO);

    init_tables_kernel<<<1, 512>>>();

    dim3 ggrid(DIM / 64, ROWS / 64);   // (12, 128)
    gemm_bias_kernel<<<ggrid, 256>>>(x, Wq, bq, Qp);
    gemm_bias_kernel<<<ggrid, 256>>>(y, Wk, bk, Kp);
    gemm_bias_kernel<<<ggrid, 256>>>(y, Wv, bv, Vp);

    const int rope_total = ROWS * HEADS * 32;
    rope_kernel<<<(rope_total + 255) / 256, 256>>>(Qp, pos_q);
    rope_kernel<<<(rope_total + 255) / 256, 256>>>(Kp, pos_kv);

    dim3 agrid(SEQ / 64, HEADS, BATCH);   // (16, 12, 8)
    flash_kernel<<<agrid, 256>>>(Qp, Kp, Vp, Ao);

    gemm_bias_kernel<<<ggrid, 256>>>(Ao, Wo, bo, out);
}

// round 4
// speedup vs baseline: 1.8858x; 1.8858x over previous
#include <cuda_runtime.h>
#include <cuda_fp16.h>
#include <math.h>
#include <stdint.h>

#define HEADS 12
#define DH 64
#define DIM 768
#define BATCH 8
#define SEQ 1024
#define ROWS (BATCH * SEQ)   // 8192

// ---------------- scratch ----------------
__device__ float g_Q[ROWS * DIM];
__device__ float g_K[ROWS * DIM];
__device__ float g_V[ROWS * DIM];
__device__ float g_AO[ROWS * DIM];
__device__ __half g_Xh[ROWS * DIM];   // fp16 activations (x / y / AO reuse)
__device__ __half g_Yh[ROWS * DIM];
__device__ __half g_WT[DIM * DIM];    // fp16 transposed weight [n][k]
__device__ float g_cosT[512];
__device__ float g_sinT[512];

// ---------------- helpers ----------------
__device__ __forceinline__ uint32_t smem_u32(const void* p) {
    uint32_t a;
    asm("{ .reg .u64 t; cvta.to.shared.u64 t, %1; cvt.u32.u64 %0, t; }" : "=r"(a) : "l"(p));
    return a;
}

// ---------------- RoPE tables (double precision) ----------------
__global__ void init_tables_kernel() {
    int i = threadIdx.x;            // 0..511
    int p = i >> 4;
    int f = i & 15;
    double inv = pow(100.0, -((double)(2 * f)) / 32.0);
    double fr = (double)p * inv;
    g_cosT[i] = (float)cos(fr);
    g_sinT[i] = (float)sin(fr);
}

// ---------------- float -> half convert (vectorized) ----------------
__global__ void f2h_kernel(const float* __restrict__ src, __half* __restrict__ dst, int n4) {
    int i = blockIdx.x * blockDim.x + threadIdx.x;
    if (i >= n4) return;
    float4 v = ((const float4*)src)[i];
    __half2 lo = __floats2half2_rn(v.x, v.y);
    __half2 hi = __floats2half2_rn(v.z, v.w);
    uint2 o;
    o.x = *(uint32_t*)&lo;
    o.y = *(uint32_t*)&hi;
    ((uint2*)dst)[i] = o;
}

// ---------------- W[k][n] fp32 -> WT[n][k] fp16 ----------------
__global__ void transpose_h_kernel(const float* __restrict__ W, __half* __restrict__ T) {
    __shared__ float tile[32][33];
    int bx = blockIdx.x * 32;   // n
    int by = blockIdx.y * 32;   // k
    int x = threadIdx.x, y = threadIdx.y;   // (32, 8)
    #pragma unroll
    for (int j = 0; j < 4; ++j)
        tile[y + 8 * j][x] = W[(by + y + 8 * j) * DIM + bx + x];
    __syncthreads();
    #pragma unroll
    for (int j = 0; j < 4; ++j)
        T[(size_t)(bx + y + 8 * j) * DIM + by + x] = __float2half(tile[x][y + 8 * j]);
}

// ---------------- fp16 mma.sync GEMM: C[8192,768] = A @ B^T + bias ----------------
// A: [ROWS][DIM] fp16 row-major.  B: [DIM(n)][DIM(k)] fp16 (W transposed).
// Block 128x128, K-slab 64 (one SW128 row = 128B), double-buffered cp.async.
#define NKT (DIM / 64)          // 12
#define AS_BYTES (128 * 128)    // 16 KB per tensor tile
#define STAGE_B (2 * AS_BYTES)  // A + B
#define GEMM_SMEM (2 * STAGE_B) // 64 KB

#define LDSM_X4(r0, r1, r2, r3, addr)                                          \
    asm volatile("ldmatrix.sync.aligned.m8n8.x4.shared.b16 {%0,%1,%2,%3}, [%4];" \
                 : "=r"(r0), "=r"(r1), "=r"(r2), "=r"(r3) : "r"(addr))

#define MMA16816(c, a, b0, b1)                                                 \
    asm volatile("mma.sync.aligned.m16n8k16.row.col.f32.f16.f16.f32 "          \
                 "{%0,%1,%2,%3}, {%4,%5,%6,%7}, {%8,%9}, {%0,%1,%2,%3};"       \
                 : "+f"((c)[0]), "+f"((c)[1]), "+f"((c)[2]), "+f"((c)[3])      \
                 : "r"((a)[0]), "r"((a)[1]), "r"((a)[2]), "r"((a)[3]),         \
                   "r"(b0), "r"(b1))

__global__ __launch_bounds__(256, 2) void hgemm_kernel(
    const __half* __restrict__ A, const __half* __restrict__ B,
    const float* __restrict__ bias, float* __restrict__ C)
{
    extern __shared__ char sm[];
    const uint32_t sbase = smem_u32(sm);
    const int tid  = threadIdx.x;
    const int lane = tid & 31;
    const int wid  = tid >> 5;
    const int warpM = wid & 3;     // 0..3
    const int warpN = wid >> 2;    // 0..1
    const int m0 = blockIdx.y * 128;
    const int n0 = blockIdx.x * 128;

    float c[2][8][4];
    #pragma unroll
    for (int i = 0; i < 2; ++i)
        #pragma unroll
        for (int j = 0; j < 8; ++j)
            #pragma unroll
            for (int q = 0; q < 4; ++q) c[i][j][q] = 0.f;

    // per-thread cp.async indices: 4 chunks of 16B per tensor per stage
    const int rr0 = tid >> 3;        // stride 32 over i
    const int cc  = tid & 7;

    auto issue_stage = [&](int kt, int s) {
        #pragma unroll
        for (int i = 0; i < 4; ++i) {
            int r = rr0 + i * 32;
            uint32_t sw = (uint32_t)(r * 128 + ((cc ^ (r & 7)) << 4));
            uint32_t da = sbase + s * STAGE_B + sw;
            uint32_t db = da + AS_BYTES;
            const char* ga = (const char*)(A + (size_t)(m0 + r) * DIM + kt * 64 + cc * 8);
            const char* gb = (const char*)(B + (size_t)(n0 + r) * DIM + kt * 64 + cc * 8);
            asm volatile("cp.async.cg.shared.global [%0], [%1], 16;" :: "r"(da), "l"(ga));
            asm volatile("cp.async.cg.shared.global [%0], [%1], 16;" :: "r"(db), "l"(gb));
        }
        asm volatile("cp.async.commit_group;" ::: "memory");
    };

    // ldmatrix lane addressing components
    const int lrow8 = ((lane >> 3) & 1) * 8 + (lane & 7);   // row within 16
    const int lcol16 = (lane >> 4) * 16;                    // byte col offset

    issue_stage(0, 0);

    for (int kt = 0; kt < NKT; ++kt) {
        if (kt + 1 < NKT) {
            issue_stage(kt + 1, (kt + 1) & 1);
            asm volatile("cp.async.wait_group 1;" ::: "memory");
        } else {
            asm volatile("cp.async.wait_group 0;" ::: "memory");
        }
        __syncthreads();

        const uint32_t ab = sbase + (kt & 1) * STAGE_B;
        const uint32_t bb = ab + AS_BYTES;

        #pragma unroll
        for (int ks = 0; ks < 4; ++ks) {
            const int kb = ks * 32;
            uint32_t af[2][4];
            #pragma unroll
            for (int i = 0; i < 2; ++i) {
                int row = warpM * 32 + i * 16 + lrow8;
                int col = kb + lcol16;
                uint32_t ad = ab + row * 128 + ((((col >> 4) ^ (row & 7)) & 7) << 4);
                LDSM_X4(af[i][0], af[i][1], af[i][2], af[i][3], ad);
            }
            uint32_t bf[4][4];
            #pragma unroll
            for (int jj = 0; jj < 4; ++jj) {
                int nrow = warpN * 64 + jj * 16 + lrow8;
                int col = kb + lcol16;
                uint32_t bd = bb + nrow * 128 + ((((col >> 4) ^ (nrow & 7)) & 7) << 4);
                LDSM_X4(bf[jj][0], bf[jj][1], bf[jj][2], bf[jj][3], bd);
            }
            #pragma unroll
            for (int i = 0; i < 2; ++i) {
                #pragma unroll
                for (int j = 0; j < 8; ++j) {
                    const int jj = j >> 1, sel = j & 1;
                    MMA16816(c[i][j], af[i], bf[jj][sel], bf[jj][sel + 2]);
                }
            }
        }
        __syncthreads();
    }

    // epilogue: + bias, fp32 out
    #pragma unroll
    for (int i = 0; i < 2; ++i) {
        #pragma unroll
        for (int j = 0; j < 8; ++j) {
            int row = m0 + warpM * 32 + i * 16 + (lane >> 2);
            int col = n0 + warpN * 64 + j * 8 + (lane & 3) * 2;
            float b0v = bias[col], b1v = bias[col + 1];
            float2 o0 = {c[i][j][0] + b0v, c[i][j][1] + b1v};
            float2 o1 = {c[i][j][2] + b0v, c[i][j][3] + b1v};
            *(float2*)&C[(size_t)row * DIM + col] = o0;
            *(float2*)&C[(size_t)(row + 8) * DIM + col] = o1;
        }
    }
}

// ---------------- 2D RoPE (unchanged, fp32 in place) ----------------
__global__ void rope_kernel(float* __restrict__ T, const int* __restrict__ pos) {
    int idx = blockIdx.x * blockDim.x + threadIdx.x;
    const int total = ROWS * HEADS * 32;
    if (idx >= total) return;
    int j = idx & 31;
    int h = (idx >> 5) % HEADS;
    int s = idx / (32 * HEADS);
    int half = j >> 4;
    int f = j & 15;
    int p = pos[s * 2 + half];
    float c  = g_cosT[p * 16 + f];
    float sn = g_sinT[p * 16 + f];
    int base = s * DIM + h * DH + half * 32 + f;
    float v1 = T[base];
    float v2 = T[base + 16];
    T[base]      = v1 * c - v2 * sn;
    T[base + 16] = v2 * c + v1 * sn;
}

// ---------------- flash attention (unchanged from R1, fp32) ----------------
__device__ __forceinline__ int swz(int row, int d) {
    return row * 64 + ((((d >> 2) ^ ((row >> 2) & 7)) << 2) | (d & 3));
}

__global__ __launch_bounds__(256) void flash_kernel(
    const float* __restrict__ Qp, const float* __restrict__ Kp,
    const float* __restrict__ Vp, float* __restrict__ Ao)
{
    __shared__ float Qs[64 * 64];
    __shared__ float KPs[64 * 64];
    __shared__ float Vs[64 * 64];

    const int t  = threadIdx.x;
    const int tx = t & 15;
    const int ty = t >> 4;
    const int qb = blockIdx.x * 64;
    const int h  = blockIdx.y;
    const int b  = blockIdx.z;
    const long qrow0 = (long)b * SEQ + qb;
    const int col0 = h * DH;

    {
        int r  = t >> 4;
        int d4 = (t & 15) << 2;
        #pragma unroll
        for (int it = 0; it < 4; ++it) {
            int row = r + it * 16;
            *(float4*)&Qs[row * 64 + d4] =
                *(const float4*)&Qp[(qrow0 + row) * DIM + col0 + d4];
        }
    }

    float m_run[4], l_run[4];
    float4 acc[4];
    #pragma unroll
    for (int i = 0; i < 4; ++i) {
        m_run[i] = -1e30f; l_run[i] = 0.f;
        acc[i] = make_float4(0.f, 0.f, 0.f, 0.f);
    }

    for (int kt = 0; kt < SEQ / 64; ++kt) {
        {
            int r  = t >> 4;
            int d4 = (t & 15) << 2;
            #pragma unroll
            for (int it = 0; it < 4; ++it) {
                int row = r + it * 16;
                long g = ((long)b * SEQ + kt * 64 + row) * DIM + col0 + d4;
                *(float4*)&KPs[swz(row, d4)] = *(const float4*)&Kp[g];
                *(float4*)&Vs[row * 64 + d4] = *(const float4*)&Vp[g];
            }
        }
        __syncthreads();

        float s00=0,s01=0,s02=0,s03=0, s10=0,s11=0,s12=0,s13=0;
        float s20=0,s21=0,s22=0,s23=0, s30=0,s31=0,s32=0,s33=0;
        #pragma unroll
        for (int d = 0; d < 64; d += 4) {
            float4 a0 = *(const float4*)&Qs[((ty << 2) + 0) * 64 + d];
            float4 a1 = *(const float4*)&Qs[((ty << 2) + 1) * 64 + d];
            float4 a2 = *(const float4*)&Qs[((ty << 2) + 2) * 64 + d];
            float4 a3 = *(const float4*)&Qs[((ty << 2) + 3) * 64 + d];
            float4 b0 = *(const float4*)&KPs[swz((tx << 2) + 0, d)];
            float4 b1 = *(const float4*)&KPs[swz((tx << 2) + 1, d)];
            float4 b2 = *(const float4*)&KPs[swz((tx << 2) + 2, d)];
            float4 b3 = *(const float4*)&KPs[swz((tx << 2) + 3, d)];
            s00 += a0.x*b0.x + a0.y*b0.y + a0.z*b0.z + a0.w*b0.w;
            s01 += a0.x*b1.x + a0.y*b1.y + a0.z*b1.z + a0.w*b1.w;
            s02 += a0.x*b2.x + a0.y*b2.y + a0.z*b2.z + a0.w*b2.w;
            s03 += a0.x*b3.x + a0.y*b3.y + a0.z*b3.z + a0.w*b3.w;
            s10 += a1.x*b0.x + a1.y*b0.y + a1.z*b0.z + a1.w*b0.w;
            s11 += a1.x*b1.x + a1.y*b1.y + a1.z*b1.z + a1.w*b1.w;
            s12 += a1.x*b2.x + a1.y*b2.y + a1.z*b2.z + a1.w*b2.w;
            s13 += a1.x*b3.x + a1.y*b3.y + a1.z*b3.z + a1.w*b3.w;
            s20 += a2.x*b0.x + a2.y*b0.y + a2.z*b0.z + a2.w*b0.w;
            s21 += a2.x*b1.x + a2.y*b1.y + a2.z*b1.z + a2.w*b1.w;
            s22 += a2.x*b2.x + a2.y*b2.y + a2.z*b2.z + a2.w*b2.w;
            s23 += a2.x*b3.x + a2.y*b3.y + a2.z*b3.z + a2.w*b3.w;
            s30 += a3.x*b0.x + a3.y*b0.y + a3.z*b0.z + a3.w*b0.w;
            s31 += a3.x*b1.x + a3.y*b1.y + a3.z*b1.z + a3.w*b1.w;
            s32 += a3.x*b2.x + a3.y*b2.y + a3.z*b2.z + a3.w*b2.w;
            s33 += a3.x*b3.x + a3.y*b3.y + a3.z*b3.z + a3.w*b3.w;
        }

        float s[4][4] = {{s00,s01,s02,s03},{s10,s11,s12,s13},{s20,s21,s22,s23},{s30,s31,s32,s33}};
        float p[4][4];
        #pragma unroll
        for (int i = 0; i < 4; ++i) {
            float v0 = s[i][0] * 0.125f, v1 = s[i][1] * 0.125f;
            float v2 = s[i][2] * 0.125f, v3 = s[i][3] * 0.125f;
            float mx = fmaxf(fmaxf(v0, v1), fmaxf(v2, v3));
            mx = fmaxf(mx, __shfl_xor_sync(0xffffffffu, mx, 1));
            mx = fmaxf(mx, __shfl_xor_sync(0xffffffffu, mx, 2));
            mx = fmaxf(mx, __shfl_xor_sync(0xffffffffu, mx, 4));
            mx = fmaxf(mx, __shfl_xor_sync(0xffffffffu, mx, 8));
            float mnew = fmaxf(m_run[i], mx);
            float corr = __expf(m_run[i] - mnew);
            m_run[i] = mnew;
            p[i][0] = __expf(v0 - mnew);
            p[i][1] = __expf(v1 - mnew);
            p[i][2] = __expf(v2 - mnew);
            p[i][3] = __expf(v3 - mnew);
            float ps = p[i][0] + p[i][1] + p[i][2] + p[i][3];
            ps += __shfl_xor_sync(0xffffffffu, ps, 1);
            ps += __shfl_xor_sync(0xffffffffu, ps, 2);
            ps += __shfl_xor_sync(0xffffffffu, ps, 4);
            ps += __shfl_xor_sync(0xffffffffu, ps, 8);
            l_run[i] = l_run[i] * corr + ps;
            acc[i].x *= corr; acc[i].y *= corr; acc[i].z *= corr; acc[i].w *= corr;
        }
        __syncthreads();

        #pragma unroll
        for (int i = 0; i < 4; ++i)
            *(float4*)&KPs[swz((ty << 2) + i, tx << 2)] =
                make_float4(p[i][0], p[i][1], p[i][2], p[i][3]);
        __syncthreads();

        #pragma unroll
        for (int kv = 0; kv < 64; kv += 4) {
            float4 a0 = *(const float4*)&KPs[swz((ty << 2) + 0, kv)];
            float4 a1 = *(const float4*)&KPs[swz((ty << 2) + 1, kv)];
            float4 a2 = *(const float4*)&KPs[swz((ty << 2) + 2, kv)];
            float4 a3 = *(const float4*)&KPs[swz((ty << 2) + 3, kv)];
            float4 b0 = *(const float4*)&Vs[(kv + 0) * 64 + (tx << 2)];
            float4 b1 = *(const float4*)&Vs[(kv + 1) * 64 + (tx << 2)];
            float4 b2 = *(const float4*)&Vs[(kv + 2) * 64 + (tx << 2)];
            float4 b3 = *(const float4*)&Vs[(kv + 3) * 64 + (tx << 2)];
            acc[0].x += a0.x*b0.x + a0.y*b1.x + a0.z*b2.x + a0.w*b3.x;
            acc[0].y += a0.x*b0.y + a0.y*b1.y + a0.z*b2.y + a0.w*b3.y;
            acc[0].z += a0.x*b0.z + a0.y*b1.z + a0.z*b2.z + a0.w*b3.z;
            acc[0].w += a0.x*b0.w + a0.y*b1.w + a0.z*b2.w + a0.w*b3.w;
            acc[1].x += a1.x*b0.x + a1.y*b1.x + a1.z*b2.x + a1.w*b3.x;
            acc[1].y += a1.x*b0.y + a1.y*b1.y + a1.z*b2.y + a1.w*b3.y;
            acc[1].z += a1.x*b0.z + a1.y*b1.z + a1.z*b2.z + a1.w*b3.z;
            acc[1].w += a1.x*b0.w + a1.y*b1.w + a1.z*b2.w + a1.w*b3.w;
            acc[2].x += a2.x*b0.x + a2.y*b1.x + a2.z*b2.x + a2.w*b3.x;
            acc[2].y += a2.x*b0.y + a2.y*b1.y + a2.z*b2.y + a2.w*b3.y;
            acc[2].z += a2.x*b0.z + a2.y*b1.z + a2.z*b2.z + a2.w*b3.z;
            acc[2].w += a2.x*b0.w + a2.y*b1.w + a2.z*b2.w + a2.w*b3.w;
            acc[3].x += a3.x*b0.x + a3.y*b1.x + a3.z*b2.x + a3.w*b3.x;
            acc[3].y += a3.x*b0.y + a3.y*b1.y + a3.z*b2.y + a3.w*b3.y;
            acc[3].z += a3.x*b0.z + a3.y*b1.z + a3.z*b2.z + a3.w*b3.z;
            acc[3].w += a3.x*b0.w + a3.y*b1.w + a3.z*b2.w + a3.w*b3.w;
        }
        __syncthreads();
    }

    #pragma unroll
    for (int i = 0; i < 4; ++i) {
        float inv = 1.0f / l_run[i];
        float4 o = acc[i];
        o.x *= inv; o.y *= inv; o.z *= inv; o.w *= inv;
        *(float4*)&Ao[(qrow0 + (ty << 2) + i) * DIM + col0 + (tx << 2)] = o;
    }
}

// ---------------- launch ----------------
extern "C" void kernel_launch(void* const* d_in, const int* in_sizes, int n_in,
                              void* d_out, int out_size) {
    const float* x      = (const float*)d_in[0];
    const float* y      = (const float*)d_in[1];
    const int*   pos_q  = (const int*)d_in[2];
    const int*   pos_kv = (const int*)d_in[3];
    const float* Wq = (const float*)d_in[4];
    const float* bq = (const float*)d_in[5];
    const float* Wk = (const float*)d_in[6];
    const float* bk = (const float*)d_in[7];
    const float* Wv = (const float*)d_in[8];
    const float* bv = (const float*)d_in[9];
    const float* Wo = (const float*)d_in[10];
    const float* bo = (const float*)d_in[11];
    float* out = (float*)d_out;

    float *Qp, *Kp, *Vp, *Ao;
    __half *Xh, *Yh, *WT;
    cudaGetSymbolAddress((void**)&Qp, g_Q);
    cudaGetSymbolAddress((void**)&Kp, g_K);
    cudaGetSymbolAddress((void**)&Vp, g_V);
    cudaGetSymbolAddress((void**)&Ao, g_AO);
    cudaGetSymbolAddress((void**)&Xh, g_Xh);
    cudaGetSymbolAddress((void**)&Yh, g_Yh);
    cudaGetSymbolAddress((void**)&WT, g_WT);

    cudaFuncSetAttribute(hgemm_kernel,
                         cudaFuncAttributeMaxDynamicSharedMemorySize, GEMM_SMEM);

    init_tables_kernel<<<1, 512>>>();

    const int n4 = (ROWS * DIM) / 4;
    const dim3 tgrid(DIM / 32, DIM / 32);
    const dim3 tblk(32, 8);
    const dim3 ggrid(DIM / 128, ROWS / 128);   // (6, 64)

    f2h_kernel<<<(n4 + 255) / 256, 256>>>(x, Xh, n4);
    f2h_kernel<<<(n4 + 255) / 256, 256>>>(y, Yh, n4);

    transpose_h_kernel<<<tgrid, tblk>>>(Wq, WT);
    hgemm_kernel<<<ggrid, 256, GEMM_SMEM>>>(Xh, WT, bq, Qp);

    transpose_h_kernel<<<tgrid, tblk>>>(Wk, WT);
    hgemm_kernel<<<ggrid, 256, GEMM_SMEM>>>(Yh, WT, bk, Kp);

    transpose_h_kernel<<<tgrid, tblk>>>(Wv, WT);
    hgemm_kernel<<<ggrid, 256, GEMM_SMEM>>>(Yh, WT, bv, Vp);

    const int rope_total = ROWS * HEADS * 32;
    rope_kernel<<<(rope_total + 255) / 256, 256>>>(Qp, pos_q);
    rope_kernel<<<(rope_total + 255) / 256, 256>>>(Kp, pos_kv);

    dim3 agrid(SEQ / 64, HEADS, BATCH);
    flash_kernel<<<agrid, 256>>>(Qp, Kp, Vp, Ao);

    f2h_kernel<<<(n4 + 255) / 256, 256>>>(Ao, Xh, n4);
    transpose_h_kernel<<<tgrid, tblk>>>(Wo, WT);
    hgemm_kernel<<<ggrid, 256, GEMM_SMEM>>>(Xh, WT, bo, out);
}

// round 5
// speedup vs baseline: 4.8689x; 2.5819x over previous
#include <cuda_runtime.h>
#include <cuda_fp16.h>
#include <math.h>
#include <stdint.h>

#define HEADS 12
#define DH 64
#define DIM 768
#define BATCH 8
#define SEQ 1024
#define ROWS (BATCH * SEQ)   // 8192

#define QSCALE 0.1803368801111204f   // 0.125 * log2(e)

// ---------------- scratch ----------------
__device__ float g_Q[ROWS * DIM];
__device__ float g_K[ROWS * DIM];
__device__ float g_V[ROWS * DIM];
__device__ float g_AO[ROWS * DIM];
__device__ __half g_Xh[ROWS * DIM];
__device__ __half g_Yh[ROWS * DIM];
__device__ __half g_WT[DIM * DIM];
__device__ __half g_Qh[ROWS * DIM];
__device__ __half g_Ql[ROWS * DIM];
__device__ __half g_Kh[ROWS * DIM];
__device__ __half g_Kl[ROWS * DIM];
__device__ __half g_Vh[ROWS * DIM];
__device__ __half g_Vl[ROWS * DIM];
__device__ float g_cosT[512];
__device__ float g_sinT[512];

// ---------------- helpers ----------------
__device__ __forceinline__ uint32_t smem_u32(const void* p) {
    uint32_t a;
    asm("{ .reg .u64 t; cvta.to.shared.u64 t, %1; cvt.u32.u64 %0, t; }" : "=r"(a) : "l"(p));
    return a;
}
__device__ __forceinline__ float ex2f(float x) {
    float y;
    asm("ex2.approx.ftz.f32 %0, %1;" : "=f"(y) : "f"(x));
    return y;
}

#define LDSM_X4(r0, r1, r2, r3, addr)                                          \
    asm volatile("ldmatrix.sync.aligned.m8n8.x4.shared.b16 {%0,%1,%2,%3}, [%4];" \
                 : "=r"(r0), "=r"(r1), "=r"(r2), "=r"(r3) : "r"(addr))

#define LDSM_X4_T(r0, r1, r2, r3, addr)                                        \
    asm volatile("ldmatrix.sync.aligned.m8n8.x4.trans.shared.b16 {%0,%1,%2,%3}, [%4];" \
                 : "=r"(r0), "=r"(r1), "=r"(r2), "=r"(r3) : "r"(addr))

#define MMA16816(c, a, b0, b1)                                                 \
    asm volatile("mma.sync.aligned.m16n8k16.row.col.f32.f16.f16.f32 "          \
                 "{%0,%1,%2,%3}, {%4,%5,%6,%7}, {%8,%9}, {%0,%1,%2,%3};"       \
                 : "+f"((c)[0]), "+f"((c)[1]), "+f"((c)[2]), "+f"((c)[3])      \
                 : "r"((a)[0]), "r"((a)[1]), "r"((a)[2]), "r"((a)[3]),         \
                   "r"(b0), "r"(b1))

#define CP_ASYNC16(dst, src)                                                   \
    asm volatile("cp.async.cg.shared.global [%0], [%1], 16;" :: "r"(dst), "l"(src))
#define CP_COMMIT() asm volatile("cp.async.commit_group;" ::: "memory")
#define CP_WAIT(n)  asm volatile("cp.async.wait_group %0;" :: "n"(n) : "memory")

// ---------------- RoPE tables ----------------
__global__ void init_tables_kernel() {
    int i = threadIdx.x;
    int p = i >> 4;
    int f = i & 15;
    double inv = pow(100.0, -((double)(2 * f)) / 32.0);
    double fr = (double)p * inv;
    g_cosT[i] = (float)cos(fr);
    g_sinT[i] = (float)sin(fr);
}

// ---------------- float -> half ----------------
__global__ void f2h_kernel(const float* __restrict__ src, __half* __restrict__ dst, int n4) {
    int i = blockIdx.x * blockDim.x + threadIdx.x;
    if (i >= n4) return;
    float4 v = ((const float4*)src)[i];
    __half2 lo = __floats2half2_rn(v.x, v.y);
    __half2 hi = __floats2half2_rn(v.z, v.w);
    uint2 o;
    o.x = *(uint32_t*)&lo;
    o.y = *(uint32_t*)&hi;
    ((uint2*)dst)[i] = o;
}

// ---------------- fp32 -> fp16 hi/lo split (with scale) ----------------
__global__ void split_kernel(const float* __restrict__ src, __half* __restrict__ hi,
                             __half* __restrict__ lo, float scale, int n4) {
    int i = blockIdx.x * blockDim.x + threadIdx.x;
    if (i >= n4) return;
    float4 v = ((const float4*)src)[i];
    v.x *= scale; v.y *= scale; v.z *= scale; v.w *= scale;
    __half hx = __float2half(v.x), hy = __float2half(v.y);
    __half hz = __float2half(v.z), hw = __float2half(v.w);
    __half lx = __float2half(v.x - __half2float(hx));
    __half ly = __float2half(v.y - __half2float(hy));
    __half lz = __float2half(v.z - __half2float(hz));
    __half lw = __float2half(v.w - __half2float(hw));
    __half2 h01 = __halves2half2(hx, hy), h23 = __halves2half2(hz, hw);
    __half2 l01 = __halves2half2(lx, ly), l23 = __halves2half2(lz, lw);
    uint2 ho, loo;
    ho.x = *(uint32_t*)&h01;  ho.y = *(uint32_t*)&h23;
    loo.x = *(uint32_t*)&l01; loo.y = *(uint32_t*)&l23;
    ((uint2*)hi)[i] = ho;
    ((uint2*)lo)[i] = loo;
}

// ---------------- W[k][n] fp32 -> WT[n][k] fp16 ----------------
__global__ void transpose_h_kernel(const float* __restrict__ W, __half* __restrict__ T) {
    __shared__ float tile[32][33];
    int bx = blockIdx.x * 32;
    int by = blockIdx.y * 32;
    int x = threadIdx.x, y = threadIdx.y;
    #pragma unroll
    for (int j = 0; j < 4; ++j)
        tile[y + 8 * j][x] = W[(by + y + 8 * j) * DIM + bx + x];
    __syncthreads();
    #pragma unroll
    for (int j = 0; j < 4; ++j)
        T[(size_t)(bx + y + 8 * j) * DIM + by + x] = __float2half(tile[x][y + 8 * j]);
}

// ---------------- fp16 mma.sync GEMM (unchanged from R4) ----------------
#define NKT (DIM / 64)
#define AS_BYTES (128 * 128)
#define STAGE_B (2 * AS_BYTES)
#define GEMM_SMEM (2 * STAGE_B)

__global__ __launch_bounds__(256, 2) void hgemm_kernel(
    const __half* __restrict__ A, const __half* __restrict__ B,
    const float* __restrict__ bias, float* __restrict__ C)
{
    extern __shared__ char sm[];
    const uint32_t sbase = smem_u32(sm);
    const int tid  = threadIdx.x;
    const int lane = tid & 31;
    const int wid  = tid >> 5;
    const int warpM = wid & 3;
    const int warpN = wid >> 2;
    const int m0 = blockIdx.y * 128;
    const int n0 = blockIdx.x * 128;

    float c[2][8][4];
    #pragma unroll
    for (int i = 0; i < 2; ++i)
        #pragma unroll
        for (int j = 0; j < 8; ++j)
            #pragma unroll
            for (int q = 0; q < 4; ++q) c[i][j][q] = 0.f;

    const int rr0 = tid >> 3;
    const int cc  = tid & 7;

    auto issue_stage = [&](int kt, int s) {
        #pragma unroll
        for (int i = 0; i < 4; ++i) {
            int r = rr0 + i * 32;
            uint32_t sw = (uint32_t)(r * 128 + ((cc ^ (r & 7)) << 4));
            uint32_t da = sbase + s * STAGE_B + sw;
            uint32_t db = da + AS_BYTES;
            const char* ga = (const char*)(A + (size_t)(m0 + r) * DIM + kt * 64 + cc * 8);
            const char* gb = (const char*)(B + (size_t)(n0 + r) * DIM + kt * 64 + cc * 8);
            CP_ASYNC16(da, ga);
            CP_ASYNC16(db, gb);
        }
        CP_COMMIT();
    };

    const int lrow8 = ((lane >> 3) & 1) * 8 + (lane & 7);
    const int lcol16 = (lane >> 4) * 16;

    issue_stage(0, 0);

    for (int kt = 0; kt < NKT; ++kt) {
        if (kt + 1 < NKT) {
            issue_stage(kt + 1, (kt + 1) & 1);
            CP_WAIT(1);
        } else {
            CP_WAIT(0);
        }
        __syncthreads();

        const uint32_t ab = sbase + (kt & 1) * STAGE_B;
        const uint32_t bb = ab + AS_BYTES;

        #pragma unroll
        for (int ks = 0; ks < 4; ++ks) {
            const int kb = ks * 32;
            uint32_t af[2][4];
            #pragma unroll
            for (int i = 0; i < 2; ++i) {
                int row = warpM * 32 + i * 16 + lrow8;
                int col = kb + lcol16;
                uint32_t ad = ab + row * 128 + ((((col >> 4) ^ (row & 7)) & 7) << 4);
                LDSM_X4(af[i][0], af[i][1], af[i][2], af[i][3], ad);
            }
            uint32_t bf[4][4];
            #pragma unroll
            for (int jj = 0; jj < 4; ++jj) {
                int nrow = warpN * 64 + jj * 16 + lrow8;
                int col = kb + lcol16;
                uint32_t bd = bb + nrow * 128 + ((((col >> 4) ^ (nrow & 7)) & 7) << 4);
                LDSM_X4(bf[jj][0], bf[jj][1], bf[jj][2], bf[jj][3], bd);
            }
            #pragma unroll
            for (int i = 0; i < 2; ++i) {
                #pragma unroll
                for (int j = 0; j < 8; ++j) {
                    const int jj = j >> 1, sel = j & 1;
                    MMA16816(c[i][j], af[i], bf[jj][sel], bf[jj][sel + 2]);
                }
            }
        }
        __syncthreads();
    }

    #pragma unroll
    for (int i = 0; i < 2; ++i) {
        #pragma unroll
        for (int j = 0; j < 8; ++j) {
            int row = m0 + warpM * 32 + i * 16 + (lane >> 2);
            int col = n0 + warpN * 64 + j * 8 + (lane & 3) * 2;
            float b0v = bias[col], b1v = bias[col + 1];
            float2 o0 = {c[i][j][0] + b0v, c[i][j][1] + b1v};
            float2 o1 = {c[i][j][2] + b0v, c[i][j][3] + b1v};
            *(float2*)&C[(size_t)row * DIM + col] = o0;
            *(float2*)&C[(size_t)(row + 8) * DIM + col] = o1;
        }
    }
}

// ---------------- 2D RoPE (fp32 in place) ----------------
__global__ void rope_kernel(float* __restrict__ T, const int* __restrict__ pos) {
    int idx = blockIdx.x * blockDim.x + threadIdx.x;
    const int total = ROWS * HEADS * 32;
    if (idx >= total) return;
    int j = idx & 31;
    int h = (idx >> 5) % HEADS;
    int s = idx / (32 * HEADS);
    int half = j >> 4;
    int f = j & 15;
    int p = pos[s * 2 + half];
    float c  = g_cosT[p * 16 + f];
    float sn = g_sinT[p * 16 + f];
    int base = s * DIM + h * DH + half * 32 + f;
    float v1 = T[base];
    float v2 = T[base + 16];
    T[base]      = v1 * c - v2 * sn;
    T[base + 16] = v2 * c + v1 * sn;
}

// ---------------- fp16 tensor-core flash attention ----------------
// 128 q x 64 kv tiles; 8 warps, each warp m16 q-rows.
// QK 3-pass (Qh*Kh + Qh*Kl + Ql*Kh), PV 2-pass (P*Vh + P*Vl).
// Q pre-scaled by 0.125*log2(e); softmax via ex2.
#define FS_STAGE 32768                        // Kh,Kl,Vh,Vl @ 8 KB each
#define FS_Q_OFF (2 * FS_STAGE)               // 65536
#define FS_SMEM (FS_Q_OFF + 2 * 16384)        // 98304

__global__ __launch_bounds__(256) void flash16_kernel(
    const __half* __restrict__ Qh, const __half* __restrict__ Ql,
    const __half* __restrict__ Kh, const __half* __restrict__ Kl,
    const __half* __restrict__ Vh, const __half* __restrict__ Vl,
    float* __restrict__ Ao)
{
    extern __shared__ char sm[];
    const uint32_t sb = smem_u32(sm);
    const int tid  = threadIdx.x;
    const int lane = tid & 31;
    const int wid  = tid >> 5;
    const int qb   = blockIdx.x * 128;
    const int h    = blockIdx.y;
    const int b    = blockIdx.z;
    const size_t qrow0 = (size_t)b * SEQ + qb;
    const int colh = h * DH;

    const int lrow8  = ((lane >> 3) & 1) * 8 + (lane & 7);
    const int lcol16 = (lane >> 4) * 16;

    // ---- prologue: load Q hi/lo tiles (128 x 64 halves each) ----
    #pragma unroll
    for (int i = 0; i < 4; ++i) {
        int idx = tid + i * 256;
        int r = idx >> 3, c = idx & 7;
        uint32_t sw = (uint32_t)(r * 128 + ((c ^ (r & 7)) << 4));
        size_t goff = (qrow0 + r) * DIM + colh + c * 8;
        CP_ASYNC16(sb + FS_Q_OFF + sw,        (const char*)(Qh + goff));
        CP_ASYNC16(sb + FS_Q_OFF + 16384 + sw,(const char*)(Ql + goff));
    }
    CP_COMMIT();

    auto issue_kv = [&](int kt, int s) {
        const size_t rowbase = (size_t)b * SEQ + (size_t)kt * 64;
        const uint32_t st = sb + s * FS_STAGE;
        #pragma unroll
        for (int i = 0; i < 2; ++i) {
            int idx = tid + i * 256;
            int r = idx >> 3, c = idx & 7;
            uint32_t sw = (uint32_t)(r * 128 + ((c ^ (r & 7)) << 4));
            size_t goff = (rowbase + r) * DIM + colh + c * 8;
            CP_ASYNC16(st + sw,         (const char*)(Kh + goff));
            CP_ASYNC16(st + 8192 + sw,  (const char*)(Kl + goff));
            CP_ASYNC16(st + 16384 + sw, (const char*)(Vh + goff));
            CP_ASYNC16(st + 24576 + sw, (const char*)(Vl + goff));
        }
        CP_COMMIT();
    };

    issue_kv(0, 0);
    CP_WAIT(0);
    __syncthreads();

    // ---- extract persistent Q fragments ----
    uint32_t qhf[4][4], qlf[4][4];
    #pragma unroll
    for (int kc = 0; kc < 4; ++kc) {
        int row = wid * 16 + lrow8;
        int col = kc * 32 + lcol16;
        uint32_t ad = sb + FS_Q_OFF + row * 128 + ((((col >> 4) ^ (row & 7)) & 7) << 4);
        LDSM_X4(qhf[kc][0], qhf[kc][1], qhf[kc][2], qhf[kc][3], ad);
        LDSM_X4(qlf[kc][0], qlf[kc][1], qlf[kc][2], qlf[kc][3], ad + 16384);
    }

    float o[8][4];
    #pragma unroll
    for (int i = 0; i < 8; ++i)
        #pragma unroll
        for (int q = 0; q < 4; ++q) o[i][q] = 0.f;
    float m0 = -1e30f, m1 = -1e30f, l0 = 0.f, l1 = 0.f;

    for (int kt = 0; kt < SEQ / 64; ++kt) {
        if (kt + 1 < SEQ / 64) {
            issue_kv(kt + 1, (kt + 1) & 1);
            CP_WAIT(1);
        } else {
            CP_WAIT(0);
        }
        __syncthreads();

        const uint32_t kb  = sb + (kt & 1) * FS_STAGE;       // Kh
        const uint32_t vb  = kb + 16384;                      // Vh

        // ---- S = Q K^T (3-pass) ----
        float s[8][4];
        #pragma unroll
        for (int i = 0; i < 8; ++i)
            #pragma unroll
            for (int q = 0; q < 4; ++q) s[i][q] = 0.f;

        #pragma unroll
        for (int kc = 0; kc < 4; ++kc) {
            const int col = kc * 32 + lcol16;
            #pragma unroll
            for (int nb2 = 0; nb2 < 4; ++nb2) {
                int row = nb2 * 16 + lrow8;
                uint32_t ad = kb + row * 128 + ((((col >> 4) ^ (row & 7)) & 7) << 4);
                uint32_t f0, f1, f2, f3;
                LDSM_X4(f0, f1, f2, f3, ad);
                MMA16816(s[2 * nb2],     qhf[kc], f0, f2);
                MMA16816(s[2 * nb2 + 1], qhf[kc], f1, f3);
                MMA16816(s[2 * nb2],     qlf[kc], f0, f2);
                MMA16816(s[2 * nb2 + 1], qlf[kc], f1, f3);
                LDSM_X4(f0, f1, f2, f3, ad + 8192);           // Kl
                MMA16816(s[2 * nb2],     qhf[kc], f0, f2);
                MMA16816(s[2 * nb2 + 1], qhf[kc], f1, f3);
            }
        }

        // ---- online softmax (scores already in log2 units) ----
        float mx0 = -1e30f, mx1 = -1e30f;
        #pragma unroll
        for (int nb = 0; nb < 8; ++nb) {
            mx0 = fmaxf(mx0, fmaxf(s[nb][0], s[nb][1]));
            mx1 = fmaxf(mx1, fmaxf(s[nb][2], s[nb][3]));
        }
        mx0 = fmaxf(mx0, __shfl_xor_sync(0xffffffffu, mx0, 1));
        mx0 = fmaxf(mx0, __shfl_xor_sync(0xffffffffu, mx0, 2));
        mx1 = fmaxf(mx1, __shfl_xor_sync(0xffffffffu, mx1, 1));
        mx1 = fmaxf(mx1, __shfl_xor_sync(0xffffffffu, mx1, 2));
        float mn0 = fmaxf(m0, mx0), mn1 = fmaxf(m1, mx1);
        float cr0 = ex2f(m0 - mn0), cr1 = ex2f(m1 - mn1);
        m0 = mn0; m1 = mn1;

        float ls0 = 0.f, ls1 = 0.f;
        uint32_t a[4][4];
        #pragma unroll
        for (int nb = 0; nb < 8; ++nb) {
            float p0 = ex2f(s[nb][0] - mn0);
            float p1 = ex2f(s[nb][1] - mn0);
            float p2 = ex2f(s[nb][2] - mn1);
            float p3 = ex2f(s[nb][3] - mn1);
            ls0 += p0 + p1;
            ls1 += p2 + p3;
            __half2 h01 = __floats2half2_rn(p0, p1);
            __half2 h23 = __floats2half2_rn(p2, p3);
            int kc = nb >> 1;
            if ((nb & 1) == 0) {
                a[kc][0] = *(uint32_t*)&h01;
                a[kc][1] = *(uint32_t*)&h23;
            } else {
                a[kc][2] = *(uint32_t*)&h01;
                a[kc][3] = *(uint32_t*)&h23;
            }
        }
        ls0 += __shfl_xor_sync(0xffffffffu, ls0, 1);
        ls0 += __shfl_xor_sync(0xffffffffu, ls0, 2);
        ls1 += __shfl_xor_sync(0xffffffffu, ls1, 1);
        ls1 += __shfl_xor_sync(0xffffffffu, ls1, 2);
        l0 = l0 * cr0 + ls0;
        l1 = l1 * cr1 + ls1;
        #pragma unroll
        for (int db = 0; db < 8; ++db) {
            o[db][0] *= cr0; o[db][1] *= cr0;
            o[db][2] *= cr1; o[db][3] *= cr1;
        }

        // ---- O += P V (2-pass: Vh then Vl) ----
        #pragma unroll
        for (int kc = 0; kc < 4; ++kc) {
            int row = kc * 16 + lrow8;                         // kv rows
            #pragma unroll
            for (int db2 = 0; db2 < 4; ++db2) {
                int col = db2 * 32 + lcol16;
                uint32_t ad = vb + row * 128 + ((((col >> 4) ^ (row & 7)) & 7) << 4);
                uint32_t f0, f1, f2, f3;
                LDSM_X4_T(f0, f1, f2, f3, ad);
                MMA16816(o[2 * db2],     a[kc], f0, f1);
                MMA16816(o[2 * db2 + 1], a[kc], f2, f3);
                LDSM_X4_T(f0, f1, f2, f3, ad + 8192);          // Vl
                MMA16816(o[2 * db2],     a[kc], f0, f1);
                MMA16816(o[2 * db2 + 1], a[kc], f2, f3);
            }
        }
        __syncthreads();
    }

    // ---- epilogue ----
    float inv0 = 1.0f / l0, inv1 = 1.0f / l1;
    size_t r0 = qrow0 + wid * 16 + (lane >> 2);
    size_t r1 = r0 + 8;
    int cb = colh + (lane & 3) * 2;
    #pragma unroll
    for (int db = 0; db < 8; ++db) {
        float2 w0 = {o[db][0] * inv0, o[db][1] * inv0};
        float2 w1 = {o[db][2] * inv1, o[db][3] * inv1};
        *(float2*)&Ao[r0 * DIM + cb + db * 8] = w0;
        *(float2*)&Ao[r1 * DIM + cb + db * 8] = w1;
    }
}

// ---------------- launch ----------------
extern "C" void kernel_launch(void* const* d_in, const int* in_sizes, int n_in,
                              void* d_out, int out_size) {
    const float* x      = (const float*)d_in[0];
    const float* y      = (const float*)d_in[1];
    const int*   pos_q  = (const int*)d_in[2];
    const int*   pos_kv = (const int*)d_in[3];
    const float* Wq = (const float*)d_in[4];
    const float* bq = (const float*)d_in[5];
    const float* Wk = (const float*)d_in[6];
    const float* bk = (const float*)d_in[7];
    const float* Wv = (const float*)d_in[8];
    const float* bv = (const float*)d_in[9];
    const float* Wo = (const float*)d_in[10];
    const float* bo = (const float*)d_in[11];
    float* out = (float*)d_out;

    float *Qp, *Kp, *Vp, *Ao;
    __half *Xh, *Yh, *WT, *Qhp, *Qlp, *Khp, *Klp, *Vhp, *Vlp;
    cudaGetSymbolAddress((void**)&Qp, g_Q);
    cudaGetSymbolAddress((void**)&Kp, g_K);
    cudaGetSymbolAddress((void**)&Vp, g_V);
    cudaGetSymbolAddress((void**)&Ao, g_AO);
    cudaGetSymbolAddress((void**)&Xh, g_Xh);
    cudaGetSymbolAddress((void**)&Yh, g_Yh);
    cudaGetSymbolAddress((void**)&WT, g_WT);
    cudaGetSymbolAddress((void**)&Qhp, g_Qh);
    cudaGetSymbolAddress((void**)&Qlp, g_Ql);
    cudaGetSymbolAddress((void**)&Khp, g_Kh);
    cudaGetSymbolAddress((void**)&Klp, g_Kl);
    cudaGetSymbolAddress((void**)&Vhp, g_Vh);
    cudaGetSymbolAddress((void**)&Vlp, g_Vl);

    cudaFuncSetAttribute(hgemm_kernel,
                         cudaFuncAttributeMaxDynamicSharedMemorySize, GEMM_SMEM);
    cudaFuncSetAttribute(flash16_kernel,
                         cudaFuncAttributeMaxDynamicSharedMemorySize, FS_SMEM);

    init_tables_kernel<<<1, 512>>>();

    const int n4 = (ROWS * DIM) / 4;
    const dim3 tgrid(DIM / 32, DIM / 32);
    const dim3 tblk(32, 8);
    const dim3 ggrid(DIM / 128, ROWS / 128);

    f2h_kernel<<<(n4 + 255) / 256, 256>>>(x, Xh, n4);
    f2h_kernel<<<(n4 + 255) / 256, 256>>>(y, Yh, n4);

    transpose_h_kernel<<<tgrid, tblk>>>(Wq, WT);
    hgemm_kernel<<<ggrid, 256, GEMM_SMEM>>>(Xh, WT, bq, Qp);

    transpose_h_kernel<<<tgrid, tblk>>>(Wk, WT);
    hgemm_kernel<<<ggrid, 256, GEMM_SMEM>>>(Yh, WT, bk, Kp);

    transpose_h_kernel<<<tgrid, tblk>>>(Wv, WT);
    hgemm_kernel<<<ggrid, 256, GEMM_SMEM>>>(Yh, WT, bv, Vp);

    const int rope_total = ROWS * HEADS * 32;
    rope_kernel<<<(rope_total + 255) / 256, 256>>>(Qp, pos_q);
    rope_kernel<<<(rope_total + 255) / 256, 256>>>(Kp, pos_kv);

    split_kernel<<<(n4 + 255) / 256, 256>>>(Qp, Qhp, Qlp, QSCALE, n4);
    split_kernel<<<(n4 + 255) / 256, 256>>>(Kp, Khp, Klp, 1.0f, n4);
    split_kernel<<<(n4 + 255) / 256, 256>>>(Vp, Vhp, Vlp, 1.0f, n4);

    dim3 agrid(SEQ / 128, HEADS, BATCH);   // (8, 12, 8)
    flash16_kernel<<<agrid, 256, FS_SMEM>>>(Qhp, Qlp, Khp, Klp, Vhp, Vlp, Ao);

    f2h_kernel<<<(n4 + 255) / 256, 256>>>(Ao, Xh, n4);
    transpose_h_kernel<<<tgrid, tblk>>>(Wo, WT);
    hgemm_kernel<<<ggrid, 256, GEMM_SMEM>>>(Xh, WT, bo, out);
}

// round 7
// speedup vs baseline: 5.2878x; 1.0860x over previous
#include <cuda_runtime.h>
#include <cuda_fp16.h>
#include <math.h>
#include <stdint.h>

#define HEADS 12
#define DH 64
#define DIM 768
#define BATCH 8
#define SEQ 1024
#define ROWS (BATCH * SEQ)   // 8192

#define QSCALE 0.1803368801111204f   // 0.125 * log2(e)

// ---------------- scratch ----------------
__device__ __half g_Xh[ROWS * DIM];   // x fp16
__device__ __half g_Yh[ROWS * DIM];   // y fp16
__device__ __half g_WT[DIM * DIM];    // transposed weight fp16
__device__ __half g_Qh[ROWS * DIM];
__device__ __half g_Ql[ROWS * DIM];
__device__ __half g_Kh[ROWS * DIM];
__device__ __half g_Kl[ROWS * DIM];
__device__ __half g_Vh[ROWS * DIM];
__device__ __half g_Vl[ROWS * DIM];
__device__ __half g_Aoh[ROWS * DIM];  // attention output fp16
__device__ float g_cosT[512];
__device__ float g_sinT[512];

// ---------------- helpers ----------------
__device__ __forceinline__ uint32_t smem_u32(const void* p) {
    uint32_t a;
    asm("{ .reg .u64 t; cvta.to.shared.u64 t, %1; cvt.u32.u64 %0, t; }" : "=r"(a) : "l"(p));
    return a;
}
__device__ __forceinline__ float ex2f(float x) {
    float y;
    asm("ex2.approx.ftz.f32 %0, %1;" : "=f"(y) : "f"(x));
    return y;
}
__device__ __forceinline__ void store_split2(__half* __restrict__ H, __half* __restrict__ L,
                                             size_t off, float x, float y) {
    __half hx = __float2half(x), hy = __float2half(y);
    __half lx = __float2half(x - __half2float(hx));
    __half ly = __float2half(y - __half2float(hy));
    *(__half2*)&H[off] = __halves2half2(hx, hy);
    *(__half2*)&L[off] = __halves2half2(lx, ly);
}

#define LDSM_X4(r0, r1, r2, r3, addr)                                          \
    asm volatile("ldmatrix.sync.aligned.m8n8.x4.shared.b16 {%0,%1,%2,%3}, [%4];" \
                 : "=r"(r0), "=r"(r1), "=r"(r2), "=r"(r3) : "r"(addr))

#define LDSM_X4_T(r0, r1, r2, r3, addr)                                        \
    asm volatile("ldmatrix.sync.aligned.m8n8.x4.trans.shared.b16 {%0,%1,%2,%3}, [%4];" \
                 : "=r"(r0), "=r"(r1), "=r"(r2), "=r"(r3) : "r"(addr))

#define MMA16816(c, a, b0, b1)                                                 \
    asm volatile("mma.sync.aligned.m16n8k16.row.col.f32.f16.f16.f32 "          \
                 "{%0,%1,%2,%3}, {%4,%5,%6,%7}, {%8,%9}, {%0,%1,%2,%3};"       \
                 : "+f"((c)[0]), "+f"((c)[1]), "+f"((c)[2]), "+f"((c)[3])      \
                 : "r"((a)[0]), "r"((a)[1]), "r"((a)[2]), "r"((a)[3]),         \
                   "r"(b0), "r"(b1))

#define CP_ASYNC16(dst, src)                                                   \
    asm volatile("cp.async.cg.shared.global [%0], [%1], 16;" :: "r"(dst), "l"(src))
#define CP_COMMIT() asm volatile("cp.async.commit_group;" ::: "memory")
#define CP_WAIT(n)  asm volatile("cp.async.wait_group %0;" :: "n"(n) : "memory")

// ---------------- RoPE tables ----------------
__global__ void init_tables_kernel() {
    int i = threadIdx.x;
    int p = i >> 4;
    int f = i & 15;
    double inv = pow(100.0, -((double)(2 * f)) / 32.0);
    double fr = (double)p * inv;
    g_cosT[i] = (float)cos(fr);
    g_sinT[i] = (float)sin(fr);
}

// ---------------- float -> half ----------------
__global__ void f2h_kernel(const float* __restrict__ src, __half* __restrict__ dst, int n4) {
    int i = blockIdx.x * blockDim.x + threadIdx.x;
    if (i >= n4) return;
    float4 v = ((const float4*)src)[i];
    __half2 lo = __floats2half2_rn(v.x, v.y);
    __half2 hi = __floats2half2_rn(v.z, v.w);
    uint2 o;
    o.x = *(uint32_t*)&lo;
    o.y = *(uint32_t*)&hi;
    ((uint2*)dst)[i] = o;
}

// ---------------- W[k][n] fp32 -> WT[n][k] fp16 ----------------
__global__ void transpose_h_kernel(const float* __restrict__ W, __half* __restrict__ T) {
    __shared__ float tile[32][33];
    int bx = blockIdx.x * 32;
    int by = blockIdx.y * 32;
    int x = threadIdx.x, y = threadIdx.y;
    #pragma unroll
    for (int j = 0; j < 4; ++j)
        tile[y + 8 * j][x] = W[(by + y + 8 * j) * DIM + bx + x];
    __syncthreads();
    #pragma unroll
    for (int j = 0; j < 4; ++j)
        T[(size_t)(bx + y + 8 * j) * DIM + by + x] = __float2half(tile[x][y + 8 * j]);
}

// ---------------- fp16 mma.sync GEMM with fused epilogues ----------------
// MODE 0: C = A@B^T + bias, fp32 out (final projection)
// MODE 1: rope(C+bias)*QSCALE -> hi/lo fp16 (Q)
// MODE 2: rope(C+bias)        -> hi/lo fp16 (K)
// MODE 3: (C+bias)            -> hi/lo fp16 (V)
#define NKT (DIM / 64)
#define AS_BYTES (128 * 128)
#define STAGE_B (2 * AS_BYTES)
#define GEMM_SMEM (2 * STAGE_B)

template <int MODE>
__global__ __launch_bounds__(256, 2) void hgemm_kernel(
    const __half* __restrict__ A, const __half* __restrict__ B,
    const float* __restrict__ bias, const int* __restrict__ pos,
    float* __restrict__ Cf, __half* __restrict__ Ch, __half* __restrict__ Cl)
{
    extern __shared__ char sm[];
    const uint32_t sbase = smem_u32(sm);
    const int tid  = threadIdx.x;
    const int lane = tid & 31;
    const int wid  = tid >> 5;
    const int warpM = wid & 3;
    const int warpN = wid >> 2;
    const int m0 = blockIdx.y * 128;
    const int n0 = blockIdx.x * 128;

    float c[2][8][4];
    #pragma unroll
    for (int i = 0; i < 2; ++i)
        #pragma unroll
        for (int j = 0; j < 8; ++j)
            #pragma unroll
            for (int q = 0; q < 4; ++q) c[i][j][q] = 0.f;

    const int rr0 = tid >> 3;
    const int cc  = tid & 7;

    auto issue_stage = [&](int kt, int s) {
        #pragma unroll
        for (int i = 0; i < 4; ++i) {
            int r = rr0 + i * 32;
            uint32_t sw = (uint32_t)(r * 128 + ((cc ^ (r & 7)) << 4));
            uint32_t da = sbase + s * STAGE_B + sw;
            uint32_t db = da + AS_BYTES;
            const char* ga = (const char*)(A + (size_t)(m0 + r) * DIM + kt * 64 + cc * 8);
            const char* gb = (const char*)(B + (size_t)(n0 + r) * DIM + kt * 64 + cc * 8);
            CP_ASYNC16(da, ga);
            CP_ASYNC16(db, gb);
        }
        CP_COMMIT();
    };

    const int lrow8 = ((lane >> 3) & 1) * 8 + (lane & 7);
    const int lcol16 = (lane >> 4) * 16;

    issue_stage(0, 0);

    for (int kt = 0; kt < NKT; ++kt) {
        if (kt + 1 < NKT) {
            issue_stage(kt + 1, (kt + 1) & 1);
            CP_WAIT(1);
        } else {
            CP_WAIT(0);
        }
        __syncthreads();

        const uint32_t ab = sbase + (kt & 1) * STAGE_B;
        const uint32_t bb = ab + AS_BYTES;

        #pragma unroll
        for (int ks = 0; ks < 4; ++ks) {
            const int kb = ks * 32;
            uint32_t af[2][4];
            #pragma unroll
            for (int i = 0; i < 2; ++i) {
                int row = warpM * 32 + i * 16 + lrow8;
                int col = kb + lcol16;
                uint32_t ad = ab + row * 128 + ((((col >> 4) ^ (row & 7)) & 7) << 4);
                LDSM_X4(af[i][0], af[i][1], af[i][2], af[i][3], ad);
            }
            uint32_t bf[4][4];
            #pragma unroll
            for (int jj = 0; jj < 4; ++jj) {
                int nrow = warpN * 64 + jj * 16 + lrow8;
                int col = kb + lcol16;
                uint32_t bd = bb + nrow * 128 + ((((col >> 4) ^ (nrow & 7)) & 7) << 4);
                LDSM_X4(bf[jj][0], bf[jj][1], bf[jj][2], bf[jj][3], bd);
            }
            #pragma unroll
            for (int i = 0; i < 2; ++i) {
                #pragma unroll
                for (int j = 0; j < 8; ++j) {
                    const int jj = j >> 1, sel = j & 1;
                    MMA16816(c[i][j], af[i], bf[jj][sel], bf[jj][sel + 2]);
                }
            }
        }
        __syncthreads();
    }

    // ---------------- fused epilogue ----------------
    if (MODE == 0) {
        #pragma unroll
        for (int i = 0; i < 2; ++i) {
            #pragma unroll
            for (int j = 0; j < 8; ++j) {
                int row = m0 + warpM * 32 + i * 16 + (lane >> 2);
                int col = n0 + warpN * 64 + j * 8 + (lane & 3) * 2;
                float b0v = bias[col], b1v = bias[col + 1];
                float2 o0 = {c[i][j][0] + b0v, c[i][j][1] + b1v};
                float2 o1 = {c[i][j][2] + b0v, c[i][j][3] + b1v};
                *(float2*)&Cf[(size_t)row * DIM + col] = o0;
                *(float2*)&Cf[(size_t)(row + 8) * DIM + col] = o1;
            }
        }
    } else if (MODE == 3) {
        #pragma unroll
        for (int i = 0; i < 2; ++i) {
            #pragma unroll
            for (int j = 0; j < 8; ++j) {
                int row = m0 + warpM * 32 + i * 16 + (lane >> 2);
                int col = n0 + warpN * 64 + j * 8 + (lane & 3) * 2;
                float b0v = bias[col], b1v = bias[col + 1];
                store_split2(Ch, Cl, (size_t)row * DIM + col,
                             c[i][j][0] + b0v, c[i][j][1] + b1v);
                store_split2(Ch, Cl, (size_t)(row + 8) * DIM + col,
                             c[i][j][2] + b0v, c[i][j][3] + b1v);
            }
        }
    } else {
        // RoPE fused: pairs (j, j+2) are 16 dims apart inside a head-aligned 64-col group
        const float scale = (MODE == 1) ? QSCALE : 1.0f;
        #pragma unroll
        for (int i = 0; i < 2; ++i) {
            int rowA = m0 + warpM * 32 + i * 16 + (lane >> 2);
            int rowB = rowA + 8;
            int pA0 = pos[2 * rowA], pA1 = pos[2 * rowA + 1];
            int pB0 = pos[2 * rowB], pB1 = pos[2 * rowB + 1];
            #pragma unroll
            for (int jj = 0; jj < 4; ++jj) {
                const int j = (jj < 2) ? jj : jj + 2;   // 0,1,4,5
                const int half = (j >= 4);
                int col = n0 + warpN * 64 + j * 8 + (lane & 3) * 2;
                int f0 = (j & 1) * 8 + (lane & 3) * 2;
                int pA = half ? pA1 : pA0;
                int pB = half ? pB1 : pB0;
                float cA0 = g_cosT[pA * 16 + f0], cA1 = g_cosT[pA * 16 + f0 + 1];
                float sA0 = g_sinT[pA * 16 + f0], sA1 = g_sinT[pA * 16 + f0 + 1];
                float cB0 = g_cosT[pB * 16 + f0], cB1 = g_cosT[pB * 16 + f0 + 1];
                float sB0 = g_sinT[pB * 16 + f0], sB1 = g_sinT[pB * 16 + f0 + 1];
                float b1x = bias[col], b1y = bias[col + 1];
                float b2x = bias[col + 16], b2y = bias[col + 17];

                // row A
                {
                    float v1x = c[i][j][0] + b1x,     v1y = c[i][j][1] + b1y;
                    float v2x = c[i][j + 2][0] + b2x, v2y = c[i][j + 2][1] + b2y;
                    float o1x = (v1x * cA0 - v2x * sA0) * scale;
                    float o1y = (v1y * cA1 - v2y * sA1) * scale;
                    float o2x = (v2x * cA0 + v1x * sA0) * scale;
                    float o2y = (v2y * cA1 + v1y * sA1) * scale;
                    store_split2(Ch, Cl, (size_t)rowA * DIM + col, o1x, o1y);
                    store_split2(Ch, Cl, (size_t)rowA * DIM + col + 16, o2x, o2y);
                }
                // row B
                {
                    float v1x = c[i][j][2] + b1x,     v1y = c[i][j][3] + b1y;
                    float v2x = c[i][j + 2][2] + b2x, v2y = c[i][j + 2][3] + b2y;
                    float o1x = (v1x * cB0 - v2x * sB0) * scale;
                    float o1y = (v1y * cB1 - v2y * sB1) * scale;
                    float o2x = (v2x * cB0 + v1x * sB0) * scale;
                    float o2y = (v2y * cB1 + v1y * sB1) * scale;
                    store_split2(Ch, Cl, (size_t)rowB * DIM + col, o1x, o1y);
                    store_split2(Ch, Cl, (size_t)rowB * DIM + col + 16, o2x, o2y);
                }
            }
        }
    }
}

// ---------------- fp16 tensor-core flash attention (fp16 output) ----------------
#define FS_STAGE 32768
#define FS_Q_OFF (2 * FS_STAGE)
#define FS_SMEM (FS_Q_OFF + 2 * 16384)

__global__ __launch_bounds__(256) void flash16_kernel(
    const __half* __restrict__ Qh, const __half* __restrict__ Ql,
    const __half* __restrict__ Kh, const __half* __restrict__ Kl,
    const __half* __restrict__ Vh, const __half* __restrict__ Vl,
    __half* __restrict__ Ao)
{
    extern __shared__ char sm[];
    const uint32_t sb = smem_u32(sm);
    const int tid  = threadIdx.x;
    const int lane = tid & 31;
    const int wid  = tid >> 5;
    const int qb   = blockIdx.x * 128;
    const int h    = blockIdx.y;
    const int b    = blockIdx.z;
    const size_t qrow0 = (size_t)b * SEQ + qb;
    const int colh = h * DH;

    const int lrow8  = ((lane >> 3) & 1) * 8 + (lane & 7);
    const int lcol16 = (lane >> 4) * 16;

    #pragma unroll
    for (int i = 0; i < 4; ++i) {
        int idx = tid + i * 256;
        int r = idx >> 3, c = idx & 7;
        uint32_t sw = (uint32_t)(r * 128 + ((c ^ (r & 7)) << 4));
        size_t goff = (qrow0 + r) * DIM + colh + c * 8;
        CP_ASYNC16(sb + FS_Q_OFF + sw,         (const char*)(Qh + goff));
        CP_ASYNC16(sb + FS_Q_OFF + 16384 + sw, (const char*)(Ql + goff));
    }
    CP_COMMIT();

    auto issue_kv = [&](int kt, int s) {
        const size_t rowbase = (size_t)b * SEQ + (size_t)kt * 64;
        const uint32_t st = sb + s * FS_STAGE;
        #pragma unroll
        for (int i = 0; i < 2; ++i) {
            int idx = tid + i * 256;
            int r = idx >> 3, c = idx & 7;
            uint32_t sw = (uint32_t)(r * 128 + ((c ^ (r & 7)) << 4));
            size_t goff = (rowbase + r) * DIM + colh + c * 8;
            CP_ASYNC16(st + sw,         (const char*)(Kh + goff));
            CP_ASYNC16(st + 8192 + sw,  (const char*)(Kl + goff));
            CP_ASYNC16(st + 16384 + sw, (const char*)(Vh + goff));
            CP_ASYNC16(st + 24576 + sw, (const char*)(Vl + goff));
        }
        CP_COMMIT();
    };

    issue_kv(0, 0);
    CP_WAIT(0);
    __syncthreads();

    uint32_t qhf[4][4], qlf[4][4];
    #pragma unroll
    for (int kc = 0; kc < 4; ++kc) {
        int row = wid * 16 + lrow8;
        int col = kc * 32 + lcol16;
        uint32_t ad = sb + FS_Q_OFF + row * 128 + ((((col >> 4) ^ (row & 7)) & 7) << 4);
        LDSM_X4(qhf[kc][0], qhf[kc][1], qhf[kc][2], qhf[kc][3], ad);
        LDSM_X4(qlf[kc][0], qlf[kc][1], qlf[kc][2], qlf[kc][3], ad + 16384);
    }

    float o[8][4];
    #pragma unroll
    for (int i = 0; i < 8; ++i)
        #pragma unroll
        for (int q = 0; q < 4; ++q) o[i][q] = 0.f;
    float m0 = -1e30f, m1 = -1e30f, l0 = 0.f, l1 = 0.f;

    for (int kt = 0; kt < SEQ / 64; ++kt) {
        if (kt + 1 < SEQ / 64) {
            issue_kv(kt + 1, (kt + 1) & 1);
            CP_WAIT(1);
        } else {
            CP_WAIT(0);
        }
        __syncthreads();

        const uint32_t kb = sb + (kt & 1) * FS_STAGE;
        const uint32_t vb = kb + 16384;

        float s[8][4];
        #pragma unroll
        for (int i = 0; i < 8; ++i)
            #pragma unroll
            for (int q = 0; q < 4; ++q) s[i][q] = 0.f;

        #pragma unroll
        for (int kc = 0; kc < 4; ++kc) {
            const int col = kc * 32 + lcol16;
            #pragma unroll
            for (int nb2 = 0; nb2 < 4; ++nb2) {
                int row = nb2 * 16 + lrow8;
                uint32_t ad = kb + row * 128 + ((((col >> 4) ^ (row & 7)) & 7) << 4);
                uint32_t f0, f1, f2, f3;
                LDSM_X4(f0, f1, f2, f3, ad);
                MMA16816(s[2 * nb2],     qhf[kc], f0, f2);
                MMA16816(s[2 * nb2 + 1], qhf[kc], f1, f3);
                MMA16816(s[2 * nb2],     qlf[kc], f0, f2);
                MMA16816(s[2 * nb2 + 1], qlf[kc], f1, f3);
                LDSM_X4(f0, f1, f2, f3, ad + 8192);
                MMA16816(s[2 * nb2],     qhf[kc], f0, f2);
                MMA16816(s[2 * nb2 + 1], qhf[kc], f1, f3);
            }
        }

        float mx0 = -1e30f, mx1 = -1e30f;
        #pragma unroll
        for (int nb = 0; nb < 8; ++nb) {
            mx0 = fmaxf(mx0, fmaxf(s[nb][0], s[nb][1]));
            mx1 = fmaxf(mx1, fmaxf(s[nb][2], s[nb][3]));
        }
        mx0 = fmaxf(mx0, __shfl_xor_sync(0xffffffffu, mx0, 1));
        mx0 = fmaxf(mx0, __shfl_xor_sync(0xffffffffu, mx0, 2));
        mx1 = fmaxf(mx1, __shfl_xor_sync(0xffffffffu, mx1, 1));
        mx1 = fmaxf(mx1, __shfl_xor_sync(0xffffffffu, mx1, 2));
        float mn0 = fmaxf(m0, mx0), mn1 = fmaxf(m1, mx1);
        float cr0 = ex2f(m0 - mn0), cr1 = ex2f(m1 - mn1);
        m0 = mn0; m1 = mn1;

        float ls0 = 0.f, ls1 = 0.f;
        uint32_t a[4][4];
        #pragma unroll
        for (int nb = 0; nb < 8; ++nb) {
            float p0 = ex2f(s[nb][0] - mn0);
            float p1 = ex2f(s[nb][1] - mn0);
            float p2 = ex2f(s[nb][2] - mn1);
            float p3 = ex2f(s[nb][3] - mn1);
            ls0 += p0 + p1;
            ls1 += p2 + p3;
            __half2 h01 = __floats2half2_rn(p0, p1);
            __half2 h23 = __floats2half2_rn(p2, p3);
            int kc = nb >> 1;
            if ((nb & 1) == 0) {
                a[kc][0] = *(uint32_t*)&h01;
                a[kc][1] = *(uint32_t*)&h23;
            } else {
                a[kc][2] = *(uint32_t*)&h01;
                a[kc][3] = *(uint32_t*)&h23;
            }
        }
        ls0 += __shfl_xor_sync(0xffffffffu, ls0, 1);
        ls0 += __shfl_xor_sync(0xffffffffu, ls0, 2);
        ls1 += __shfl_xor_sync(0xffffffffu, ls1, 1);
        ls1 += __shfl_xor_sync(0xffffffffu, ls1, 2);
        l0 = l0 * cr0 + ls0;
        l1 = l1 * cr1 + ls1;
        #pragma unroll
        for (int db = 0; db < 8; ++db) {
            o[db][0] *= cr0; o[db][1] *= cr0;
            o[db][2] *= cr1; o[db][3] *= cr1;
        }

        #pragma unroll
        for (int kc = 0; kc < 4; ++kc) {
            int row = kc * 16 + lrow8;
            #pragma unroll
            for (int db2 = 0; db2 < 4; ++db2) {
                int col = db2 * 32 + lcol16;
                uint32_t ad = vb + row * 128 + ((((col >> 4) ^ (row & 7)) & 7) << 4);
                uint32_t f0, f1, f2, f3;
                LDSM_X4_T(f0, f1, f2, f3, ad);
                MMA16816(o[2 * db2],     a[kc], f0, f1);
                MMA16816(o[2 * db2 + 1], a[kc], f2, f3);
                LDSM_X4_T(f0, f1, f2, f3, ad + 8192);
                MMA16816(o[2 * db2],     a[kc], f0, f1);
                MMA16816(o[2 * db2 + 1], a[kc], f2, f3);
            }
        }
        __syncthreads();
    }

    // fp16 epilogue
    float inv0 = 1.0f / l0, inv1 = 1.0f / l1;
    size_t r0 = qrow0 + wid * 16 + (lane >> 2);
    size_t r1 = r0 + 8;
    int cb = colh + (lane & 3) * 2;
    #pragma unroll
    for (int db = 0; db < 8; ++db) {
        __half2 w0 = __floats2half2_rn(o[db][0] * inv0, o[db][1] * inv0);
        __half2 w1 = __floats2half2_rn(o[db][2] * inv1, o[db][3] * inv1);
        *(__half2*)&Ao[r0 * DIM + cb + db * 8] = w0;
        *(__half2*)&Ao[r1 * DIM + cb + db * 8] = w1;
    }
}

// ---------------- launch ----------------
extern "C" void kernel_launch(void* const* d_in, const int* in_sizes, int n_in,
                              void* d_out, int out_size) {
    const float* x      = (const float*)d_in[0];
    const float* y      = (const float*)d_in[1];
    const int*   pos_q  = (const int*)d_in[2];
    const int*   pos_kv = (const int*)d_in[3];
    const float* Wq = (const float*)d_in[4];
    const float* bq = (const float*)d_in[5];
    const float* Wk = (const float*)d_in[6];
    const float* bk = (const float*)d_in[7];
    const float* Wv = (const float*)d_in[8];
    const float* bv = (const float*)d_in[9];
    const float* Wo = (const float*)d_in[10];
    const float* bo = (const float*)d_in[11];
    float* out = (float*)d_out;

    __half *Xh, *Yh, *WT, *Qhp, *Qlp, *Khp, *Klp, *Vhp, *Vlp, *Aohp;
    cudaGetSymbolAddress((void**)&Xh, g_Xh);
    cudaGetSymbolAddress((void**)&Yh, g_Yh);
    cudaGetSymbolAddress((void**)&WT, g_WT);
    cudaGetSymbolAddress((void**)&Qhp, g_Qh);
    cudaGetSymbolAddress((void**)&Qlp, g_Ql);
    cudaGetSymbolAddress((void**)&Khp, g_Kh);
    cudaGetSymbolAddress((void**)&Klp, g_Kl);
    cudaGetSymbolAddress((void**)&Vhp, g_Vh);
    cudaGetSymbolAddress((void**)&Vlp, g_Vl);
    cudaGetSymbolAddress((void**)&Aohp, g_Aoh);

    cudaFuncSetAttribute(hgemm_kernel<0>, cudaFuncAttributeMaxDynamicSharedMemorySize, GEMM_SMEM);
    cudaFuncSetAttribute(hgemm_kernel<1>, cudaFuncAttributeMaxDynamicSharedMemorySize, GEMM_SMEM);
    cudaFuncSetAttribute(hgemm_kernel<2>, cudaFuncAttributeMaxDynamicSharedMemorySize, GEMM_SMEM);
    cudaFuncSetAttribute(hgemm_kernel<3>, cudaFuncAttributeMaxDynamicSharedMemorySize, GEMM_SMEM);
    cudaFuncSetAttribute(flash16_kernel, cudaFuncAttributeMaxDynamicSharedMemorySize, FS_SMEM);

    init_tables_kernel<<<1, 512>>>();

    const int n4 = (ROWS * DIM) / 4;
    const dim3 tgrid(DIM / 32, DIM / 32);
    const dim3 tblk(32, 8);
    const dim3 ggrid(DIM / 128, ROWS / 128);

    f2h_kernel<<<(n4 + 255) / 256, 256>>>(x, Xh, n4);
    f2h_kernel<<<(n4 + 255) / 256, 256>>>(y, Yh, n4);

    transpose_h_kernel<<<tgrid, tblk>>>(Wq, WT);
    hgemm_kernel<1><<<ggrid, 256, GEMM_SMEM>>>(Xh, WT, bq, pos_q, nullptr, Qhp, Qlp);

    transpose_h_kernel<<<tgrid, tblk>>>(Wk, WT);
    hgemm_kernel<2><<<ggrid, 256, GEMM_SMEM>>>(Yh, WT, bk, pos_kv, nullptr, Khp, Klp);

    transpose_h_kernel<<<tgrid, tblk>>>(Wv, WT);
    hgemm_kernel<3><<<ggrid, 256, GEMM_SMEM>>>(Yh, WT, bv, nullptr, nullptr, Vhp, Vlp);

    dim3 agrid(SEQ / 128, HEADS, BATCH);
    flash16_kernel<<<agrid, 256, FS_SMEM>>>(Qhp, Qlp, Khp, Klp, Vhp, Vlp, Aohp);

    transpose_h_kernel<<<tgrid, tblk>>>(Wo, WT);
    hgemm_kernel<0><<<ggrid, 256, GEMM_SMEM>>>(Aohp, WT, bo, nullptr, out, nullptr, nullptr);
}

// round 8
// speedup vs baseline: 5.6104x; 1.0610x over previous
#include <cuda_runtime.h>
#include <cuda_fp16.h>
#include <math.h>
#include <stdint.h>

#define HEADS 12
#define DH 64
#define DIM 768
#define BATCH 8
#define SEQ 1024
#define ROWS (BATCH * SEQ)   // 8192

#define QSCALE 0.1803368801111204f   // 0.125 * log2(e)

// ---------------- scratch ----------------
__device__ __half g_Xh[ROWS * DIM];
__device__ __half g_Yh[ROWS * DIM];
__device__ __half g_WTq[DIM * DIM];
__device__ __half g_WTk[DIM * DIM];
__device__ __half g_WTv[DIM * DIM];
__device__ __half g_WTo[DIM * DIM];
__device__ __half g_Qh[ROWS * DIM];
__device__ __half g_Ql[ROWS * DIM];
__device__ __half g_Kh[ROWS * DIM];
__device__ __half g_Kl[ROWS * DIM];
__device__ __half g_Vh[ROWS * DIM];
__device__ __half g_Vl[ROWS * DIM];
__device__ __half g_Aoh[ROWS * DIM];
__device__ float g_cosT[512];
__device__ float g_sinT[512];

// ---------------- helpers ----------------
__device__ __forceinline__ uint32_t smem_u32(const void* p) {
    uint32_t a;
    asm("{ .reg .u64 t; cvta.to.shared.u64 t, %1; cvt.u32.u64 %0, t; }" : "=r"(a) : "l"(p));
    return a;
}
__device__ __forceinline__ float ex2f(float x) {
    float y;
    asm("ex2.approx.ftz.f32 %0, %1;" : "=f"(y) : "f"(x));
    return y;
}
__device__ __forceinline__ void store_split2(__half* __restrict__ H, __half* __restrict__ L,
                                             size_t off, float x, float y) {
    __half hx = __float2half(x), hy = __float2half(y);
    __half lx = __float2half(x - __half2float(hx));
    __half ly = __float2half(y - __half2float(hy));
    *(__half2*)&H[off] = __halves2half2(hx, hy);
    *(__half2*)&L[off] = __halves2half2(lx, ly);
}

#define LDSM_X4(r0, r1, r2, r3, addr)                                          \
    asm volatile("ldmatrix.sync.aligned.m8n8.x4.shared.b16 {%0,%1,%2,%3}, [%4];" \
                 : "=r"(r0), "=r"(r1), "=r"(r2), "=r"(r3) : "r"(addr))

#define LDSM_X4_T(r0, r1, r2, r3, addr)                                        \
    asm volatile("ldmatrix.sync.aligned.m8n8.x4.trans.shared.b16 {%0,%1,%2,%3}, [%4];" \
                 : "=r"(r0), "=r"(r1), "=r"(r2), "=r"(r3) : "r"(addr))

#define MMA16816(c, a, b0, b1)                                                 \
    asm volatile("mma.sync.aligned.m16n8k16.row.col.f32.f16.f16.f32 "          \
                 "{%0,%1,%2,%3}, {%4,%5,%6,%7}, {%8,%9}, {%0,%1,%2,%3};"       \
                 : "+f"((c)[0]), "+f"((c)[1]), "+f"((c)[2]), "+f"((c)[3])      \
                 : "r"((a)[0]), "r"((a)[1]), "r"((a)[2]), "r"((a)[3]),         \
                   "r"(b0), "r"(b1))

#define CP_ASYNC16(dst, src)                                                   \
    asm volatile("cp.async.cg.shared.global [%0], [%1], 16;" :: "r"(dst), "l"(src))
#define CP_COMMIT() asm volatile("cp.async.commit_group;" ::: "memory")
#define CP_WAIT(n)  asm volatile("cp.async.wait_group %0;" :: "n"(n) : "memory")

// ---------------- RoPE tables ----------------
__global__ void init_tables_kernel() {
    int i = threadIdx.x;
    int p = i >> 4;
    int f = i & 15;
    double inv = pow(100.0, -((double)(2 * f)) / 32.0);
    double fr = (double)p * inv;
    g_cosT[i] = (float)cos(fr);
    g_sinT[i] = (float)sin(fr);
}

// ---------------- float -> half (x and y in one launch) ----------------
__global__ void f2h2_kernel(const float* __restrict__ x, const float* __restrict__ y,
                            __half* __restrict__ Xh, __half* __restrict__ Yh, int n4) {
    int i = blockIdx.x * blockDim.x + threadIdx.x;
    if (i >= n4) return;
    const float* src = blockIdx.y ? y : x;
    __half* dst = blockIdx.y ? Yh : Xh;
    float4 v = ((const float4*)src)[i];
    __half2 lo = __floats2half2_rn(v.x, v.y);
    __half2 hi = __floats2half2_rn(v.z, v.w);
    uint2 o;
    o.x = *(uint32_t*)&lo;
    o.y = *(uint32_t*)&hi;
    ((uint2*)dst)[i] = o;
}

// ---------------- 4 weight transposes in one launch ----------------
__global__ void transpose4_kernel(const float* __restrict__ Wq, const float* __restrict__ Wk,
                                  const float* __restrict__ Wv, const float* __restrict__ Wo,
                                  __half* __restrict__ Tq, __half* __restrict__ Tk,
                                  __half* __restrict__ Tv, __half* __restrict__ To) {
    const int z = blockIdx.z;
    const float* W = (z == 0) ? Wq : (z == 1) ? Wk : (z == 2) ? Wv : Wo;
    __half* T = (z == 0) ? Tq : (z == 1) ? Tk : (z == 2) ? Tv : To;
    __shared__ float tile[32][33];
    int bx = blockIdx.x * 32;
    int by = blockIdx.y * 32;
    int x = threadIdx.x, y = threadIdx.y;
    #pragma unroll
    for (int j = 0; j < 4; ++j)
        tile[y + 8 * j][x] = W[(by + y + 8 * j) * DIM + bx + x];
    __syncthreads();
    #pragma unroll
    for (int j = 0; j < 4; ++j)
        T[(size_t)(bx + y + 8 * j) * DIM + by + x] = __float2half(tile[x][y + 8 * j]);
}

// ---------------- GEMM tile constants ----------------
#define NKT (DIM / 64)
#define AS_BYTES (128 * 128)
#define STAGE_B (2 * AS_BYTES)
#define GEMM_SMEM (2 * STAGE_B)

// ---------------- fused Q/K/V projection GEMM (one launch, z picks mode) ----------------
// z=0: rope(C+bq)*QSCALE -> Qh/Ql   z=1: rope(C+bk) -> Kh/Kl   z=2: (C+bv) -> Vh/Vl
__global__ __launch_bounds__(256, 2) void qkv_gemm_kernel(
    const __half* __restrict__ Xh, const __half* __restrict__ Yh,
    const __half* __restrict__ WTq, const __half* __restrict__ WTk, const __half* __restrict__ WTv,
    const float* __restrict__ bq, const float* __restrict__ bk, const float* __restrict__ bv,
    const int* __restrict__ pos_q, const int* __restrict__ pos_kv,
    __half* __restrict__ Qh, __half* __restrict__ Ql,
    __half* __restrict__ Kh, __half* __restrict__ Kl,
    __half* __restrict__ Vh, __half* __restrict__ Vl)
{
    extern __shared__ char sm[];
    const uint32_t sbase = smem_u32(sm);
    const int z = blockIdx.z;
    const __half* A = (z == 0) ? Xh : Yh;
    const __half* B = (z == 0) ? WTq : (z == 1) ? WTk : WTv;
    const float* bias = (z == 0) ? bq : (z == 1) ? bk : bv;
    const int* pos = (z == 0) ? pos_q : pos_kv;
    __half* Ch = (z == 0) ? Qh : (z == 1) ? Kh : Vh;
    __half* Cl = (z == 0) ? Ql : (z == 1) ? Kl : Vl;

    const int tid  = threadIdx.x;
    const int lane = tid & 31;
    const int wid  = tid >> 5;
    const int warpM = wid & 3;
    const int warpN = wid >> 2;
    const int m0 = blockIdx.y * 128;
    const int n0 = blockIdx.x * 128;

    float c[2][8][4];
    #pragma unroll
    for (int i = 0; i < 2; ++i)
        #pragma unroll
        for (int j = 0; j < 8; ++j)
            #pragma unroll
            for (int q = 0; q < 4; ++q) c[i][j][q] = 0.f;

    const int rr0 = tid >> 3;
    const int cc  = tid & 7;

    auto issue_stage = [&](int kt, int s) {
        #pragma unroll
        for (int i = 0; i < 4; ++i) {
            int r = rr0 + i * 32;
            uint32_t sw = (uint32_t)(r * 128 + ((cc ^ (r & 7)) << 4));
            uint32_t da = sbase + s * STAGE_B + sw;
            uint32_t db = da + AS_BYTES;
            const char* ga = (const char*)(A + (size_t)(m0 + r) * DIM + kt * 64 + cc * 8);
            const char* gb = (const char*)(B + (size_t)(n0 + r) * DIM + kt * 64 + cc * 8);
            CP_ASYNC16(da, ga);
            CP_ASYNC16(db, gb);
        }
        CP_COMMIT();
    };

    const int lrow8 = ((lane >> 3) & 1) * 8 + (lane & 7);
    const int lcol16 = (lane >> 4) * 16;

    issue_stage(0, 0);

    for (int kt = 0; kt < NKT; ++kt) {
        CP_WAIT(0);
        __syncthreads();
        if (kt + 1 < NKT) issue_stage(kt + 1, (kt + 1) & 1);

        const uint32_t ab = sbase + (kt & 1) * STAGE_B;
        const uint32_t bb = ab + AS_BYTES;

        #pragma unroll
        for (int ks = 0; ks < 4; ++ks) {
            const int kb = ks * 32;
            uint32_t af[2][4];
            #pragma unroll
            for (int i = 0; i < 2; ++i) {
                int row = warpM * 32 + i * 16 + lrow8;
                int col = kb + lcol16;
                uint32_t ad = ab + row * 128 + ((((col >> 4) ^ (row & 7)) & 7) << 4);
                LDSM_X4(af[i][0], af[i][1], af[i][2], af[i][3], ad);
            }
            uint32_t bf[4][4];
            #pragma unroll
            for (int jj = 0; jj < 4; ++jj) {
                int nrow = warpN * 64 + jj * 16 + lrow8;
                int col = kb + lcol16;
                uint32_t bd = bb + nrow * 128 + ((((col >> 4) ^ (nrow & 7)) & 7) << 4);
                LDSM_X4(bf[jj][0], bf[jj][1], bf[jj][2], bf[jj][3], bd);
            }
            #pragma unroll
            for (int i = 0; i < 2; ++i) {
                #pragma unroll
                for (int j = 0; j < 8; ++j) {
                    const int jj = j >> 1, sel = j & 1;
                    MMA16816(c[i][j], af[i], bf[jj][sel], bf[jj][sel + 2]);
                }
            }
        }
    }

    // ---------------- fused epilogue ----------------
    if (z == 2) {
        #pragma unroll
        for (int i = 0; i < 2; ++i) {
            #pragma unroll
            for (int j = 0; j < 8; ++j) {
                int row = m0 + warpM * 32 + i * 16 + (lane >> 2);
                int col = n0 + warpN * 64 + j * 8 + (lane & 3) * 2;
                float b0v = bias[col], b1v = bias[col + 1];
                store_split2(Ch, Cl, (size_t)row * DIM + col,
                             c[i][j][0] + b0v, c[i][j][1] + b1v);
                store_split2(Ch, Cl, (size_t)(row + 8) * DIM + col,
                             c[i][j][2] + b0v, c[i][j][3] + b1v);
            }
        }
    } else {
        const float scale = (z == 0) ? QSCALE : 1.0f;
        #pragma unroll
        for (int i = 0; i < 2; ++i) {
            int rowA = m0 + warpM * 32 + i * 16 + (lane >> 2);
            int rowB = rowA + 8;
            int pA0 = pos[2 * rowA], pA1 = pos[2 * rowA + 1];
            int pB0 = pos[2 * rowB], pB1 = pos[2 * rowB + 1];
            #pragma unroll
            for (int jj = 0; jj < 4; ++jj) {
                const int j = (jj < 2) ? jj : jj + 2;   // 0,1,4,5
                const int half = (j >= 4);
                int col = n0 + warpN * 64 + j * 8 + (lane & 3) * 2;
                int f0 = (j & 1) * 8 + (lane & 3) * 2;
                int pA = half ? pA1 : pA0;
                int pB = half ? pB1 : pB0;
                float cA0 = g_cosT[pA * 16 + f0], cA1 = g_cosT[pA * 16 + f0 + 1];
                float sA0 = g_sinT[pA * 16 + f0], sA1 = g_sinT[pA * 16 + f0 + 1];
                float cB0 = g_cosT[pB * 16 + f0], cB1 = g_cosT[pB * 16 + f0 + 1];
                float sB0 = g_sinT[pB * 16 + f0], sB1 = g_sinT[pB * 16 + f0 + 1];
                float b1x = bias[col], b1y = bias[col + 1];
                float b2x = bias[col + 16], b2y = bias[col + 17];

                {
                    float v1x = c[i][j][0] + b1x,     v1y = c[i][j][1] + b1y;
                    float v2x = c[i][j + 2][0] + b2x, v2y = c[i][j + 2][1] + b2y;
                    float o1x = (v1x * cA0 - v2x * sA0) * scale;
                    float o1y = (v1y * cA1 - v2y * sA1) * scale;
                    float o2x = (v2x * cA0 + v1x * sA0) * scale;
                    float o2y = (v2y * cA1 + v1y * sA1) * scale;
                    store_split2(Ch, Cl, (size_t)rowA * DIM + col, o1x, o1y);
                    store_split2(Ch, Cl, (size_t)rowA * DIM + col + 16, o2x, o2y);
                }
                {
                    float v1x = c[i][j][2] + b1x,     v1y = c[i][j][3] + b1y;
                    float v2x = c[i][j + 2][2] + b2x, v2y = c[i][j + 2][3] + b2y;
                    float o1x = (v1x * cB0 - v2x * sB0) * scale;
                    float o1y = (v1y * cB1 - v2y * sB1) * scale;
                    float o2x = (v2x * cB0 + v1x * sB0) * scale;
                    float o2y = (v2y * cB1 + v1y * sB1) * scale;
                    store_split2(Ch, Cl, (size_t)rowB * DIM + col, o1x, o1y);
                    store_split2(Ch, Cl, (size_t)rowB * DIM + col + 16, o2x, o2y);
                }
            }
        }
    }
}

// ---------------- final output GEMM: out = Aoh @ WTo^T + bo (fp32) ----------------
__global__ __launch_bounds__(256, 2) void out_gemm_kernel(
    const __half* __restrict__ A, const __half* __restrict__ B,
    const float* __restrict__ bias, float* __restrict__ Cf)
{
    extern __shared__ char sm[];
    const uint32_t sbase = smem_u32(sm);
    const int tid  = threadIdx.x;
    const int lane = tid & 31;
    const int wid  = tid >> 5;
    const int warpM = wid & 3;
    const int warpN = wid >> 2;
    const int m0 = blockIdx.y * 128;
    const int n0 = blockIdx.x * 128;

    float c[2][8][4];
    #pragma unroll
    for (int i = 0; i < 2; ++i)
        #pragma unroll
        for (int j = 0; j < 8; ++j)
            #pragma unroll
            for (int q = 0; q < 4; ++q) c[i][j][q] = 0.f;

    const int rr0 = tid >> 3;
    const int cc  = tid & 7;

    auto issue_stage = [&](int kt, int s) {
        #pragma unroll
        for (int i = 0; i < 4; ++i) {
            int r = rr0 + i * 32;
            uint32_t sw = (uint32_t)(r * 128 + ((cc ^ (r & 7)) << 4));
            uint32_t da = sbase + s * STAGE_B + sw;
            uint32_t db = da + AS_BYTES;
            const char* ga = (const char*)(A + (size_t)(m0 + r) * DIM + kt * 64 + cc * 8);
            const char* gb = (const char*)(B + (size_t)(n0 + r) * DIM + kt * 64 + cc * 8);
            CP_ASYNC16(da, ga);
            CP_ASYNC16(db, gb);
        }
        CP_COMMIT();
    };

    const int lrow8 = ((lane >> 3) & 1) * 8 + (lane & 7);
    const int lcol16 = (lane >> 4) * 16;

    issue_stage(0, 0);

    for (int kt = 0; kt < NKT; ++kt) {
        CP_WAIT(0);
        __syncthreads();
        if (kt + 1 < NKT) issue_stage(kt + 1, (kt + 1) & 1);

        const uint32_t ab = sbase + (kt & 1) * STAGE_B;
        const uint32_t bb = ab + AS_BYTES;

        #pragma unroll
        for (int ks = 0; ks < 4; ++ks) {
            const int kb = ks * 32;
            uint32_t af[2][4];
            #pragma unroll
            for (int i = 0; i < 2; ++i) {
                int row = warpM * 32 + i * 16 + lrow8;
                int col = kb + lcol16;
                uint32_t ad = ab + row * 128 + ((((col >> 4) ^ (row & 7)) & 7) << 4);
                LDSM_X4(af[i][0], af[i][1], af[i][2], af[i][3], ad);
            }
            uint32_t bf[4][4];
            #pragma unroll
            for (int jj = 0; jj < 4; ++jj) {
                int nrow = warpN * 64 + jj * 16 + lrow8;
                int col = kb + lcol16;
                uint32_t bd = bb + nrow * 128 + ((((col >> 4) ^ (nrow & 7)) & 7) << 4);
                LDSM_X4(bf[jj][0], bf[jj][1], bf[jj][2], bf[jj][3], bd);
            }
            #pragma unroll
            for (int i = 0; i < 2; ++i) {
                #pragma unroll
                for (int j = 0; j < 8; ++j) {
                    const int jj = j >> 1, sel = j & 1;
                    MMA16816(c[i][j], af[i], bf[jj][sel], bf[jj][sel + 2]);
                }
            }
        }
    }

    #pragma unroll
    for (int i = 0; i < 2; ++i) {
        #pragma unroll
        for (int j = 0; j < 8; ++j) {
            int row = m0 + warpM * 32 + i * 16 + (lane >> 2);
            int col = n0 + warpN * 64 + j * 8 + (lane & 3) * 2;
            float b0v = bias[col], b1v = bias[col + 1];
            float2 o0 = {c[i][j][0] + b0v, c[i][j][1] + b1v};
            float2 o1 = {c[i][j][2] + b0v, c[i][j][3] + b1v};
            *(float2*)&Cf[(size_t)row * DIM + col] = o0;
            *(float2*)&Cf[(size_t)(row + 8) * DIM + col] = o1;
        }
    }
}

// ---------------- fp16 tensor-core flash attention (fp16 output) ----------------
#define FS_STAGE 32768
#define FS_Q_OFF (2 * FS_STAGE)
#define FS_SMEM (FS_Q_OFF + 2 * 16384)

__global__ __launch_bounds__(256) void flash16_kernel(
    const __half* __restrict__ Qh, const __half* __restrict__ Ql,
    const __half* __restrict__ Kh, const __half* __restrict__ Kl,
    const __half* __restrict__ Vh, const __half* __restrict__ Vl,
    __half* __restrict__ Ao)
{
    extern __shared__ char sm[];
    const uint32_t sb = smem_u32(sm);
    const int tid  = threadIdx.x;
    const int lane = tid & 31;
    const int wid  = tid >> 5;
    const int qb   = blockIdx.x * 128;
    const int h    = blockIdx.y;
    const int b    = blockIdx.z;
    const size_t qrow0 = (size_t)b * SEQ + qb;
    const int colh = h * DH;

    const int lrow8  = ((lane >> 3) & 1) * 8 + (lane & 7);
    const int lcol16 = (lane >> 4) * 16;

    #pragma unroll
    for (int i = 0; i < 4; ++i) {
        int idx = tid + i * 256;
        int r = idx >> 3, c = idx & 7;
        uint32_t sw = (uint32_t)(r * 128 + ((c ^ (r & 7)) << 4));
        size_t goff = (qrow0 + r) * DIM + colh + c * 8;
        CP_ASYNC16(sb + FS_Q_OFF + sw,         (const char*)(Qh + goff));
        CP_ASYNC16(sb + FS_Q_OFF + 16384 + sw, (const char*)(Ql + goff));
    }
    CP_COMMIT();

    auto issue_kv = [&](int kt, int s) {
        const size_t rowbase = (size_t)b * SEQ + (size_t)kt * 64;
        const uint32_t st = sb + s * FS_STAGE;
        #pragma unroll
        for (int i = 0; i < 2; ++i) {
            int idx = tid + i * 256;
            int r = idx >> 3, c = idx & 7;
            uint32_t sw = (uint32_t)(r * 128 + ((c ^ (r & 7)) << 4));
            size_t goff = (rowbase + r) * DIM + colh + c * 8;
            CP_ASYNC16(st + sw,         (const char*)(Kh + goff));
            CP_ASYNC16(st + 8192 + sw,  (const char*)(Kl + goff));
            CP_ASYNC16(st + 16384 + sw, (const char*)(Vh + goff));
            CP_ASYNC16(st + 24576 + sw, (const char*)(Vl + goff));
        }
        CP_COMMIT();
    };

    issue_kv(0, 0);
    CP_WAIT(0);
    __syncthreads();

    uint32_t qhf[4][4], qlf[4][4];
    #pragma unroll
    for (int kc = 0; kc < 4; ++kc) {
        int row = wid * 16 + lrow8;
        int col = kc * 32 + lcol16;
        uint32_t ad = sb + FS_Q_OFF + row * 128 + ((((col >> 4) ^ (row & 7)) & 7) << 4);
        LDSM_X4(qhf[kc][0], qhf[kc][1], qhf[kc][2], qhf[kc][3], ad);
        LDSM_X4(qlf[kc][0], qlf[kc][1], qlf[kc][2], qlf[kc][3], ad + 16384);
    }

    float o[8][4];
    #pragma unroll
    for (int i = 0; i < 8; ++i)
        #pragma unroll
        for (int q = 0; q < 4; ++q) o[i][q] = 0.f;
    float m0 = -1e30f, m1 = -1e30f, l0 = 0.f, l1 = 0.f;

    for (int kt = 0; kt < SEQ / 64; ++kt) {
        if (kt) {
            CP_WAIT(0);
            __syncthreads();
        }
        if (kt + 1 < SEQ / 64) issue_kv(kt + 1, (kt + 1) & 1);

        const uint32_t kb = sb + (kt & 1) * FS_STAGE;
        const uint32_t vb = kb + 16384;

        float s[8][4];
        #pragma unroll
        for (int i = 0; i < 8; ++i)
            #pragma unroll
            for (int q = 0; q < 4; ++q) s[i][q] = 0.f;

        #pragma unroll
        for (int kc = 0; kc < 4; ++kc) {
            const int col = kc * 32 + lcol16;
            #pragma unroll
            for (int nb2 = 0; nb2 < 4; ++nb2) {
                int row = nb2 * 16 + lrow8;
                uint32_t ad = kb + row * 128 + ((((col >> 4) ^ (row & 7)) & 7) << 4);
                uint32_t f0, f1, f2, f3;
                LDSM_X4(f0, f1, f2, f3, ad);
                MMA16816(s[2 * nb2],     qhf[kc], f0, f2);
                MMA16816(s[2 * nb2 + 1], qhf[kc], f1, f3);
                MMA16816(s[2 * nb2],     qlf[kc], f0, f2);
                MMA16816(s[2 * nb2 + 1], qlf[kc], f1, f3);
                LDSM_X4(f0, f1, f2, f3, ad + 8192);
                MMA16816(s[2 * nb2],     qhf[kc], f0, f2);
                MMA16816(s[2 * nb2 + 1], qhf[kc], f1, f3);
            }
        }

        float mx0 = -1e30f, mx1 = -1e30f;
        #pragma unroll
        for (int nb = 0; nb < 8; ++nb) {
            mx0 = fmaxf(mx0, fmaxf(s[nb][0], s[nb][1]));
            mx1 = fmaxf(mx1, fmaxf(s[nb][2], s[nb][3]));
        }
        mx0 = fmaxf(mx0, __shfl_xor_sync(0xffffffffu, mx0, 1));
        mx0 = fmaxf(mx0, __shfl_xor_sync(0xffffffffu, mx0, 2));
        mx1 = fmaxf(mx1, __shfl_xor_sync(0xffffffffu, mx1, 1));
        mx1 = fmaxf(mx1, __shfl_xor_sync(0xffffffffu, mx1, 2));
        float mn0 = fmaxf(m0, mx0), mn1 = fmaxf(m1, mx1);
        float cr0 = ex2f(m0 - mn0), cr1 = ex2f(m1 - mn1);
        m0 = mn0; m1 = mn1;

        float ls0 = 0.f, ls1 = 0.f;
        uint32_t a[4][4];
        #pragma unroll
        for (int nb = 0; nb < 8; ++nb) {
            float p0 = ex2f(s[nb][0] - mn0);
            float p1 = ex2f(s[nb][1] - mn0);
            float p2 = ex2f(s[nb][2] - mn1);
            float p3 = ex2f(s[nb][3] - mn1);
            ls0 += p0 + p1;
            ls1 += p2 + p3;
            __half2 h01 = __floats2half2_rn(p0, p1);
            __half2 h23 = __floats2half2_rn(p2, p3);
            int kc = nb >> 1;
            if ((nb & 1) == 0) {
                a[kc][0] = *(uint32_t*)&h01;
                a[kc][1] = *(uint32_t*)&h23;
            } else {
                a[kc][2] = *(uint32_t*)&h01;
                a[kc][3] = *(uint32_t*)&h23;
            }
        }
        ls0 += __shfl_xor_sync(0xffffffffu, ls0, 1);
        ls0 += __shfl_xor_sync(0xffffffffu, ls0, 2);
        ls1 += __shfl_xor_sync(0xffffffffu, ls1, 1);
        ls1 += __shfl_xor_sync(0xffffffffu, ls1, 2);
        l0 = l0 * cr0 + ls0;
        l1 = l1 * cr1 + ls1;
        #pragma unroll
        for (int db = 0; db < 8; ++db) {
            o[db][0] *= cr0; o[db][1] *= cr0;
            o[db][2] *= cr1; o[db][3] *= cr1;
        }

        #pragma unroll
        for (int kc = 0; kc < 4; ++kc) {
            int row = kc * 16 + lrow8;
            #pragma unroll
            for (int db2 = 0; db2 < 4; ++db2) {
                int col = db2 * 32 + lcol16;
                uint32_t ad = vb + row * 128 + ((((col >> 4) ^ (row & 7)) & 7) << 4);
                uint32_t f0, f1, f2, f3;
                LDSM_X4_T(f0, f1, f2, f3, ad);
                MMA16816(o[2 * db2],     a[kc], f0, f1);
                MMA16816(o[2 * db2 + 1], a[kc], f2, f3);
                LDSM_X4_T(f0, f1, f2, f3, ad + 8192);
                MMA16816(o[2 * db2],     a[kc], f0, f1);
                MMA16816(o[2 * db2 + 1], a[kc], f2, f3);
            }
        }
    }

    float inv0 = 1.0f / l0, inv1 = 1.0f / l1;
    size_t r0 = qrow0 + wid * 16 + (lane >> 2);
    size_t r1 = r0 + 8;
    int cb = colh + (lane & 3) * 2;
    #pragma unroll
    for (int db = 0; db < 8; ++db) {
        __half2 w0 = __floats2half2_rn(o[db][0] * inv0, o[db][1] * inv0);
        __half2 w1 = __floats2half2_rn(o[db][2] * inv1, o[db][3] * inv1);
        *(__half2*)&Ao[r0 * DIM + cb + db * 8] = w0;
        *(__half2*)&Ao[r1 * DIM + cb + db * 8] = w1;
    }
}

// ---------------- launch ----------------
extern "C" void kernel_launch(void* const* d_in, const int* in_sizes, int n_in,
                              void* d_out, int out_size) {
    const float* x      = (const float*)d_in[0];
    const float* y      = (const float*)d_in[1];
    const int*   pos_q  = (const int*)d_in[2];
    const int*   pos_kv = (const int*)d_in[3];
    const float* Wq = (const float*)d_in[4];
    const float* bq = (const float*)d_in[5];
    const float* Wk = (const float*)d_in[6];
    const float* bk = (const float*)d_in[7];
    const float* Wv = (const float*)d_in[8];
    const float* bv = (const float*)d_in[9];
    const float* Wo = (const float*)d_in[10];
    const float* bo = (const float*)d_in[11];
    float* out = (float*)d_out;

    __half *Xh, *Yh, *WTq, *WTk, *WTv, *WTo;
    __half *Qhp, *Qlp, *Khp, *Klp, *Vhp, *Vlp, *Aohp;
    cudaGetSymbolAddress((void**)&Xh, g_Xh);
    cudaGetSymbolAddress((void**)&Yh, g_Yh);
    cudaGetSymbolAddress((void**)&WTq, g_WTq);
    cudaGetSymbolAddress((void**)&WTk, g_WTk);
    cudaGetSymbolAddress((void**)&WTv, g_WTv);
    cudaGetSymbolAddress((void**)&WTo, g_WTo);
    cudaGetSymbolAddress((void**)&Qhp, g_Qh);
    cudaGetSymbolAddress((void**)&Qlp, g_Ql);
    cudaGetSymbolAddress((void**)&Khp, g_Kh);
    cudaGetSymbolAddress((void**)&Klp, g_Kl);
    cudaGetSymbolAddress((void**)&Vhp, g_Vh);
    cudaGetSymbolAddress((void**)&Vlp, g_Vl);
    cudaGetSymbolAddress((void**)&Aohp, g_Aoh);

    cudaFuncSetAttribute(qkv_gemm_kernel, cudaFuncAttributeMaxDynamicSharedMemorySize, GEMM_SMEM);
    cudaFuncSetAttribute(out_gemm_kernel, cudaFuncAttributeMaxDynamicSharedMemorySize, GEMM_SMEM);
    cudaFuncSetAttribute(flash16_kernel, cudaFuncAttributeMaxDynamicSharedMemorySize, FS_SMEM);

    init_tables_kernel<<<1, 512>>>();

    const int n4 = (ROWS * DIM) / 4;
    f2h2_kernel<<<dim3((n4 + 255) / 256, 2), 256>>>(x, y, Xh, Yh, n4);

    transpose4_kernel<<<dim3(DIM / 32, DIM / 32, 4), dim3(32, 8)>>>(
        Wq, Wk, Wv, Wo, WTq, WTk, WTv, WTo);

    qkv_gemm_kernel<<<dim3(DIM / 128, ROWS / 128, 3), 256, GEMM_SMEM>>>(
        Xh, Yh, WTq, WTk, WTv, bq, bk, bv, pos_q, pos_kv,
        Qhp, Qlp, Khp, Klp, Vhp, Vlp);

    flash16_kernel<<<dim3(SEQ / 128, HEADS, BATCH), 256, FS_SMEM>>>(
        Qhp, Qlp, Khp, Klp, Vhp, Vlp, Aohp);

    out_gemm_kernel<<<dim3(DIM / 128, ROWS / 128), 256, GEMM_SMEM>>>(Aohp, WTo, bo, out);
}

// round 9
// speedup vs baseline: 6.1840x; 1.1022x over previous
#include <cuda_runtime.h>
#include <cuda_fp16.h>
#include <math.h>
#include <stdint.h>

#define HEADS 12
#define DH 64
#define DIM 768
#define BATCH 8
#define SEQ 1024
#define ROWS (BATCH * SEQ)   // 8192

#define QSCALE 0.1803368801111204f   // 0.125 * log2(e)

// ---------------- scratch ----------------
__device__ __half g_Xh[ROWS * DIM];
__device__ __half g_Yh[ROWS * DIM];
__device__ __half g_WTq[DIM * DIM];
__device__ __half g_WTk[DIM * DIM];
__device__ __half g_WTv[DIM * DIM];
__device__ __half g_WTo[DIM * DIM];
__device__ __half g_Qh[ROWS * DIM];
__device__ __half g_Ql[ROWS * DIM];
__device__ __half g_Kh[ROWS * DIM];
__device__ __half g_Kl[ROWS * DIM];
__device__ __half g_Vh[ROWS * DIM];
__device__ __half g_Aoh[ROWS * DIM];
__device__ float g_cosT[512];
__device__ float g_sinT[512];

// ---------------- helpers ----------------
__device__ __forceinline__ uint32_t smem_u32(const void* p) {
    uint32_t a;
    asm("{ .reg .u64 t; cvta.to.shared.u64 t, %1; cvt.u32.u64 %0, t; }" : "=r"(a) : "l"(p));
    return a;
}
__device__ __forceinline__ float ex2f(float x) {
    float y;
    asm("ex2.approx.ftz.f32 %0, %1;" : "=f"(y) : "f"(x));
    return y;
}
__device__ __forceinline__ void store_split2(__half* __restrict__ H, __half* __restrict__ L,
                                             size_t off, float x, float y) {
    __half hx = __float2half(x), hy = __float2half(y);
    __half lx = __float2half(x - __half2float(hx));
    __half ly = __float2half(y - __half2float(hy));
    *(__half2*)&H[off] = __halves2half2(hx, hy);
    *(__half2*)&L[off] = __halves2half2(lx, ly);
}

#define LDSM_X4(r0, r1, r2, r3, addr)                                          \
    asm volatile("ldmatrix.sync.aligned.m8n8.x4.shared.b16 {%0,%1,%2,%3}, [%4];" \
                 : "=r"(r0), "=r"(r1), "=r"(r2), "=r"(r3) : "r"(addr))

#define LDSM_X4_T(r0, r1, r2, r3, addr)                                        \
    asm volatile("ldmatrix.sync.aligned.m8n8.x4.trans.shared.b16 {%0,%1,%2,%3}, [%4];" \
                 : "=r"(r0), "=r"(r1), "=r"(r2), "=r"(r3) : "r"(addr))

#define MMA16816(c, a, b0, b1)                                                 \
    asm volatile("mma.sync.aligned.m16n8k16.row.col.f32.f16.f16.f32 "          \
                 "{%0,%1,%2,%3}, {%4,%5,%6,%7}, {%8,%9}, {%0,%1,%2,%3};"       \
                 : "+f"((c)[0]), "+f"((c)[1]), "+f"((c)[2]), "+f"((c)[3])      \
                 : "r"((a)[0]), "r"((a)[1]), "r"((a)[2]), "r"((a)[3]),         \
                   "r"(b0), "r"(b1))

#define CP_ASYNC16(dst, src)                                                   \
    asm volatile("cp.async.cg.shared.global [%0], [%1], 16;" :: "r"(dst), "l"(src))
#define CP_COMMIT() asm volatile("cp.async.commit_group;" ::: "memory")
#define CP_WAIT(n)  asm volatile("cp.async.wait_group %0;" :: "n"(n) : "memory")

// ---------------- float -> half (x and y in one launch) ----------------
__global__ void f2h2_kernel(const float* __restrict__ x, const float* __restrict__ y,
                            __half* __restrict__ Xh, __half* __restrict__ Yh, int n4) {
    int i = blockIdx.x * blockDim.x + threadIdx.x;
    if (i >= n4) return;
    const float* src = blockIdx.y ? y : x;
    __half* dst = blockIdx.y ? Yh : Xh;
    float4 v = ((const float4*)src)[i];
    __half2 lo = __floats2half2_rn(v.x, v.y);
    __half2 hi = __floats2half2_rn(v.z, v.w);
    uint2 o;
    o.x = *(uint32_t*)&lo;
    o.y = *(uint32_t*)&hi;
    ((uint2*)dst)[i] = o;
}

// ---------------- 4 weight transposes + RoPE table init in one launch ----------------
__global__ void transpose4_kernel(const float* __restrict__ Wq, const float* __restrict__ Wk,
                                  const float* __restrict__ Wv, const float* __restrict__ Wo,
                                  __half* __restrict__ Tq, __half* __restrict__ Tk,
                                  __half* __restrict__ Tv, __half* __restrict__ To) {
    const int z = blockIdx.z;
    // fold the tiny RoPE-table init into one block of this launch
    if (z == 0 && blockIdx.x == 0 && blockIdx.y == 0) {
        int t = threadIdx.y * 32 + threadIdx.x;   // 0..255
        #pragma unroll
        for (int rep = 0; rep < 2; ++rep) {
            int i = t + rep * 256;                // 0..511
            int p = i >> 4;
            int f = i & 15;
            double inv = pow(100.0, -((double)(2 * f)) / 32.0);
            double fr = (double)p * inv;
            g_cosT[i] = (float)cos(fr);
            g_sinT[i] = (float)sin(fr);
        }
    }
    const float* W = (z == 0) ? Wq : (z == 1) ? Wk : (z == 2) ? Wv : Wo;
    __half* T = (z == 0) ? Tq : (z == 1) ? Tk : (z == 2) ? Tv : To;
    __shared__ float tile[32][33];
    int bx = blockIdx.x * 32;
    int by = blockIdx.y * 32;
    int x = threadIdx.x, y = threadIdx.y;
    #pragma unroll
    for (int j = 0; j < 4; ++j)
        tile[y + 8 * j][x] = W[(by + y + 8 * j) * DIM + bx + x];
    __syncthreads();
    #pragma unroll
    for (int j = 0; j < 4; ++j)
        T[(size_t)(bx + y + 8 * j) * DIM + by + x] = __float2half(tile[x][y + 8 * j]);
}

// ---------------- GEMM tile constants ----------------
#define NKT (DIM / 64)
#define AS_BYTES (128 * 128)
#define STAGE_B (2 * AS_BYTES)
#define GEMM_SMEM (2 * STAGE_B)

// ---------------- fused Q/K/V projection GEMM (one launch, z picks mode) ----------------
// z=0: rope(C+bq)*QSCALE -> Qh/Ql   z=1: rope(C+bk) -> Kh/Kl   z=2: (C+bv) -> Vh (fp16)
__global__ __launch_bounds__(256, 2) void qkv_gemm_kernel(
    const __half* __restrict__ Xh, const __half* __restrict__ Yh,
    const __half* __restrict__ WTq, const __half* __restrict__ WTk, const __half* __restrict__ WTv,
    const float* __restrict__ bq, const float* __restrict__ bk, const float* __restrict__ bv,
    const int* __restrict__ pos_q, const int* __restrict__ pos_kv,
    __half* __restrict__ Qh, __half* __restrict__ Ql,
    __half* __restrict__ Kh, __half* __restrict__ Kl,
    __half* __restrict__ Vh)
{
    extern __shared__ char sm[];
    const uint32_t sbase = smem_u32(sm);
    const int z = blockIdx.z;
    const __half* A = (z == 0) ? Xh : Yh;
    const __half* B = (z == 0) ? WTq : (z == 1) ? WTk : WTv;
    const float* bias = (z == 0) ? bq : (z == 1) ? bk : bv;
    const int* pos = (z == 0) ? pos_q : pos_kv;
    __half* Ch = (z == 0) ? Qh : (z == 1) ? Kh : Vh;
    __half* Cl = (z == 0) ? Ql : Kl;

    const int tid  = threadIdx.x;
    const int lane = tid & 31;
    const int wid  = tid >> 5;
    const int warpM = wid & 3;
    const int warpN = wid >> 2;
    const int m0 = blockIdx.y * 128;
    const int n0 = blockIdx.x * 128;

    float c[2][8][4];
    #pragma unroll
    for (int i = 0; i < 2; ++i)
        #pragma unroll
        for (int j = 0; j < 8; ++j)
            #pragma unroll
            for (int q = 0; q < 4; ++q) c[i][j][q] = 0.f;

    const int rr0 = tid >> 3;
    const int cc  = tid & 7;

    auto issue_stage = [&](int kt, int s) {
        #pragma unroll
        for (int i = 0; i < 4; ++i) {
            int r = rr0 + i * 32;
            uint32_t sw = (uint32_t)(r * 128 + ((cc ^ (r & 7)) << 4));
            uint32_t da = sbase + s * STAGE_B + sw;
            uint32_t db = da + AS_BYTES;
            const char* ga = (const char*)(A + (size_t)(m0 + r) * DIM + kt * 64 + cc * 8);
            const char* gb = (const char*)(B + (size_t)(n0 + r) * DIM + kt * 64 + cc * 8);
            CP_ASYNC16(da, ga);
            CP_ASYNC16(db, gb);
        }
        CP_COMMIT();
    };

    const int lrow8 = ((lane >> 3) & 1) * 8 + (lane & 7);
    const int lcol16 = (lane >> 4) * 16;

    issue_stage(0, 0);

    for (int kt = 0; kt < NKT; ++kt) {
        CP_WAIT(0);
        __syncthreads();
        if (kt + 1 < NKT) issue_stage(kt + 1, (kt + 1) & 1);

        const uint32_t ab = sbase + (kt & 1) * STAGE_B;
        const uint32_t bb = ab + AS_BYTES;

        #pragma unroll
        for (int ks = 0; ks < 4; ++ks) {
            const int kb = ks * 32;
            uint32_t af[2][4];
            #pragma unroll
            for (int i = 0; i < 2; ++i) {
                int row = warpM * 32 + i * 16 + lrow8;
                int col = kb + lcol16;
                uint32_t ad = ab + row * 128 + ((((col >> 4) ^ (row & 7)) & 7) << 4);
                LDSM_X4(af[i][0], af[i][1], af[i][2], af[i][3], ad);
            }
            uint32_t bf[4][4];
            #pragma unroll
            for (int jj = 0; jj < 4; ++jj) {
                int nrow = warpN * 64 + jj * 16 + lrow8;
                int col = kb + lcol16;
                uint32_t bd = bb + nrow * 128 + ((((col >> 4) ^ (nrow & 7)) & 7) << 4);
                LDSM_X4(bf[jj][0], bf[jj][1], bf[jj][2], bf[jj][3], bd);
            }
            #pragma unroll
            for (int i = 0; i < 2; ++i) {
                #pragma unroll
                for (int j = 0; j < 8; ++j) {
                    const int jj = j >> 1, sel = j & 1;
                    MMA16816(c[i][j], af[i], bf[jj][sel], bf[jj][sel + 2]);
                }
            }
        }
    }

    // ---------------- fused epilogue ----------------
    if (z == 2) {
        #pragma unroll
        for (int i = 0; i < 2; ++i) {
            #pragma unroll
            for (int j = 0; j < 8; ++j) {
                int row = m0 + warpM * 32 + i * 16 + (lane >> 2);
                int col = n0 + warpN * 64 + j * 8 + (lane & 3) * 2;
                float b0v = bias[col], b1v = bias[col + 1];
                *(__half2*)&Ch[(size_t)row * DIM + col] =
                    __floats2half2_rn(c[i][j][0] + b0v, c[i][j][1] + b1v);
                *(__half2*)&Ch[(size_t)(row + 8) * DIM + col] =
                    __floats2half2_rn(c[i][j][2] + b0v, c[i][j][3] + b1v);
            }
        }
    } else {
        const float scale = (z == 0) ? QSCALE : 1.0f;
        #pragma unroll
        for (int i = 0; i < 2; ++i) {
            int rowA = m0 + warpM * 32 + i * 16 + (lane >> 2);
            int rowB = rowA + 8;
            int pA0 = pos[2 * rowA], pA1 = pos[2 * rowA + 1];
            int pB0 = pos[2 * rowB], pB1 = pos[2 * rowB + 1];
            #pragma unroll
            for (int jj = 0; jj < 4; ++jj) {
                const int j = (jj < 2) ? jj : jj + 2;   // 0,1,4,5
                const int half = (j >= 4);
                int col = n0 + warpN * 64 + j * 8 + (lane & 3) * 2;
                int f0 = (j & 1) * 8 + (lane & 3) * 2;
                int pA = half ? pA1 : pA0;
                int pB = half ? pB1 : pB0;
                float cA0 = g_cosT[pA * 16 + f0], cA1 = g_cosT[pA * 16 + f0 + 1];
                float sA0 = g_sinT[pA * 16 + f0], sA1 = g_sinT[pA * 16 + f0 + 1];
                float cB0 = g_cosT[pB * 16 + f0], cB1 = g_cosT[pB * 16 + f0 + 1];
                float sB0 = g_sinT[pB * 16 + f0], sB1 = g_sinT[pB * 16 + f0 + 1];
                float b1x = bias[col], b1y = bias[col + 1];
                float b2x = bias[col + 16], b2y = bias[col + 17];

                {
                    float v1x = c[i][j][0] + b1x,     v1y = c[i][j][1] + b1y;
                    float v2x = c[i][j + 2][0] + b2x, v2y = c[i][j + 2][1] + b2y;
                    float o1x = (v1x * cA0 - v2x * sA0) * scale;
                    float o1y = (v1y * cA1 - v2y * sA1) * scale;
                    float o2x = (v2x * cA0 + v1x * sA0) * scale;
                    float o2y = (v2y * cA1 + v1y * sA1) * scale;
                    store_split2(Ch, Cl, (size_t)rowA * DIM + col, o1x, o1y);
                    store_split2(Ch, Cl, (size_t)rowA * DIM + col + 16, o2x, o2y);
                }
                {
                    float v1x = c[i][j][2] + b1x,     v1y = c[i][j][3] + b1y;
                    float v2x = c[i][j + 2][2] + b2x, v2y = c[i][j + 2][3] + b2y;
                    float o1x = (v1x * cB0 - v2x * sB0) * scale;
                    float o1y = (v1y * cB1 - v2y * sB1) * scale;
                    float o2x = (v2x * cB0 + v1x * sB0) * scale;
                    float o2y = (v2y * cB1 + v1y * sB1) * scale;
                    store_split2(Ch, Cl, (size_t)rowB * DIM + col, o1x, o1y);
                    store_split2(Ch, Cl, (size_t)rowB * DIM + col + 16, o2x, o2y);
                }
            }
        }
    }
}

// ---------------- final output GEMM: out = Aoh @ WTo^T + bo (fp32) ----------------
__global__ __launch_bounds__(256, 2) void out_gemm_kernel(
    const __half* __restrict__ A, const __half* __restrict__ B,
    const float* __restrict__ bias, float* __restrict__ Cf)
{
    extern __shared__ char sm[];
    const uint32_t sbase = smem_u32(sm);
    const int tid  = threadIdx.x;
    const int lane = tid & 31;
    const int wid  = tid >> 5;
    const int warpM = wid & 3;
    const int warpN = wid >> 2;
    const int m0 = blockIdx.y * 128;
    const int n0 = blockIdx.x * 128;

    float c[2][8][4];
    #pragma unroll
    for (int i = 0; i < 2; ++i)
        #pragma unroll
        for (int j = 0; j < 8; ++j)
            #pragma unroll
            for (int q = 0; q < 4; ++q) c[i][j][q] = 0.f;

    const int rr0 = tid >> 3;
    const int cc  = tid & 7;

    auto issue_stage = [&](int kt, int s) {
        #pragma unroll
        for (int i = 0; i < 4; ++i) {
            int r = rr0 + i * 32;
            uint32_t sw = (uint32_t)(r * 128 + ((cc ^ (r & 7)) << 4));
            uint32_t da = sbase + s * STAGE_B + sw;
            uint32_t db = da + AS_BYTES;
            const char* ga = (const char*)(A + (size_t)(m0 + r) * DIM + kt * 64 + cc * 8);
            const char* gb = (const char*)(B + (size_t)(n0 + r) * DIM + kt * 64 + cc * 8);
            CP_ASYNC16(da, ga);
            CP_ASYNC16(db, gb);
        }
        CP_COMMIT();
    };

    const int lrow8 = ((lane >> 3) & 1) * 8 + (lane & 7);
    const int lcol16 = (lane >> 4) * 16;

    issue_stage(0, 0);

    for (int kt = 0; kt < NKT; ++kt) {
        CP_WAIT(0);
        __syncthreads();
        if (kt + 1 < NKT) issue_stage(kt + 1, (kt + 1) & 1);

        const uint32_t ab = sbase + (kt & 1) * STAGE_B;
        const uint32_t bb = ab + AS_BYTES;

        #pragma unroll
        for (int ks = 0; ks < 4; ++ks) {
            const int kb = ks * 32;
            uint32_t af[2][4];
            #pragma unroll
            for (int i = 0; i < 2; ++i) {
                int row = warpM * 32 + i * 16 + lrow8;
                int col = kb + lcol16;
                uint32_t ad = ab + row * 128 + ((((col >> 4) ^ (row & 7)) & 7) << 4);
                LDSM_X4(af[i][0], af[i][1], af[i][2], af[i][3], ad);
            }
            uint32_t bf[4][4];
            #pragma unroll
            for (int jj = 0; jj < 4; ++jj) {
                int nrow = warpN * 64 + jj * 16 + lrow8;
                int col = kb + lcol16;
                uint32_t bd = bb + nrow * 128 + ((((col >> 4) ^ (nrow & 7)) & 7) << 4);
                LDSM_X4(bf[jj][0], bf[jj][1], bf[jj][2], bf[jj][3], bd);
            }
            #pragma unroll
            for (int i = 0; i < 2; ++i) {
                #pragma unroll
                for (int j = 0; j < 8; ++j) {
                    const int jj = j >> 1, sel = j & 1;
                    MMA16816(c[i][j], af[i], bf[jj][sel], bf[jj][sel + 2]);
                }
            }
        }
    }

    #pragma unroll
    for (int i = 0; i < 2; ++i) {
        #pragma unroll
        for (int j = 0; j < 8; ++j) {
            int row = m0 + warpM * 32 + i * 16 + (lane >> 2);
            int col = n0 + warpN * 64 + j * 8 + (lane & 3) * 2;
            float b0v = bias[col], b1v = bias[col + 1];
            float2 o0 = {c[i][j][0] + b0v, c[i][j][1] + b1v};
            float2 o1 = {c[i][j][2] + b0v, c[i][j][3] + b1v};
            *(float2*)&Cf[(size_t)row * DIM + col] = o0;
            *(float2*)&Cf[(size_t)(row + 8) * DIM + col] = o1;
        }
    }
}

// ---------------- fp16 tensor-core flash attention ----------------
// stage: Kh (8K) + Kl (8K) + V (8K) = 24 KB; Q hi/lo tiles 16 KB each.
#define FS_STAGE 24576
#define FS_Q_OFF (2 * FS_STAGE)                 // 49152
#define FS_SMEM (FS_Q_OFF + 2 * 16384)          // 81920

__global__ __launch_bounds__(256) void flash16_kernel(
    const __half* __restrict__ Qh, const __half* __restrict__ Ql,
    const __half* __restrict__ Kh, const __half* __restrict__ Kl,
    const __half* __restrict__ Vh,
    __half* __restrict__ Ao)
{
    extern __shared__ char sm[];
    const uint32_t sb = smem_u32(sm);
    const int tid  = threadIdx.x;
    const int lane = tid & 31;
    const int wid  = tid >> 5;
    const int qb   = blockIdx.x * 128;
    const int h    = blockIdx.y;
    const int b    = blockIdx.z;
    const size_t qrow0 = (size_t)b * SEQ + qb;
    const int colh = h * DH;

    const int lrow8  = ((lane >> 3) & 1) * 8 + (lane & 7);
    const int lcol16 = (lane >> 4) * 16;

    #pragma unroll
    for (int i = 0; i < 4; ++i) {
        int idx = tid + i * 256;
        int r = idx >> 3, c = idx & 7;
        uint32_t sw = (uint32_t)(r * 128 + ((c ^ (r & 7)) << 4));
        size_t goff = (qrow0 + r) * DIM + colh + c * 8;
        CP_ASYNC16(sb + FS_Q_OFF + sw,         (const char*)(Qh + goff));
        CP_ASYNC16(sb + FS_Q_OFF + 16384 + sw, (const char*)(Ql + goff));
    }
    CP_COMMIT();

    auto issue_kv = [&](int kt, int s) {
        const size_t rowbase = (size_t)b * SEQ + (size_t)kt * 64;
        const uint32_t st = sb + s * FS_STAGE;
        #pragma unroll
        for (int i = 0; i < 2; ++i) {
            int idx = tid + i * 256;
            int r = idx >> 3, c = idx & 7;
            uint32_t sw = (uint32_t)(r * 128 + ((c ^ (r & 7)) << 4));
            size_t goff = (rowbase + r) * DIM + colh + c * 8;
            CP_ASYNC16(st + sw,         (const char*)(Kh + goff));
            CP_ASYNC16(st + 8192 + sw,  (const char*)(Kl + goff));
            CP_ASYNC16(st + 16384 + sw, (const char*)(Vh + goff));
        }
        CP_COMMIT();
    };

    issue_kv(0, 0);
    CP_WAIT(0);
    __syncthreads();

    uint32_t qhf[4][4], qlf[4][4];
    #pragma unroll
    for (int kc = 0; kc < 4; ++kc) {
        int row = wid * 16 + lrow8;
        int col = kc * 32 + lcol16;
        uint32_t ad = sb + FS_Q_OFF + row * 128 + ((((col >> 4) ^ (row & 7)) & 7) << 4);
        LDSM_X4(qhf[kc][0], qhf[kc][1], qhf[kc][2], qhf[kc][3], ad);
        LDSM_X4(qlf[kc][0], qlf[kc][1], qlf[kc][2], qlf[kc][3], ad + 16384);
    }

    float o[8][4];
    #pragma unroll
    for (int i = 0; i < 8; ++i)
        #pragma unroll
        for (int q = 0; q < 4; ++q) o[i][q] = 0.f;
    float m0 = -1e30f, m1 = -1e30f, l0 = 0.f, l1 = 0.f;

    for (int kt = 0; kt < SEQ / 64; ++kt) {
        if (kt) {
            CP_WAIT(0);
            __syncthreads();
        }
        if (kt + 1 < SEQ / 64) issue_kv(kt + 1, (kt + 1) & 1);

        const uint32_t kb = sb + (kt & 1) * FS_STAGE;
        const uint32_t vb = kb + 16384;

        float s[8][4];
        #pragma unroll
        for (int i = 0; i < 8; ++i)
            #pragma unroll
            for (int q = 0; q < 4; ++q) s[i][q] = 0.f;

        // S = Q K^T : 3-pass (Qh*Kh + Ql*Kh + Qh*Kl)
        #pragma unroll
        for (int kc = 0; kc < 4; ++kc) {
            const int col = kc * 32 + lcol16;
            #pragma unroll
            for (int nb2 = 0; nb2 < 4; ++nb2) {
                int row = nb2 * 16 + lrow8;
                uint32_t ad = kb + row * 128 + ((((col >> 4) ^ (row & 7)) & 7) << 4);
                uint32_t f0, f1, f2, f3;
                LDSM_X4(f0, f1, f2, f3, ad);
                MMA16816(s[2 * nb2],     qhf[kc], f0, f2);
                MMA16816(s[2 * nb2 + 1], qhf[kc], f1, f3);
                MMA16816(s[2 * nb2],     qlf[kc], f0, f2);
                MMA16816(s[2 * nb2 + 1], qlf[kc], f1, f3);
                LDSM_X4(f0, f1, f2, f3, ad + 8192);
                MMA16816(s[2 * nb2],     qhf[kc], f0, f2);
                MMA16816(s[2 * nb2 + 1], qhf[kc], f1, f3);
            }
        }

        float mx0 = -1e30f, mx1 = -1e30f;
        #pragma unroll
        for (int nb = 0; nb < 8; ++nb) {
            mx0 = fmaxf(mx0, fmaxf(s[nb][0], s[nb][1]));
            mx1 = fmaxf(mx1, fmaxf(s[nb][2], s[nb][3]));
        }
        mx0 = fmaxf(mx0, __shfl_xor_sync(0xffffffffu, mx0, 1));
        mx0 = fmaxf(mx0, __shfl_xor_sync(0xffffffffu, mx0, 2));
        mx1 = fmaxf(mx1, __shfl_xor_sync(0xffffffffu, mx1, 1));
        mx1 = fmaxf(mx1, __shfl_xor_sync(0xffffffffu, mx1, 2));
        float mn0 = fmaxf(m0, mx0), mn1 = fmaxf(m1, mx1);
        float cr0 = ex2f(m0 - mn0), cr1 = ex2f(m1 - mn1);
        m0 = mn0; m1 = mn1;

        float ls0 = 0.f, ls1 = 0.f;
        uint32_t a[4][4];
        #pragma unroll
        for (int nb = 0; nb < 8; ++nb) {
            float p0 = ex2f(s[nb][0] - mn0);
            float p1 = ex2f(s[nb][1] - mn0);
            float p2 = ex2f(s[nb][2] - mn1);
            float p3 = ex2f(s[nb][3] - mn1);
            ls0 += p0 + p1;
            ls1 += p2 + p3;
            __half2 h01 = __floats2half2_rn(p0, p1);
            __half2 h23 = __floats2half2_rn(p2, p3);
            int kc = nb >> 1;
            if ((nb & 1) == 0) {
                a[kc][0] = *(uint32_t*)&h01;
                a[kc][1] = *(uint32_t*)&h23;
            } else {
                a[kc][2] = *(uint32_t*)&h01;
                a[kc][3] = *(uint32_t*)&h23;
            }
        }
        ls0 += __shfl_xor_sync(0xffffffffu, ls0, 1);
        ls0 += __shfl_xor_sync(0xffffffffu, ls0, 2);
        ls1 += __shfl_xor_sync(0xffffffffu, ls1, 1);
        ls1 += __shfl_xor_sync(0xffffffffu, ls1, 2);
        l0 = l0 * cr0 + ls0;
        l1 = l1 * cr1 + ls1;
        #pragma unroll
        for (int db = 0; db < 8; ++db) {
            o[db][0] *= cr0; o[db][1] *= cr0;
            o[db][2] *= cr1; o[db][3] *= cr1;
        }

        // O += P V (single pass, fp16 V)
        #pragma unroll
        for (int kc = 0; kc < 4; ++kc) {
            int row = kc * 16 + lrow8;
            #pragma unroll
            for (int db2 = 0; db2 < 4; ++db2) {
                int col = db2 * 32 + lcol16;
                uint32_t ad = vb + row * 128 + ((((col >> 4) ^ (row & 7)) & 7) << 4);
                uint32_t f0, f1, f2, f3;
                LDSM_X4_T(f0, f1, f2, f3, ad);
                MMA16816(o[2 * db2],     a[kc], f0, f1);
                MMA16816(o[2 * db2 + 1], a[kc], f2, f3);
            }
        }
    }

    float inv0 = 1.0f / l0, inv1 = 1.0f / l1;
    size_t r0 = qrow0 + wid * 16 + (lane >> 2);
    size_t r1 = r0 + 8;
    int cb = colh + (lane & 3) * 2;
    #pragma unroll
    for (int db = 0; db < 8; ++db) {
        __half2 w0 = __floats2half2_rn(o[db][0] * inv0, o[db][1] * inv0);
        __half2 w1 = __floats2half2_rn(o[db][2] * inv1, o[db][3] * inv1);
        *(__half2*)&Ao[r0 * DIM + cb + db * 8] = w0;
        *(__half2*)&Ao[r1 * DIM + cb + db * 8] = w1;
    }
}

// ---------------- launch ----------------
extern "C" void kernel_launch(void* const* d_in, const int* in_sizes, int n_in,
                              void* d_out, int out_size) {
    const float* x      = (const float*)d_in[0];
    const float* y      = (const float*)d_in[1];
    const int*   pos_q  = (const int*)d_in[2];
    const int*   pos_kv = (const int*)d_in[3];
    const float* Wq = (const float*)d_in[4];
    const float* bq = (const float*)d_in[5];
    const float* Wk = (const float*)d_in[6];
    const float* bk = (const float*)d_in[7];
    const float* Wv = (const float*)d_in[8];
    const float* bv = (const float*)d_in[9];
    const float* Wo = (const float*)d_in[10];
    const float* bo = (const float*)d_in[11];
    float* out = (float*)d_out;

    __half *Xh, *Yh, *WTq, *WTk, *WTv, *WTo;
    __half *Qhp, *Qlp, *Khp, *Klp, *Vhp, *Aohp;
    cudaGetSymbolAddress((void**)&Xh, g_Xh);
    cudaGetSymbolAddress((void**)&Yh, g_Yh);
    cudaGetSymbolAddress((void**)&WTq, g_WTq);
    cudaGetSymbolAddress((void**)&WTk, g_WTk);
    cudaGetSymbolAddress((void**)&WTv, g_WTv);
    cudaGetSymbolAddress((void**)&WTo, g_WTo);
    cudaGetSymbolAddress((void**)&Qhp, g_Qh);
    cudaGetSymbolAddress((void**)&Qlp, g_Ql);
    cudaGetSymbolAddress((void**)&Khp, g_Kh);
    cudaGetSymbolAddress((void**)&Klp, g_Kl);
    cudaGetSymbolAddress((void**)&Vhp, g_Vh);
    cudaGetSymbolAddress((void**)&Aohp, g_Aoh);

    cudaFuncSetAttribute(qkv_gemm_kernel, cudaFuncAttributeMaxDynamicSharedMemorySize, GEMM_SMEM);
    cudaFuncSetAttribute(out_gemm_kernel, cudaFuncAttributeMaxDynamicSharedMemorySize, GEMM_SMEM);
    cudaFuncSetAttribute(flash16_kernel, cudaFuncAttributeMaxDynamicSharedMemorySize, FS_SMEM);

    const int n4 = (ROWS * DIM) / 4;
    f2h2_kernel<<<dim3((n4 + 255) / 256, 2), 256>>>(x, y, Xh, Yh, n4);

    transpose4_kernel<<<dim3(DIM / 32, DIM / 32, 4), dim3(32, 8)>>>(
        Wq, Wk, Wv, Wo, WTq, WTk, WTv, WTo);

    qkv_gemm_kernel<<<dim3(DIM / 128, ROWS / 128, 3), 256, GEMM_SMEM>>>(
        Xh, Yh, WTq, WTk, WTv, bq, bk, bv, pos_q, pos_kv,
        Qhp, Qlp, Khp, Klp, Vhp);

    flash16_kernel<<<dim3(SEQ / 128, HEADS, BATCH), 256, FS_SMEM>>>(
        Qhp, Qlp, Khp, Klp, Vhp, Aohp);

    out_gemm_kernel<<<dim3(DIM / 128, ROWS / 128), 256, GEMM_SMEM>>>(Aohp, WTo, bo, out);
}

// round 10
// speedup vs baseline: 7.0154x; 1.1344x over previous
#include <cuda_runtime.h>
#include <cuda_fp16.h>
#include <math.h>
#include <stdint.h>

#define HEADS 12
#define DH 64
#define DIM 768
#define BATCH 8
#define SEQ 1024
#define ROWS (BATCH * SEQ)   // 8192

#define QSCALE 0.1803368801111204f   // 0.125 * log2(e)

// ---------------- scratch ----------------
__device__ __half g_Xh[ROWS * DIM];
__device__ __half g_Yh[ROWS * DIM];
__device__ __half g_WTq[DIM * DIM];
__device__ __half g_WTk[DIM * DIM];
__device__ __half g_WTv[DIM * DIM];
__device__ __half g_WTo[DIM * DIM];
__device__ __half g_Qh[ROWS * DIM];
__device__ __half g_Ql[ROWS * DIM];
__device__ __half g_Kh[ROWS * DIM];
__device__ __half g_Vh[ROWS * DIM];
__device__ __half g_Aoh[ROWS * DIM];
__device__ float g_cosT[512];
__device__ float g_sinT[512];

// ---------------- helpers ----------------
__device__ __forceinline__ uint32_t smem_u32(const void* p) {
    uint32_t a;
    asm("{ .reg .u64 t; cvta.to.shared.u64 t, %1; cvt.u32.u64 %0, t; }" : "=r"(a) : "l"(p));
    return a;
}
__device__ __forceinline__ float ex2f(float x) {
    float y;
    asm("ex2.approx.ftz.f32 %0, %1;" : "=f"(y) : "f"(x));
    return y;
}
__device__ __forceinline__ void store_split2(__half* __restrict__ H, __half* __restrict__ L,
                                             size_t off, float x, float y) {
    __half hx = __float2half(x), hy = __float2half(y);
    __half lx = __float2half(x - __half2float(hx));
    __half ly = __float2half(y - __half2float(hy));
    *(__half2*)&H[off] = __halves2half2(hx, hy);
    *(__half2*)&L[off] = __halves2half2(lx, ly);
}

#define LDSM_X4(r0, r1, r2, r3, addr)                                          \
    asm volatile("ldmatrix.sync.aligned.m8n8.x4.shared.b16 {%0,%1,%2,%3}, [%4];" \
                 : "=r"(r0), "=r"(r1), "=r"(r2), "=r"(r3) : "r"(addr))

#define LDSM_X4_T(r0, r1, r2, r3, addr)                                        \
    asm volatile("ldmatrix.sync.aligned.m8n8.x4.trans.shared.b16 {%0,%1,%2,%3}, [%4];" \
                 : "=r"(r0), "=r"(r1), "=r"(r2), "=r"(r3) : "r"(addr))

#define MMA16816(c, a, b0, b1)                                                 \
    asm volatile("mma.sync.aligned.m16n8k16.row.col.f32.f16.f16.f32 "          \
                 "{%0,%1,%2,%3}, {%4,%5,%6,%7}, {%8,%9}, {%0,%1,%2,%3};"       \
                 : "+f"((c)[0]), "+f"((c)[1]), "+f"((c)[2]), "+f"((c)[3])      \
                 : "r"((a)[0]), "r"((a)[1]), "r"((a)[2]), "r"((a)[3]),         \
                   "r"(b0), "r"(b1))

#define CP_ASYNC16(dst, src)                                                   \
    asm volatile("cp.async.cg.shared.global [%0], [%1], 16;" :: "r"(dst), "l"(src))
#define CP_COMMIT() asm volatile("cp.async.commit_group;" ::: "memory")
#define CP_WAIT(n)  asm volatile("cp.async.wait_group %0;" :: "n"(n) : "memory")

// ---------------- float -> half (x and y in one launch) ----------------
__global__ void f2h2_kernel(const float* __restrict__ x, const float* __restrict__ y,
                            __half* __restrict__ Xh, __half* __restrict__ Yh, int n4) {
    int i = blockIdx.x * blockDim.x + threadIdx.x;
    if (i >= n4) return;
    const float* src = blockIdx.y ? y : x;
    __half* dst = blockIdx.y ? Yh : Xh;
    float4 v = ((const float4*)src)[i];
    __half2 lo = __floats2half2_rn(v.x, v.y);
    __half2 hi = __floats2half2_rn(v.z, v.w);
    uint2 o;
    o.x = *(uint32_t*)&lo;
    o.y = *(uint32_t*)&hi;
    ((uint2*)dst)[i] = o;
}

// ---------------- 4 weight transposes + RoPE table init in one launch ----------------
__global__ void transpose4_kernel(const float* __restrict__ Wq, const float* __restrict__ Wk,
                                  const float* __restrict__ Wv, const float* __restrict__ Wo,
                                  __half* __restrict__ Tq, __half* __restrict__ Tk,
                                  __half* __restrict__ Tv, __half* __restrict__ To) {
    const int z = blockIdx.z;
    if (z == 0 && blockIdx.x == 0 && blockIdx.y == 0) {
        int t = threadIdx.y * 32 + threadIdx.x;
        #pragma unroll
        for (int rep = 0; rep < 2; ++rep) {
            int i = t + rep * 256;
            int p = i >> 4;
            int f = i & 15;
            double inv = pow(100.0, -((double)(2 * f)) / 32.0);
            double fr = (double)p * inv;
            g_cosT[i] = (float)cos(fr);
            g_sinT[i] = (float)sin(fr);
        }
    }
    const float* W = (z == 0) ? Wq : (z == 1) ? Wk : (z == 2) ? Wv : Wo;
    __half* T = (z == 0) ? Tq : (z == 1) ? Tk : (z == 2) ? Tv : To;
    __shared__ float tile[32][33];
    int bx = blockIdx.x * 32;
    int by = blockIdx.y * 32;
    int x = threadIdx.x, y = threadIdx.y;
    #pragma unroll
    for (int j = 0; j < 4; ++j)
        tile[y + 8 * j][x] = W[(by + y + 8 * j) * DIM + bx + x];
    __syncthreads();
    #pragma unroll
    for (int j = 0; j < 4; ++j)
        T[(size_t)(bx + y + 8 * j) * DIM + by + x] = __float2half(tile[x][y + 8 * j]);
}

// ---------------- GEMM tile constants ----------------
#define NKT (DIM / 64)
#define AS_BYTES (128 * 128)
#define STAGE_B (2 * AS_BYTES)
#define GEMM_SMEM (2 * STAGE_B)

// ---------------- fused Q/K/V projection GEMM (one launch, z picks mode) ----------------
// z=0: rope(C+bq)*QSCALE -> Qh/Ql (split)  z=1: rope(C+bk) -> Kh (fp16)  z=2: (C+bv) -> Vh
__global__ __launch_bounds__(256, 2) void qkv_gemm_kernel(
    const __half* __restrict__ Xh, const __half* __restrict__ Yh,
    const __half* __restrict__ WTq, const __half* __restrict__ WTk, const __half* __restrict__ WTv,
    const float* __restrict__ bq, const float* __restrict__ bk, const float* __restrict__ bv,
    const int* __restrict__ pos_q, const int* __restrict__ pos_kv,
    __half* __restrict__ Qh, __half* __restrict__ Ql,
    __half* __restrict__ Kh, __half* __restrict__ Vh)
{
    extern __shared__ char sm[];
    const uint32_t sbase = smem_u32(sm);
    const int z = blockIdx.z;
    const __half* A = (z == 0) ? Xh : Yh;
    const __half* B = (z == 0) ? WTq : (z == 1) ? WTk : WTv;
    const float* bias = (z == 0) ? bq : (z == 1) ? bk : bv;
    const int* pos = (z == 0) ? pos_q : pos_kv;
    __half* Ch = (z == 0) ? Qh : (z == 1) ? Kh : Vh;

    const int tid  = threadIdx.x;
    const int lane = tid & 31;
    const int wid  = tid >> 5;
    const int warpM = wid & 3;
    const int warpN = wid >> 2;
    const int m0 = blockIdx.y * 128;
    const int n0 = blockIdx.x * 128;

    float c[2][8][4];
    #pragma unroll
    for (int i = 0; i < 2; ++i)
        #pragma unroll
        for (int j = 0; j < 8; ++j)
            #pragma unroll
            for (int q = 0; q < 4; ++q) c[i][j][q] = 0.f;

    const int rr0 = tid >> 3;
    const int cc  = tid & 7;

    auto issue_stage = [&](int kt, int s) {
        #pragma unroll
        for (int i = 0; i < 4; ++i) {
            int r = rr0 + i * 32;
            uint32_t sw = (uint32_t)(r * 128 + ((cc ^ (r & 7)) << 4));
            uint32_t da = sbase + s * STAGE_B + sw;
            uint32_t db = da + AS_BYTES;
            const char* ga = (const char*)(A + (size_t)(m0 + r) * DIM + kt * 64 + cc * 8);
            const char* gb = (const char*)(B + (size_t)(n0 + r) * DIM + kt * 64 + cc * 8);
            CP_ASYNC16(da, ga);
            CP_ASYNC16(db, gb);
        }
        CP_COMMIT();
    };

    const int lrow8 = ((lane >> 3) & 1) * 8 + (lane & 7);
    const int lcol16 = (lane >> 4) * 16;

    issue_stage(0, 0);

    for (int kt = 0; kt < NKT; ++kt) {
        CP_WAIT(0);
        __syncthreads();
        if (kt + 1 < NKT) issue_stage(kt + 1, (kt + 1) & 1);

        const uint32_t ab = sbase + (kt & 1) * STAGE_B;
        const uint32_t bb = ab + AS_BYTES;

        #pragma unroll
        for (int ks = 0; ks < 4; ++ks) {
            const int kb = ks * 32;
            uint32_t af[2][4];
            #pragma unroll
            for (int i = 0; i < 2; ++i) {
                int row = warpM * 32 + i * 16 + lrow8;
                int col = kb + lcol16;
                uint32_t ad = ab + row * 128 + ((((col >> 4) ^ (row & 7)) & 7) << 4);
                LDSM_X4(af[i][0], af[i][1], af[i][2], af[i][3], ad);
            }
            uint32_t bf[4][4];
            #pragma unroll
            for (int jj = 0; jj < 4; ++jj) {
                int nrow = warpN * 64 + jj * 16 + lrow8;
                int col = kb + lcol16;
                uint32_t bd = bb + nrow * 128 + ((((col >> 4) ^ (nrow & 7)) & 7) << 4);
                LDSM_X4(bf[jj][0], bf[jj][1], bf[jj][2], bf[jj][3], bd);
            }
            #pragma unroll
            for (int i = 0; i < 2; ++i) {
                #pragma unroll
                for (int j = 0; j < 8; ++j) {
                    const int jj = j >> 1, sel = j & 1;
                    MMA16816(c[i][j], af[i], bf[jj][sel], bf[jj][sel + 2]);
                }
            }
        }
    }

    // ---------------- fused epilogue ----------------
    if (z == 2) {
        #pragma unroll
        for (int i = 0; i < 2; ++i) {
            #pragma unroll
            for (int j = 0; j < 8; ++j) {
                int row = m0 + warpM * 32 + i * 16 + (lane >> 2);
                int col = n0 + warpN * 64 + j * 8 + (lane & 3) * 2;
                float b0v = bias[col], b1v = bias[col + 1];
                *(__half2*)&Ch[(size_t)row * DIM + col] =
                    __floats2half2_rn(c[i][j][0] + b0v, c[i][j][1] + b1v);
                *(__half2*)&Ch[(size_t)(row + 8) * DIM + col] =
                    __floats2half2_rn(c[i][j][2] + b0v, c[i][j][3] + b1v);
            }
        }
    } else {
        const float scale = (z == 0) ? QSCALE : 1.0f;
        #pragma unroll
        for (int i = 0; i < 2; ++i) {
            int rowA = m0 + warpM * 32 + i * 16 + (lane >> 2);
            int rowB = rowA + 8;
            int pA0 = pos[2 * rowA], pA1 = pos[2 * rowA + 1];
            int pB0 = pos[2 * rowB], pB1 = pos[2 * rowB + 1];
            #pragma unroll
            for (int jj = 0; jj < 4; ++jj) {
                const int j = (jj < 2) ? jj : jj + 2;   // 0,1,4,5
                const int half = (j >= 4);
                int col = n0 + warpN * 64 + j * 8 + (lane & 3) * 2;
                int f0 = (j & 1) * 8 + (lane & 3) * 2;
                int pA = half ? pA1 : pA0;
                int pB = half ? pB1 : pB0;
                float cA0 = g_cosT[pA * 16 + f0], cA1 = g_cosT[pA * 16 + f0 + 1];
                float sA0 = g_sinT[pA * 16 + f0], sA1 = g_sinT[pA * 16 + f0 + 1];
                float cB0 = g_cosT[pB * 16 + f0], cB1 = g_cosT[pB * 16 + f0 + 1];
                float sB0 = g_sinT[pB * 16 + f0], sB1 = g_sinT[pB * 16 + f0 + 1];
                float b1x = bias[col], b1y = bias[col + 1];
                float b2x = bias[col + 16], b2y = bias[col + 17];

                {
                    float v1x = c[i][j][0] + b1x,     v1y = c[i][j][1] + b1y;
                    float v2x = c[i][j + 2][0] + b2x, v2y = c[i][j + 2][1] + b2y;
                    float o1x = (v1x * cA0 - v2x * sA0) * scale;
                    float o1y = (v1y * cA1 - v2y * sA1) * scale;
                    float o2x = (v2x * cA0 + v1x * sA0) * scale;
                    float o2y = (v2y * cA1 + v1y * sA1) * scale;
                    if (z == 0) {
                        store_split2(Ch, Ql, (size_t)rowA * DIM + col, o1x, o1y);
                        store_split2(Ch, Ql, (size_t)rowA * DIM + col + 16, o2x, o2y);
                    } else {
                        *(__half2*)&Ch[(size_t)rowA * DIM + col] = __floats2half2_rn(o1x, o1y);
                        *(__half2*)&Ch[(size_t)rowA * DIM + col + 16] = __floats2half2_rn(o2x, o2y);
                    }
                }
                {
                    float v1x = c[i][j][2] + b1x,     v1y = c[i][j][3] + b1y;
                    float v2x = c[i][j + 2][2] + b2x, v2y = c[i][j + 2][3] + b2y;
                    float o1x = (v1x * cB0 - v2x * sB0) * scale;
                    float o1y = (v1y * cB1 - v2y * sB1) * scale;
                    float o2x = (v2x * cB0 + v1x * sB0) * scale;
                    float o2y = (v2y * cB1 + v1y * sB1) * scale;
                    if (z == 0) {
                        store_split2(Ch, Ql, (size_t)rowB * DIM + col, o1x, o1y);
                        store_split2(Ch, Ql, (size_t)rowB * DIM + col + 16, o2x, o2y);
                    } else {
                        *(__half2*)&Ch[(size_t)rowB * DIM + col] = __floats2half2_rn(o1x, o1y);
                        *(__half2*)&Ch[(size_t)rowB * DIM + col + 16] = __floats2half2_rn(o2x, o2y);
                    }
                }
            }
        }
    }
}

// ---------------- final output GEMM: out = Aoh @ WTo^T + bo (fp32) ----------------
__global__ __launch_bounds__(256, 2) void out_gemm_kernel(
    const __half* __restrict__ A, const __half* __restrict__ B,
    const float* __restrict__ bias, float* __restrict__ Cf)
{
    extern __shared__ char sm[];
    const uint32_t sbase = smem_u32(sm);
    const int tid  = threadIdx.x;
    const int lane = tid & 31;
    const int wid  = tid >> 5;
    const int warpM = wid & 3;
    const int warpN = wid >> 2;
    const int m0 = blockIdx.y * 128;
    const int n0 = blockIdx.x * 128;

    float c[2][8][4];
    #pragma unroll
    for (int i = 0; i < 2; ++i)
        #pragma unroll
        for (int j = 0; j < 8; ++j)
            #pragma unroll
            for (int q = 0; q < 4; ++q) c[i][j][q] = 0.f;

    const int rr0 = tid >> 3;
    const int cc  = tid & 7;

    auto issue_stage = [&](int kt, int s) {
        #pragma unroll
        for (int i = 0; i < 4; ++i) {
            int r = rr0 + i * 32;
            uint32_t sw = (uint32_t)(r * 128 + ((cc ^ (r & 7)) << 4));
            uint32_t da = sbase + s * STAGE_B + sw;
            uint32_t db = da + AS_BYTES;
            const char* ga = (const char*)(A + (size_t)(m0 + r) * DIM + kt * 64 + cc * 8);
            const char* gb = (const char*)(B + (size_t)(n0 + r) * DIM + kt * 64 + cc * 8);
            CP_ASYNC16(da, ga);
            CP_ASYNC16(db, gb);
        }
        CP_COMMIT();
    };

    const int lrow8 = ((lane >> 3) & 1) * 8 + (lane & 7);
    const int lcol16 = (lane >> 4) * 16;

    issue_stage(0, 0);

    for (int kt = 0; kt < NKT; ++kt) {
        CP_WAIT(0);
        __syncthreads();
        if (kt + 1 < NKT) issue_stage(kt + 1, (kt + 1) & 1);

        const uint32_t ab = sbase + (kt & 1) * STAGE_B;
        const uint32_t bb = ab + AS_BYTES;

        #pragma unroll
        for (int ks = 0; ks < 4; ++ks) {
            const int kb = ks * 32;
            uint32_t af[2][4];
            #pragma unroll
            for (int i = 0; i < 2; ++i) {
                int row = warpM * 32 + i * 16 + lrow8;
                int col = kb + lcol16;
                uint32_t ad = ab + row * 128 + ((((col >> 4) ^ (row & 7)) & 7) << 4);
                LDSM_X4(af[i][0], af[i][1], af[i][2], af[i][3], ad);
            }
            uint32_t bf[4][4];
            #pragma unroll
            for (int jj = 0; jj < 4; ++jj) {
                int nrow = warpN * 64 + jj * 16 + lrow8;
                int col = kb + lcol16;
                uint32_t bd = bb + nrow * 128 + ((((col >> 4) ^ (nrow & 7)) & 7) << 4);
                LDSM_X4(bf[jj][0], bf[jj][1], bf[jj][2], bf[jj][3], bd);
            }
            #pragma unroll
            for (int i = 0; i < 2; ++i) {
                #pragma unroll
                for (int j = 0; j < 8; ++j) {
                    const int jj = j >> 1, sel = j & 1;
                    MMA16816(c[i][j], af[i], bf[jj][sel], bf[jj][sel + 2]);
                }
            }
        }
    }

    #pragma unroll
    for (int i = 0; i < 2; ++i) {
        #pragma unroll
        for (int j = 0; j < 8; ++j) {
            int row = m0 + warpM * 32 + i * 16 + (lane >> 2);
            int col = n0 + warpN * 64 + j * 8 + (lane & 3) * 2;
            float b0v = bias[col], b1v = bias[col + 1];
            float2 o0 = {c[i][j][0] + b0v, c[i][j][1] + b1v};
            float2 o1 = {c[i][j][2] + b0v, c[i][j][3] + b1v};
            *(float2*)&Cf[(size_t)row * DIM + col] = o0;
            *(float2*)&Cf[(size_t)(row + 8) * DIM + col] = o1;
        }
    }
}

// ---------------- fp16 tensor-core flash attention ----------------
// stage: Kh (8K) + V (8K) = 16 KB; Q hi/lo tiles 16 KB each.
#define FS_STAGE 16384
#define FS_Q_OFF (2 * FS_STAGE)                 // 32768
#define FS_SMEM (FS_Q_OFF + 2 * 16384)          // 65536

__global__ __launch_bounds__(256) void flash16_kernel(
    const __half* __restrict__ Qh, const __half* __restrict__ Ql,
    const __half* __restrict__ Kh, const __half* __restrict__ Vh,
    __half* __restrict__ Ao)
{
    extern __shared__ char sm[];
    const uint32_t sb = smem_u32(sm);
    const int tid  = threadIdx.x;
    const int lane = tid & 31;
    const int wid  = tid >> 5;
    const int qb   = blockIdx.x * 128;
    const int h    = blockIdx.y;
    const int b    = blockIdx.z;
    const size_t qrow0 = (size_t)b * SEQ + qb;
    const int colh = h * DH;

    const int lrow8  = ((lane >> 3) & 1) * 8 + (lane & 7);
    const int lcol16 = (lane >> 4) * 16;

    #pragma unroll
    for (int i = 0; i < 4; ++i) {
        int idx = tid + i * 256;
        int r = idx >> 3, c = idx & 7;
        uint32_t sw = (uint32_t)(r * 128 + ((c ^ (r & 7)) << 4));
        size_t goff = (qrow0 + r) * DIM + colh + c * 8;
        CP_ASYNC16(sb + FS_Q_OFF + sw,         (const char*)(Qh + goff));
        CP_ASYNC16(sb + FS_Q_OFF + 16384 + sw, (const char*)(Ql + goff));
    }
    CP_COMMIT();

    auto issue_kv = [&](int kt, int s) {
        const size_t rowbase = (size_t)b * SEQ + (size_t)kt * 64;
        const uint32_t st = sb + s * FS_STAGE;
        #pragma unroll
        for (int i = 0; i < 2; ++i) {
            int idx = tid + i * 256;
            int r = idx >> 3, c = idx & 7;
            uint32_t sw = (uint32_t)(r * 128 + ((c ^ (r & 7)) << 4));
            size_t goff = (rowbase + r) * DIM + colh + c * 8;
            CP_ASYNC16(st + sw,        (const char*)(Kh + goff));
            CP_ASYNC16(st + 8192 + sw, (const char*)(Vh + goff));
        }
        CP_COMMIT();
    };

    issue_kv(0, 0);
    CP_WAIT(0);
    __syncthreads();

    uint32_t qhf[4][4], qlf[4][4];
    #pragma unroll
    for (int kc = 0; kc < 4; ++kc) {
        int row = wid * 16 + lrow8;
        int col = kc * 32 + lcol16;
        uint32_t ad = sb + FS_Q_OFF + row * 128 + ((((col >> 4) ^ (row & 7)) & 7) << 4);
        LDSM_X4(qhf[kc][0], qhf[kc][1], qhf[kc][2], qhf[kc][3], ad);
        LDSM_X4(qlf[kc][0], qlf[kc][1], qlf[kc][2], qlf[kc][3], ad + 16384);
    }

    float o[8][4];
    #pragma unroll
    for (int i = 0; i < 8; ++i)
        #pragma unroll
        for (int q = 0; q < 4; ++q) o[i][q] = 0.f;
    float m0 = -1e30f, m1 = -1e30f, l0 = 0.f, l1 = 0.f;

    for (int kt = 0; kt < SEQ / 64; ++kt) {
        if (kt) {
            CP_WAIT(0);
            __syncthreads();
        }
        if (kt + 1 < SEQ / 64) issue_kv(kt + 1, (kt + 1) & 1);

        const uint32_t kb = sb + (kt & 1) * FS_STAGE;
        const uint32_t vb = kb + 8192;

        float s[8][4];
        #pragma unroll
        for (int i = 0; i < 8; ++i)
            #pragma unroll
            for (int q = 0; q < 4; ++q) s[i][q] = 0.f;

        // S = Q K^T : 2-pass (Qh*Kh + Ql*Kh), K fragments loaded once
        #pragma unroll
        for (int kc = 0; kc < 4; ++kc) {
            const int col = kc * 32 + lcol16;
            #pragma unroll
            for (int nb2 = 0; nb2 < 4; ++nb2) {
                int row = nb2 * 16 + lrow8;
                uint32_t ad = kb + row * 128 + ((((col >> 4) ^ (row & 7)) & 7) << 4);
                uint32_t f0, f1, f2, f3;
                LDSM_X4(f0, f1, f2, f3, ad);
                MMA16816(s[2 * nb2],     qhf[kc], f0, f2);
                MMA16816(s[2 * nb2 + 1], qhf[kc], f1, f3);
                MMA16816(s[2 * nb2],     qlf[kc], f0, f2);
                MMA16816(s[2 * nb2 + 1], qlf[kc], f1, f3);
            }
        }

        float mx0 = -1e30f, mx1 = -1e30f;
        #pragma unroll
        for (int nb = 0; nb < 8; ++nb) {
            mx0 = fmaxf(mx0, fmaxf(s[nb][0], s[nb][1]));
            mx1 = fmaxf(mx1, fmaxf(s[nb][2], s[nb][3]));
        }
        mx0 = fmaxf(mx0, __shfl_xor_sync(0xffffffffu, mx0, 1));
        mx0 = fmaxf(mx0, __shfl_xor_sync(0xffffffffu, mx0, 2));
        mx1 = fmaxf(mx1, __shfl_xor_sync(0xffffffffu, mx1, 1));
        mx1 = fmaxf(mx1, __shfl_xor_sync(0xffffffffu, mx1, 2));
        float mn0 = fmaxf(m0, mx0), mn1 = fmaxf(m1, mx1);
        float cr0 = ex2f(m0 - mn0), cr1 = ex2f(m1 - mn1);
        m0 = mn0; m1 = mn1;

        float ls0 = 0.f, ls1 = 0.f;
        uint32_t a[4][4];
        #pragma unroll
        for (int nb = 0; nb < 8; ++nb) {
            float p0 = ex2f(s[nb][0] - mn0);
            float p1 = ex2f(s[nb][1] - mn0);
            float p2 = ex2f(s[nb][2] - mn1);
            float p3 = ex2f(s[nb][3] - mn1);
            ls0 += p0 + p1;
            ls1 += p2 + p3;
            __half2 h01 = __floats2half2_rn(p0, p1);
            __half2 h23 = __floats2half2_rn(p2, p3);
            int kc = nb >> 1;
            if ((nb & 1) == 0) {
                a[kc][0] = *(uint32_t*)&h01;
                a[kc][1] = *(uint32_t*)&h23;
            } else {
                a[kc][2] = *(uint32_t*)&h01;
                a[kc][3] = *(uint32_t*)&h23;
            }
        }
        ls0 += __shfl_xor_sync(0xffffffffu, ls0, 1);
        ls0 += __shfl_xor_sync(0xffffffffu, ls0, 2);
        ls1 += __shfl_xor_sync(0xffffffffu, ls1, 1);
        ls1 += __shfl_xor_sync(0xffffffffu, ls1, 2);
        l0 = l0 * cr0 + ls0;
        l1 = l1 * cr1 + ls1;
        #pragma unroll
        for (int db = 0; db < 8; ++db) {
            o[db][0] *= cr0; o[db][1] *= cr0;
            o[db][2] *= cr1; o[db][3] *= cr1;
        }

        // O += P V (single pass, fp16 V)
        #pragma unroll
        for (int kc = 0; kc < 4; ++kc) {
            int row = kc * 16 + lrow8;
            #pragma unroll
            for (int db2 = 0; db2 < 4; ++db2) {
                int col = db2 * 32 + lcol16;
                uint32_t ad = vb + row * 128 + ((((col >> 4) ^ (row & 7)) & 7) << 4);
                uint32_t f0, f1, f2, f3;
                LDSM_X4_T(f0, f1, f2, f3, ad);
                MMA16816(o[2 * db2],     a[kc], f0, f1);
                MMA16816(o[2 * db2 + 1], a[kc], f2, f3);
            }
        }
    }

    float inv0 = 1.0f / l0, inv1 = 1.0f / l1;
    size_t r0 = qrow0 + wid * 16 + (lane >> 2);
    size_t r1 = r0 + 8;
    int cb = colh + (lane & 3) * 2;
    #pragma unroll
    for (int db = 0; db < 8; ++db) {
        __half2 w0 = __floats2half2_rn(o[db][0] * inv0, o[db][1] * inv0);
        __half2 w1 = __floats2half2_rn(o[db][2] * inv1, o[db][3] * inv1);
        *(__half2*)&Ao[r0 * DIM + cb + db * 8] = w0;
        *(__half2*)&Ao[r1 * DIM + cb + db * 8] = w1;
    }
}

// ---------------- launch ----------------
extern "C" void kernel_launch(void* const* d_in, const int* in_sizes, int n_in,
                              void* d_out, int out_size) {
    const float* x      = (const float*)d_in[0];
    const float* y      = (const float*)d_in[1];
    const int*   pos_q  = (const int*)d_in[2];
    const int*   pos_kv = (const int*)d_in[3];
    const float* Wq = (const float*)d_in[4];
    const float* bq = (const float*)d_in[5];
    const float* Wk = (const float*)d_in[6];
    const float* bk = (const float*)d_in[7];
    const float* Wv = (const float*)d_in[8];
    const float* bv = (const float*)d_in[9];
    const float* Wo = (const float*)d_in[10];
    const float* bo = (const float*)d_in[11];
    float* out = (float*)d_out;

    __half *Xh, *Yh, *WTq, *WTk, *WTv, *WTo;
    __half *Qhp, *Qlp, *Khp, *Vhp, *Aohp;
    cudaGetSymbolAddress((void**)&Xh, g_Xh);
    cudaGetSymbolAddress((void**)&Yh, g_Yh);
    cudaGetSymbolAddress((void**)&WTq, g_WTq);
    cudaGetSymbolAddress((void**)&WTk, g_WTk);
    cudaGetSymbolAddress((void**)&WTv, g_WTv);
    cudaGetSymbolAddress((void**)&WTo, g_WTo);
    cudaGetSymbolAddress((void**)&Qhp, g_Qh);
    cudaGetSymbolAddress((void**)&Qlp, g_Ql);
    cudaGetSymbolAddress((void**)&Khp, g_Kh);
    cudaGetSymbolAddress((void**)&Vhp, g_Vh);
    cudaGetSymbolAddress((void**)&Aohp, g_Aoh);

    cudaFuncSetAttribute(qkv_gemm_kernel, cudaFuncAttributeMaxDynamicSharedMemorySize, GEMM_SMEM);
    cudaFuncSetAttribute(out_gemm_kernel, cudaFuncAttributeMaxDynamicSharedMemorySize, GEMM_SMEM);
    cudaFuncSetAttribute(flash16_kernel, cudaFuncAttributeMaxDynamicSharedMemorySize, FS_SMEM);

    const int n4 = (ROWS * DIM) / 4;
    f2h2_kernel<<<dim3((n4 + 255) / 256, 2), 256>>>(x, y, Xh, Yh, n4);

    transpose4_kernel<<<dim3(DIM / 32, DIM / 32, 4), dim3(32, 8)>>>(
        Wq, Wk, Wv, Wo, WTq, WTk, WTv, WTo);

    qkv_gemm_kernel<<<dim3(DIM / 128, ROWS / 128, 3), 256, GEMM_SMEM>>>(
        Xh, Yh, WTq, WTk, WTv, bq, bk, bv, pos_q, pos_kv,
        Qhp, Qlp, Khp, Vhp);

    flash16_kernel<<<dim3(SEQ / 128, HEADS, BATCH), 256, FS_SMEM>>>(
        Qhp, Qlp, Khp, Vhp, Aohp);

    out_gemm_kernel<<<dim3(DIM / 128, ROWS / 128), 256, GEMM_SMEM>>>(Aohp, WTo, bo, out);
}

// round 11
// speedup vs baseline: 8.3265x; 1.1869x over previous
#include <cuda_runtime.h>
#include <cuda_fp16.h>
#include <math.h>
#include <stdint.h>

#define HEADS 12
#define DH 64
#define DIM 768
#define BATCH 8
#define SEQ 1024
#define ROWS (BATCH * SEQ)   // 8192

#define QSCALE 0.1803368801111204f   // 0.125 * log2(e)

// ---------------- scratch ----------------
__device__ __half g_Xh[ROWS * DIM];
__device__ __half g_Yh[ROWS * DIM];
__device__ __half g_WTq[DIM * DIM];
__device__ __half g_WTk[DIM * DIM];
__device__ __half g_WTv[DIM * DIM];
__device__ __half g_WTo[DIM * DIM];
__device__ __half g_Qh[ROWS * DIM];
__device__ __half g_Kh[ROWS * DIM];
__device__ __half g_Vh[ROWS * DIM];
__device__ __half g_Aoh[ROWS * DIM];
__device__ float g_cosT[512];
__device__ float g_sinT[512];

// ---------------- helpers ----------------
__device__ __forceinline__ uint32_t smem_u32(const void* p) {
    uint32_t a;
    asm("{ .reg .u64 t; cvta.to.shared.u64 t, %1; cvt.u32.u64 %0, t; }" : "=r"(a) : "l"(p));
    return a;
}
__device__ __forceinline__ float ex2f(float x) {
    float y;
    asm("ex2.approx.ftz.f32 %0, %1;" : "=f"(y) : "f"(x));
    return y;
}

#define LDSM_X4(r0, r1, r2, r3, addr)                                          \
    asm volatile("ldmatrix.sync.aligned.m8n8.x4.shared.b16 {%0,%1,%2,%3}, [%4];" \
                 : "=r"(r0), "=r"(r1), "=r"(r2), "=r"(r3) : "r"(addr))

#define LDSM_X4_T(r0, r1, r2, r3, addr)                                        \
    asm volatile("ldmatrix.sync.aligned.m8n8.x4.trans.shared.b16 {%0,%1,%2,%3}, [%4];" \
                 : "=r"(r0), "=r"(r1), "=r"(r2), "=r"(r3) : "r"(addr))

#define MMA16816(c, a, b0, b1)                                                 \
    asm volatile("mma.sync.aligned.m16n8k16.row.col.f32.f16.f16.f32 "          \
                 "{%0,%1,%2,%3}, {%4,%5,%6,%7}, {%8,%9}, {%0,%1,%2,%3};"       \
                 : "+f"((c)[0]), "+f"((c)[1]), "+f"((c)[2]), "+f"((c)[3])      \
                 : "r"((a)[0]), "r"((a)[1]), "r"((a)[2]), "r"((a)[3]),         \
                   "r"(b0), "r"(b1))

#define CP_ASYNC16(dst, src)                                                   \
    asm volatile("cp.async.cg.shared.global [%0], [%1], 16;" :: "r"(dst), "l"(src))
#define CP_COMMIT() asm volatile("cp.async.commit_group;" ::: "memory")
#define CP_WAIT(n)  asm volatile("cp.async.wait_group %0;" :: "n"(n) : "memory")

// ---------------- float -> half (x and y in one launch) ----------------
__global__ void f2h2_kernel(const float* __restrict__ x, const float* __restrict__ y,
                            __half* __restrict__ Xh, __half* __restrict__ Yh, int n4) {
    int i = blockIdx.x * blockDim.x + threadIdx.x;
    if (i >= n4) return;
    const float* src = blockIdx.y ? y : x;
    __half* dst = blockIdx.y ? Yh : Xh;
    float4 v = ((const float4*)src)[i];
    __half2 lo = __floats2half2_rn(v.x, v.y);
    __half2 hi = __floats2half2_rn(v.z, v.w);
    uint2 o;
    o.x = *(uint32_t*)&lo;
    o.y = *(uint32_t*)&hi;
    ((uint2*)dst)[i] = o;
}

// ---------------- 4 weight transposes + RoPE table init in one launch ----------------
__global__ void transpose4_kernel(const float* __restrict__ Wq, const float* __restrict__ Wk,
                                  const float* __restrict__ Wv, const float* __restrict__ Wo,
                                  __half* __restrict__ Tq, __half* __restrict__ Tk,
                                  __half* __restrict__ Tv, __half* __restrict__ To) {
    const int z = blockIdx.z;
    if (z == 0 && blockIdx.x == 0 && blockIdx.y == 0) {
        int t = threadIdx.y * 32 + threadIdx.x;
        #pragma unroll
        for (int rep = 0; rep < 2; ++rep) {
            int i = t + rep * 256;
            int p = i >> 4;
            int f = i & 15;
            double inv = pow(100.0, -((double)(2 * f)) / 32.0);
            double fr = (double)p * inv;
            g_cosT[i] = (float)cos(fr);
            g_sinT[i] = (float)sin(fr);
        }
    }
    const float* W = (z == 0) ? Wq : (z == 1) ? Wk : (z == 2) ? Wv : Wo;
    __half* T = (z == 0) ? Tq : (z == 1) ? Tk : (z == 2) ? Tv : To;
    __shared__ float tile[32][33];
    int bx = blockIdx.x * 32;
    int by = blockIdx.y * 32;
    int x = threadIdx.x, y = threadIdx.y;
    #pragma unroll
    for (int j = 0; j < 4; ++j)
        tile[y + 8 * j][x] = W[(by + y + 8 * j) * DIM + bx + x];
    __syncthreads();
    #pragma unroll
    for (int j = 0; j < 4; ++j)
        T[(size_t)(bx + y + 8 * j) * DIM + by + x] = __float2half(tile[x][y + 8 * j]);
}

// ---------------- GEMM tile constants ----------------
#define NKT (DIM / 64)
#define AS_BYTES (128 * 128)
#define STAGE_B (2 * AS_BYTES)
#define GEMM_SMEM (2 * STAGE_B)

// ---------------- fused Q/K/V projection GEMM (one launch, z picks mode) ----------------
// z=0: rope(C+bq)*QSCALE -> Qh   z=1: rope(C+bk) -> Kh   z=2: (C+bv) -> Vh   (all fp16)
__global__ __launch_bounds__(256, 2) void qkv_gemm_kernel(
    const __half* __restrict__ Xh, const __half* __restrict__ Yh,
    const __half* __restrict__ WTq, const __half* __restrict__ WTk, const __half* __restrict__ WTv,
    const float* __restrict__ bq, const float* __restrict__ bk, const float* __restrict__ bv,
    const int* __restrict__ pos_q, const int* __restrict__ pos_kv,
    __half* __restrict__ Qh, __half* __restrict__ Kh, __half* __restrict__ Vh)
{
    extern __shared__ char sm[];
    const uint32_t sbase = smem_u32(sm);
    const int z = blockIdx.z;
    const __half* A = (z == 0) ? Xh : Yh;
    const __half* B = (z == 0) ? WTq : (z == 1) ? WTk : WTv;
    const float* bias = (z == 0) ? bq : (z == 1) ? bk : bv;
    const int* pos = (z == 0) ? pos_q : pos_kv;
    __half* Ch = (z == 0) ? Qh : (z == 1) ? Kh : Vh;

    const int tid  = threadIdx.x;
    const int lane = tid & 31;
    const int wid  = tid >> 5;
    const int warpM = wid & 3;
    const int warpN = wid >> 2;
    const int m0 = blockIdx.y * 128;
    const int n0 = blockIdx.x * 128;

    float c[2][8][4];
    #pragma unroll
    for (int i = 0; i < 2; ++i)
        #pragma unroll
        for (int j = 0; j < 8; ++j)
            #pragma unroll
            for (int q = 0; q < 4; ++q) c[i][j][q] = 0.f;

    const int rr0 = tid >> 3;
    const int cc  = tid & 7;

    auto issue_stage = [&](int kt, int s) {
        #pragma unroll
        for (int i = 0; i < 4; ++i) {
            int r = rr0 + i * 32;
            uint32_t sw = (uint32_t)(r * 128 + ((cc ^ (r & 7)) << 4));
            uint32_t da = sbase + s * STAGE_B + sw;
            uint32_t db = da + AS_BYTES;
            const char* ga = (const char*)(A + (size_t)(m0 + r) * DIM + kt * 64 + cc * 8);
            const char* gb = (const char*)(B + (size_t)(n0 + r) * DIM + kt * 64 + cc * 8);
            CP_ASYNC16(da, ga);
            CP_ASYNC16(db, gb);
        }
        CP_COMMIT();
    };

    const int lrow8 = ((lane >> 3) & 1) * 8 + (lane & 7);
    const int lcol16 = (lane >> 4) * 16;

    issue_stage(0, 0);

    for (int kt = 0; kt < NKT; ++kt) {
        CP_WAIT(0);
        __syncthreads();
        if (kt + 1 < NKT) issue_stage(kt + 1, (kt + 1) & 1);

        const uint32_t ab = sbase + (kt & 1) * STAGE_B;
        const uint32_t bb = ab + AS_BYTES;

        #pragma unroll
        for (int ks = 0; ks < 4; ++ks) {
            const int kb = ks * 32;
            uint32_t af[2][4];
            #pragma unroll
            for (int i = 0; i < 2; ++i) {
                int row = warpM * 32 + i * 16 + lrow8;
                int col = kb + lcol16;
                uint32_t ad = ab + row * 128 + ((((col >> 4) ^ (row & 7)) & 7) << 4);
                LDSM_X4(af[i][0], af[i][1], af[i][2], af[i][3], ad);
            }
            uint32_t bf[4][4];
            #pragma unroll
            for (int jj = 0; jj < 4; ++jj) {
                int nrow = warpN * 64 + jj * 16 + lrow8;
                int col = kb + lcol16;
                uint32_t bd = bb + nrow * 128 + ((((col >> 4) ^ (nrow & 7)) & 7) << 4);
                LDSM_X4(bf[jj][0], bf[jj][1], bf[jj][2], bf[jj][3], bd);
            }
            #pragma unroll
            for (int i = 0; i < 2; ++i) {
                #pragma unroll
                for (int j = 0; j < 8; ++j) {
                    const int jj = j >> 1, sel = j & 1;
                    MMA16816(c[i][j], af[i], bf[jj][sel], bf[jj][sel + 2]);
                }
            }
        }
    }

    // ---------------- fused epilogue ----------------
    if (z == 2) {
        #pragma unroll
        for (int i = 0; i < 2; ++i) {
            #pragma unroll
            for (int j = 0; j < 8; ++j) {
                int row = m0 + warpM * 32 + i * 16 + (lane >> 2);
                int col = n0 + warpN * 64 + j * 8 + (lane & 3) * 2;
                float b0v = bias[col], b1v = bias[col + 1];
                *(__half2*)&Ch[(size_t)row * DIM + col] =
                    __floats2half2_rn(c[i][j][0] + b0v, c[i][j][1] + b1v);
                *(__half2*)&Ch[(size_t)(row + 8) * DIM + col] =
                    __floats2half2_rn(c[i][j][2] + b0v, c[i][j][3] + b1v);
            }
        }
    } else {
        const float scale = (z == 0) ? QSCALE : 1.0f;
        #pragma unroll
        for (int i = 0; i < 2; ++i) {
            int rowA = m0 + warpM * 32 + i * 16 + (lane >> 2);
            int rowB = rowA + 8;
            int pA0 = pos[2 * rowA], pA1 = pos[2 * rowA + 1];
            int pB0 = pos[2 * rowB], pB1 = pos[2 * rowB + 1];
            #pragma unroll
            for (int jj = 0; jj < 4; ++jj) {
                const int j = (jj < 2) ? jj : jj + 2;   // 0,1,4,5
                const int half = (j >= 4);
                int col = n0 + warpN * 64 + j * 8 + (lane & 3) * 2;
                int f0 = (j & 1) * 8 + (lane & 3) * 2;
                int pA = half ? pA1 : pA0;
                int pB = half ? pB1 : pB0;
                float cA0 = g_cosT[pA * 16 + f0], cA1 = g_cosT[pA * 16 + f0 + 1];
                float sA0 = g_sinT[pA * 16 + f0], sA1 = g_sinT[pA * 16 + f0 + 1];
                float cB0 = g_cosT[pB * 16 + f0], cB1 = g_cosT[pB * 16 + f0 + 1];
                float sB0 = g_sinT[pB * 16 + f0], sB1 = g_sinT[pB * 16 + f0 + 1];
                float b1x = bias[col], b1y = bias[col + 1];
                float b2x = bias[col + 16], b2y = bias[col + 17];

                {
                    float v1x = c[i][j][0] + b1x,     v1y = c[i][j][1] + b1y;
                    float v2x = c[i][j + 2][0] + b2x, v2y = c[i][j + 2][1] + b2y;
                    *(__half2*)&Ch[(size_t)rowA * DIM + col] =
                        __floats2half2_rn((v1x * cA0 - v2x * sA0) * scale,
                                          (v1y * cA1 - v2y * sA1) * scale);
                    *(__half2*)&Ch[(size_t)rowA * DIM + col + 16] =
                        __floats2half2_rn((v2x * cA0 + v1x * sA0) * scale,
                                          (v2y * cA1 + v1y * sA1) * scale);
                }
                {
                    float v1x = c[i][j][2] + b1x,     v1y = c[i][j][3] + b1y;
                    float v2x = c[i][j + 2][2] + b2x, v2y = c[i][j + 2][3] + b2y;
                    *(__half2*)&Ch[(size_t)rowB * DIM + col] =
                        __floats2half2_rn((v1x * cB0 - v2x * sB0) * scale,
                                          (v1y * cB1 - v2y * sB1) * scale);
                    *(__half2*)&Ch[(size_t)rowB * DIM + col + 16] =
                        __floats2half2_rn((v2x * cB0 + v1x * sB0) * scale,
                                          (v2y * cB1 + v1y * sB1) * scale);
                }
            }
        }
    }
}

// ---------------- final output GEMM: out = Aoh @ WTo^T + bo (fp32) ----------------
__global__ __launch_bounds__(256, 2) void out_gemm_kernel(
    const __half* __restrict__ A, const __half* __restrict__ B,
    const float* __restrict__ bias, float* __restrict__ Cf)
{
    extern __shared__ char sm[];
    const uint32_t sbase = smem_u32(sm);
    const int tid  = threadIdx.x;
    const int lane = tid & 31;
    const int wid  = tid >> 5;
    const int warpM = wid & 3;
    const int warpN = wid >> 2;
    const int m0 = blockIdx.y * 128;
    const int n0 = blockIdx.x * 128;

    float c[2][8][4];
    #pragma unroll
    for (int i = 0; i < 2; ++i)
        #pragma unroll
        for (int j = 0; j < 8; ++j)
            #pragma unroll
            for (int q = 0; q < 4; ++q) c[i][j][q] = 0.f;

    const int rr0 = tid >> 3;
    const int cc  = tid & 7;

    auto issue_stage = [&](int kt, int s) {
        #pragma unroll
        for (int i = 0; i < 4; ++i) {
            int r = rr0 + i * 32;
            uint32_t sw = (uint32_t)(r * 128 + ((cc ^ (r & 7)) << 4));
            uint32_t da = sbase + s * STAGE_B + sw;
            uint32_t db = da + AS_BYTES;
            const char* ga = (const char*)(A + (size_t)(m0 + r) * DIM + kt * 64 + cc * 8);
            const char* gb = (const char*)(B + (size_t)(n0 + r) * DIM + kt * 64 + cc * 8);
            CP_ASYNC16(da, ga);
            CP_ASYNC16(db, gb);
        }
        CP_COMMIT();
    };

    const int lrow8 = ((lane >> 3) & 1) * 8 + (lane & 7);
    const int lcol16 = (lane >> 4) * 16;

    issue_stage(0, 0);

    for (int kt = 0; kt < NKT; ++kt) {
        CP_WAIT(0);
        __syncthreads();
        if (kt + 1 < NKT) issue_stage(kt + 1, (kt + 1) & 1);

        const uint32_t ab = sbase + (kt & 1) * STAGE_B;
        const uint32_t bb = ab + AS_BYTES;

        #pragma unroll
        for (int ks = 0; ks < 4; ++ks) {
            const int kb = ks * 32;
            uint32_t af[2][4];
            #pragma unroll
            for (int i = 0; i < 2; ++i) {
                int row = warpM * 32 + i * 16 + lrow8;
                int col = kb + lcol16;
                uint32_t ad = ab + row * 128 + ((((col >> 4) ^ (row & 7)) & 7) << 4);
                LDSM_X4(af[i][0], af[i][1], af[i][2], af[i][3], ad);
            }
            uint32_t bf[4][4];
            #pragma unroll
            for (int jj = 0; jj < 4; ++jj) {
                int nrow = warpN * 64 + jj * 16 + lrow8;
                int col = kb + lcol16;
                uint32_t bd = bb + nrow * 128 + ((((col >> 4) ^ (nrow & 7)) & 7) << 4);
                LDSM_X4(bf[jj][0], bf[jj][1], bf[jj][2], bf[jj][3], bd);
            }
            #pragma unroll
            for (int i = 0; i < 2; ++i) {
                #pragma unroll
                for (int j = 0; j < 8; ++j) {
                    const int jj = j >> 1, sel = j & 1;
                    MMA16816(c[i][j], af[i], bf[jj][sel], bf[jj][sel + 2]);
                }
            }
        }
    }

    #pragma unroll
    for (int i = 0; i < 2; ++i) {
        #pragma unroll
        for (int j = 0; j < 8; ++j) {
            int row = m0 + warpM * 32 + i * 16 + (lane >> 2);
            int col = n0 + warpN * 64 + j * 8 + (lane & 3) * 2;
            float b0v = bias[col], b1v = bias[col + 1];
            float2 o0 = {c[i][j][0] + b0v, c[i][j][1] + b1v};
            float2 o1 = {c[i][j][2] + b0v, c[i][j][3] + b1v};
            *(float2*)&Cf[(size_t)row * DIM + col] = o0;
            *(float2*)&Cf[(size_t)(row + 8) * DIM + col] = o1;
        }
    }
}

// ---------------- fp16 tensor-core flash attention ----------------
// stage: Kh (8K) + V (8K) = 16 KB double-buffered; Q tile 16 KB.
#define FS_STAGE 16384
#define FS_Q_OFF (2 * FS_STAGE)                 // 32768
#define FS_SMEM (FS_Q_OFF + 16384)              // 49152

__global__ __launch_bounds__(256) void flash16_kernel(
    const __half* __restrict__ Qh, const __half* __restrict__ Kh,
    const __half* __restrict__ Vh, __half* __restrict__ Ao)
{
    extern __shared__ char sm[];
    const uint32_t sb = smem_u32(sm);
    const int tid  = threadIdx.x;
    const int lane = tid & 31;
    const int wid  = tid >> 5;
    const int qb   = blockIdx.x * 128;
    const int h    = blockIdx.y;
    const int b    = blockIdx.z;
    const size_t qrow0 = (size_t)b * SEQ + qb;
    const int colh = h * DH;

    const int lrow8  = ((lane >> 3) & 1) * 8 + (lane & 7);
    const int lcol16 = (lane >> 4) * 16;

    #pragma unroll
    for (int i = 0; i < 4; ++i) {
        int idx = tid + i * 256;
        int r = idx >> 3, c = idx & 7;
        uint32_t sw = (uint32_t)(r * 128 + ((c ^ (r & 7)) << 4));
        size_t goff = (qrow0 + r) * DIM + colh + c * 8;
        CP_ASYNC16(sb + FS_Q_OFF + sw, (const char*)(Qh + goff));
    }
    CP_COMMIT();

    auto issue_kv = [&](int kt, int s) {
        const size_t rowbase = (size_t)b * SEQ + (size_t)kt * 64;
        const uint32_t st = sb + s * FS_STAGE;
        #pragma unroll
        for (int i = 0; i < 2; ++i) {
            int idx = tid + i * 256;
            int r = idx >> 3, c = idx & 7;
            uint32_t sw = (uint32_t)(r * 128 + ((c ^ (r & 7)) << 4));
            size_t goff = (rowbase + r) * DIM + colh + c * 8;
            CP_ASYNC16(st + sw,        (const char*)(Kh + goff));
            CP_ASYNC16(st + 8192 + sw, (const char*)(Vh + goff));
        }
        CP_COMMIT();
    };

    issue_kv(0, 0);
    CP_WAIT(0);
    __syncthreads();

    uint32_t qhf[4][4];
    #pragma unroll
    for (int kc = 0; kc < 4; ++kc) {
        int row = wid * 16 + lrow8;
        int col = kc * 32 + lcol16;
        uint32_t ad = sb + FS_Q_OFF + row * 128 + ((((col >> 4) ^ (row & 7)) & 7) << 4);
        LDSM_X4(qhf[kc][0], qhf[kc][1], qhf[kc][2], qhf[kc][3], ad);
    }

    float o[8][4];
    #pragma unroll
    for (int i = 0; i < 8; ++i)
        #pragma unroll
        for (int q = 0; q < 4; ++q) o[i][q] = 0.f;
    float m0 = -1e30f, m1 = -1e30f, l0 = 0.f, l1 = 0.f;

    for (int kt = 0; kt < SEQ / 64; ++kt) {
        if (kt) {
            CP_WAIT(0);
            __syncthreads();
        }
        if (kt + 1 < SEQ / 64) issue_kv(kt + 1, (kt + 1) & 1);

        const uint32_t kb = sb + (kt & 1) * FS_STAGE;
        const uint32_t vb = kb + 8192;

        float s[8][4];
        #pragma unroll
        for (int i = 0; i < 8; ++i)
            #pragma unroll
            for (int q = 0; q < 4; ++q) s[i][q] = 0.f;

        // S = Q K^T : single pass (Qh*Kh)
        #pragma unroll
        for (int kc = 0; kc < 4; ++kc) {
            const int col = kc * 32 + lcol16;
            #pragma unroll
            for (int nb2 = 0; nb2 < 4; ++nb2) {
                int row = nb2 * 16 + lrow8;
                uint32_t ad = kb + row * 128 + ((((col >> 4) ^ (row & 7)) & 7) << 4);
                uint32_t f0, f1, f2, f3;
                LDSM_X4(f0, f1, f2, f3, ad);
                MMA16816(s[2 * nb2],     qhf[kc], f0, f2);
                MMA16816(s[2 * nb2 + 1], qhf[kc], f1, f3);
            }
        }

        float mx0 = -1e30f, mx1 = -1e30f;
        #pragma unroll
        for (int nb = 0; nb < 8; ++nb) {
            mx0 = fmaxf(mx0, fmaxf(s[nb][0], s[nb][1]));
            mx1 = fmaxf(mx1, fmaxf(s[nb][2], s[nb][3]));
        }
        mx0 = fmaxf(mx0, __shfl_xor_sync(0xffffffffu, mx0, 1));
        mx0 = fmaxf(mx0, __shfl_xor_sync(0xffffffffu, mx0, 2));
        mx1 = fmaxf(mx1, __shfl_xor_sync(0xffffffffu, mx1, 1));
        mx1 = fmaxf(mx1, __shfl_xor_sync(0xffffffffu, mx1, 2));
        float mn0 = fmaxf(m0, mx0), mn1 = fmaxf(m1, mx1);
        float cr0 = ex2f(m0 - mn0), cr1 = ex2f(m1 - mn1);
        m0 = mn0; m1 = mn1;

        float ls0 = 0.f, ls1 = 0.f;
        uint32_t a[4][4];
        #pragma unroll
        for (int nb = 0; nb < 8; ++nb) {
            float p0 = ex2f(s[nb][0] - mn0);
            float p1 = ex2f(s[nb][1] - mn0);
            float p2 = ex2f(s[nb][2] - mn1);
            float p3 = ex2f(s[nb][3] - mn1);
            ls0 += p0 + p1;
            ls1 += p2 + p3;
            __half2 h01 = __floats2half2_rn(p0, p1);
            __half2 h23 = __floats2half2_rn(p2, p3);
            int kc = nb >> 1;
            if ((nb & 1) == 0) {
                a[kc][0] = *(uint32_t*)&h01;
                a[kc][1] = *(uint32_t*)&h23;
            } else {
                a[kc][2] = *(uint32_t*)&h01;
                a[kc][3] = *(uint32_t*)&h23;
            }
        }
        ls0 += __shfl_xor_sync(0xffffffffu, ls0, 1);
        ls0 += __shfl_xor_sync(0xffffffffu, ls0, 2);
        ls1 += __shfl_xor_sync(0xffffffffu, ls1, 1);
        ls1 += __shfl_xor_sync(0xffffffffu, ls1, 2);
        l0 = l0 * cr0 + ls0;
        l1 = l1 * cr1 + ls1;
        #pragma unroll
        for (int db = 0; db < 8; ++db) {
            o[db][0] *= cr0; o[db][1] *= cr0;
            o[db][2] *= cr1; o[db][3] *= cr1;
        }

        // O += P V (single pass, fp16 V)
        #pragma unroll
        for (int kc = 0; kc < 4; ++kc) {
            int row = kc * 16 + lrow8;
            #pragma unroll
            for (int db2 = 0; db2 < 4; ++db2) {
                int col = db2 * 32 + lcol16;
                uint32_t ad = vb + row * 128 + ((((col >> 4) ^ (row & 7)) & 7) << 4);
                uint32_t f0, f1, f2, f3;
                LDSM_X4_T(f0, f1, f2, f3, ad);
                MMA16816(o[2 * db2],     a[kc], f0, f1);
                MMA16816(o[2 * db2 + 1], a[kc], f2, f3);
            }
        }
    }

    float inv0 = 1.0f / l0, inv1 = 1.0f / l1;
    size_t r0 = qrow0 + wid * 16 + (lane >> 2);
    size_t r1 = r0 + 8;
    int cb = colh + (lane & 3) * 2;
    #pragma unroll
    for (int db = 0; db < 8; ++db) {
        __half2 w0 = __floats2half2_rn(o[db][0] * inv0, o[db][1] * inv0);
        __half2 w1 = __floats2half2_rn(o[db][2] * inv1, o[db][3] * inv1);
        *(__half2*)&Ao[r0 * DIM + cb + db * 8] = w0;
        *(__half2*)&Ao[r1 * DIM + cb + db * 8] = w1;
    }
}

// ---------------- launch ----------------
extern "C" void kernel_launch(void* const* d_in, const int* in_sizes, int n_in,
                              void* d_out, int out_size) {
    const float* x      = (const float*)d_in[0];
    const float* y      = (const float*)d_in[1];
    const int*   pos_q  = (const int*)d_in[2];
    const int*   pos_kv = (const int*)d_in[3];
    const float* Wq = (const float*)d_in[4];
    const float* bq = (const float*)d_in[5];
    const float* Wk = (const float*)d_in[6];
    const float* bk = (const float*)d_in[7];
    const float* Wv = (const float*)d_in[8];
    const float* bv = (const float*)d_in[9];
    const float* Wo = (const float*)d_in[10];
    const float* bo = (const float*)d_in[11];
    float* out = (float*)d_out;

    __half *Xh, *Yh, *WTq, *WTk, *WTv, *WTo;
    __half *Qhp, *Khp, *Vhp, *Aohp;
    cudaGetSymbolAddress((void**)&Xh, g_Xh);
    cudaGetSymbolAddress((void**)&Yh, g_Yh);
    cudaGetSymbolAddress((void**)&WTq, g_WTq);
    cudaGetSymbolAddress((void**)&WTk, g_WTk);
    cudaGetSymbolAddress((void**)&WTv, g_WTv);
    cudaGetSymbolAddress((void**)&WTo, g_WTo);
    cudaGetSymbolAddress((void**)&Qhp, g_Qh);
    cudaGetSymbolAddress((void**)&Khp, g_Kh);
    cudaGetSymbolAddress((void**)&Vhp, g_Vh);
    cudaGetSymbolAddress((void**)&Aohp, g_Aoh);

    cudaFuncSetAttribute(qkv_gemm_kernel, cudaFuncAttributeMaxDynamicSharedMemorySize, GEMM_SMEM);
    cudaFuncSetAttribute(out_gemm_kernel, cudaFuncAttributeMaxDynamicSharedMemorySize, GEMM_SMEM);
    cudaFuncSetAttribute(flash16_kernel, cudaFuncAttributeMaxDynamicSharedMemorySize, FS_SMEM);

    const int n4 = (ROWS * DIM) / 4;
    f2h2_kernel<<<dim3((n4 + 255) / 256, 2), 256>>>(x, y, Xh, Yh, n4);

    transpose4_kernel<<<dim3(DIM / 32, DIM / 32, 4), dim3(32, 8)>>>(
        Wq, Wk, Wv, Wo, WTq, WTk, WTv, WTo);

    qkv_gemm_kernel<<<dim3(DIM / 128, ROWS / 128, 3), 256, GEMM_SMEM>>>(
        Xh, Yh, WTq, WTk, WTv, bq, bk, bv, pos_q, pos_kv,
        Qhp, Khp, Vhp);

    flash16_kernel<<<dim3(SEQ / 128, HEADS, BATCH), 256, FS_SMEM>>>(
        Qhp, Khp, Vhp, Aohp);

    out_gemm_kernel<<<dim3(DIM / 128, ROWS / 128), 256, GEMM_SMEM>>>(Aohp, WTo, bo, out);
}